// round 4
// baseline (speedup 1.0000x reference)
#include <cuda_runtime.h>
#include <math.h>
#include <stdint.h>

#define BATCH 64
#define E 128
#define NSEQ 1024
#define NHEADS 8
#define DH 16
#define DFF 512
#define MROWS (BATCH * NSEQ)   // 65536
#define NLAYERS 4
#define LN_EPS 1e-5f
#define QKV_N 384

// ---------------- scratch (static device globals; allocation-free) ----------
__device__ float g_t[MROWS * E];          // residual stream fp32
__device__ float g_y[MROWS * E];          // layernorm output (tf32-rounded)
__device__ float g_qkv[MROWS * QKV_N];    // fused q|k|v, row stride 384
__device__ float g_ctx[BATCH * NHEADS * DH * DH];
// transposed+tf32 weights per layer: qkv^T(49152), o^T(16384), ff1^T(65536), ff2^T(65536)
#define WT_LAYER 196608
__device__ float g_wt[NLAYERS * WT_LAYER];

__device__ __forceinline__ float rna_tf32(float x) {
    uint32_t u;
    asm("cvt.rna.tf32.f32 %0, %1;" : "=r"(u) : "f"(x));
    return __uint_as_float(u);
}

__device__ __forceinline__ float gelu_f(float x) {
    float x3 = x * x * x;
    return 0.5f * x * (1.0f + tanhf(0.7978845608028654f * (x + 0.044715f * x3)));
}

#define LDSM4(d0, d1, d2, d3, addr) \
    asm volatile("ldmatrix.sync.aligned.m8n8.x4.shared.b16 {%0,%1,%2,%3}, [%4];" \
                 : "=r"(d0), "=r"(d1), "=r"(d2), "=r"(d3) : "r"(addr))

#define MMA_TF32(c, a, b) \
    asm volatile("mma.sync.aligned.m16n8k8.row.col.f32.tf32.tf32.f32 " \
                 "{%0,%1,%2,%3},{%4,%5,%6,%7},{%8,%9},{%0,%1,%2,%3};" \
                 : "+f"((c)[0]), "+f"((c)[1]), "+f"((c)[2]), "+f"((c)[3]) \
                 : "r"((a)[0]), "r"((a)[1]), "r"((a)[2]), "r"((a)[3]), \
                   "r"((b)[0]), "r"((b)[1]))

__device__ __forceinline__ void cp_async16(uint32_t dst, const void* src) {
    asm volatile("cp.async.cg.shared.global [%0], [%1], 16;" :: "r"(dst), "l"(src));
}
#define CP_COMMIT() asm volatile("cp.async.commit_group;")
#define CP_WAIT0()  asm volatile("cp.async.wait_group 0;")
#define CP_WAIT1()  asm volatile("cp.async.wait_group 1;")

// ---------------- transpose x:(B,E,N) -> t:(B,N,E) --------------------------
__global__ void transpose_kernel(const float* __restrict__ x) {
    __shared__ float tile[32][33];
    int b  = blockIdx.z;
    int n0 = blockIdx.x * 32;
    int e0 = blockIdx.y * 32;
    int tx = threadIdx.x, ty = threadIdx.y;   // (32,8)
#pragma unroll
    for (int i = 0; i < 32; i += 8)
        tile[ty + i][tx] = x[(size_t)b * E * NSEQ + (size_t)(e0 + ty + i) * NSEQ + n0 + tx];
    __syncthreads();
#pragma unroll
    for (int i = 0; i < 32; i += 8)
        g_t[(size_t)b * NSEQ * E + (size_t)(n0 + ty + i) * E + e0 + tx] = tile[tx][ty + i];
}

// ---------------- weight convert: src[K][N] -> dst[N][K], tf32 rna ----------
__global__ void wt_cvt_kernel(const float* __restrict__ src, float* __restrict__ dst,
                              int K, int N) {
    __shared__ float tile[32][33];
    int n0 = blockIdx.x * 32;
    int k0 = blockIdx.y * 32;
    int tx = threadIdx.x, ty = threadIdx.y;   // (32,8)
#pragma unroll
    for (int i = 0; i < 32; i += 8)
        tile[ty + i][tx] = src[(size_t)(k0 + ty + i) * N + n0 + tx];
    __syncthreads();
#pragma unroll
    for (int i = 0; i < 32; i += 8)
        dst[(size_t)(n0 + ty + i) * K + k0 + tx] = rna_tf32(tile[tx][ty + i]);
}

// ---------------- standalone layernorm (layer-0 entry only) -----------------
__global__ void ln_kernel(const float* __restrict__ gamma, const float* __restrict__ beta) {
    int m = blockIdx.x;
    int e = threadIdx.x;
    float v = g_t[(size_t)m * E + e];
    __shared__ float red[4];
    float s = v;
#pragma unroll
    for (int o = 16; o > 0; o >>= 1) s += __shfl_down_sync(0xffffffffu, s, o);
    if ((e & 31) == 0) red[e >> 5] = s;
    __syncthreads();
    float mu = (red[0] + red[1] + red[2] + red[3]) * (1.0f / E);
    __syncthreads();
    float d = v - mu;
    float s2 = d * d;
#pragma unroll
    for (int o = 16; o > 0; o >>= 1) s2 += __shfl_down_sync(0xffffffffu, s2, o);
    if ((e & 31) == 0) red[e >> 5] = s2;
    __syncthreads();
    float var = (red[0] + red[1] + red[2] + red[3]) * (1.0f / E);
    g_y[(size_t)m * E + e] = rna_tf32(d * rsqrtf(var + LN_EPS) * gamma[e] + beta[e]);
}

// ---------------- QKV GEMM: qkv = y @ Wqkv^T  (M=65536, N=384, K=128) -------
#define GBM 128
#define GBN 128
#define NSTAGE 3
#define STAGE_BYTES 16384
#define BSMEM_OFF (NSTAGE * STAGE_BYTES)
#define QKV_SMEM (2 * NSTAGE * STAGE_BYTES)   // 98304

__global__ __launch_bounds__(256, 2) void qkv_gemm(
    const float* __restrict__ A, const float* __restrict__ Wt, float* __restrict__ C)
{
    extern __shared__ float sm[];
    uint32_t smem_u = (uint32_t)__cvta_generic_to_shared(sm);

    int tid  = threadIdx.x;
    int lane = tid & 31;
    int wid  = tid >> 5;
    int warp_m = wid & 1;
    int warp_n = wid >> 1;
    int bm0 = blockIdx.y * GBM;
    int bn0 = blockIdx.x * GBN;

    int r0 = tid >> 3;
    int c8 = tid & 7;
    uint32_t cxor = (uint32_t)((c8 ^ (r0 & 7)) << 4);

    int sub = lane >> 3;
    int l7  = lane & 7;
    int selA = sub >> 1;
    int rowAoff = ((sub & 1) << 3) + l7;
    int selB = sub & 1;
    int rowBoff = ((sub >> 1) << 3) + l7;

    float acc[4][4][4];
#pragma unroll
    for (int i = 0; i < 4; i++)
#pragma unroll
        for (int j = 0; j < 4; j++)
#pragma unroll
            for (int k = 0; k < 4; k++) acc[i][j][k] = 0.f;

    auto load_tile = [&](int s, int k0) {
#pragma unroll
        for (int i = 0; i < 4; i++) {
            int r = r0 + i * 32;
            uint32_t doff = (uint32_t)(r << 7) + cxor;
            cp_async16(smem_u + s * STAGE_BYTES + doff, A + (size_t)(bm0 + r) * E + k0 + c8 * 4);
            cp_async16(smem_u + BSMEM_OFF + s * STAGE_BYTES + doff, Wt + (size_t)(bn0 + r) * E + k0 + c8 * 4);
        }
    };

    load_tile(0, 0);  CP_COMMIT();
    load_tile(1, 32); CP_COMMIT();

    const int nIter = 4;   // K=128 / 32
    for (int it = 0; it < nIter; it++) {
        if (it < nIter - 1) CP_WAIT1(); else CP_WAIT0();
        __syncthreads();

        int s = it % NSTAGE;
        uint32_t baseA = smem_u + s * STAGE_BYTES;
        uint32_t baseB = smem_u + BSMEM_OFF + s * STAGE_BYTES;

#pragma unroll
        for (int ks = 0; ks < 4; ks++) {
            int cb = ks * 2;
            uint32_t a[4][4], b[4][2];
#pragma unroll
            for (int mt = 0; mt < 4; mt++) {
                int row = warp_m * 64 + mt * 16 + rowAoff;
                uint32_t addr = baseA + (row << 7) + (uint32_t)(((cb + selA) ^ (row & 7)) << 4);
                LDSM4(a[mt][0], a[mt][1], a[mt][2], a[mt][3], addr);
            }
#pragma unroll
            for (int bt = 0; bt < 2; bt++) {
                int row = warp_n * 32 + bt * 16 + rowBoff;
                uint32_t addr = baseB + (row << 7) + (uint32_t)(((cb + selB) ^ (row & 7)) << 4);
                LDSM4(b[2 * bt][0], b[2 * bt][1], b[2 * bt + 1][0], b[2 * bt + 1][1], addr);
            }
#pragma unroll
            for (int mt = 0; mt < 4; mt++)
#pragma unroll
                for (int nt = 0; nt < 4; nt++)
                    MMA_TF32(acc[mt][nt], a[mt], b[nt]);
        }
        if (it + 2 < nIter) { load_tile((it + 2) % NSTAGE, (it + 2) * 32); CP_COMMIT(); }
    }

    int g  = lane >> 2;
    int t4 = lane & 3;
#pragma unroll
    for (int mt = 0; mt < 4; mt++) {
        int rowl0 = warp_m * 64 + mt * 16 + g;
#pragma unroll
        for (int nt = 0; nt < 4; nt++) {
            int col = bn0 + warp_n * 32 + nt * 8 + t4 * 2;
#pragma unroll
            for (int half = 0; half < 2; half++) {
                int row = bm0 + rowl0 + half * 8;
                *(float2*)(C + (size_t)row * QKV_N + col) =
                    make_float2(acc[mt][nt][half * 2], acc[mt][nt][half * 2 + 1]);
            }
        }
    }
}

// ---------------- fused softmax_k + ctx per (b,h) ---------------------------
__global__ void ctx_kernel() {
    int bh = blockIdx.x;
    int b = bh >> 3, h = bh & 7;
    const float* kbase = g_qkv + (size_t)b * NSEQ * QKV_N + E + h * DH;
    const float* vbase = kbase + E;
    int tid = threadIdx.x;

    __shared__ float smax[16][17];
    __shared__ float mx[16];
    int d0 = tid & 15, i0 = tid >> 4;
    float m = -1e30f;
    for (int i = 0; i < 64; i++) {
        int n = i0 + i * 16;
        m = fmaxf(m, kbase[(size_t)n * QKV_N + d0]);
    }
    smax[d0][i0] = m;
    __syncthreads();
    if (tid < 16) {
        float t = smax[tid][0];
#pragma unroll
        for (int i = 1; i < 16; i++) t = fmaxf(t, smax[tid][i]);
        mx[tid] = t;
    }
    __syncthreads();

    __shared__ float ks[128][17];
    __shared__ float vs[128][17];
    int d = tid >> 4, e = tid & 15;
    float acc = 0.f, ssum = 0.f;
    for (int n0 = 0; n0 < NSEQ; n0 += 128) {
        __syncthreads();
        for (int l = tid; l < 128 * 16; l += 256) {
            int nl = l >> 4, c = l & 15;
            ks[nl][c] = expf(kbase[(size_t)(n0 + nl) * QKV_N + c] - mx[c]);
            vs[nl][c] = vbase[(size_t)(n0 + nl) * QKV_N + c];
        }
        __syncthreads();
#pragma unroll 8
        for (int nl = 0; nl < 128; nl++) {
            float kk = ks[nl][d];
            acc += kk * vs[nl][e];
            ssum += kk;
        }
    }
    g_ctx[bh * 256 + d * 16 + e] = acc / ssum;
}

// ---------------- o-proj: fused attn-A prologue + GEMM + residual + LN ------
// t += (softmax_q(q)@ctx) @ o_w^T + o_b;  y = LN2(t)
#define OP_B_OFF 65536
#define OP_CTX_OFF 98304
#define OP_SMEM 106496

__global__ __launch_bounds__(256, 2) void oproj_kernel(
    const float* __restrict__ Wt, const float* __restrict__ bias,
    const float* __restrict__ gamma, const float* __restrict__ beta)
{
    extern __shared__ float sm[];
    uint32_t smem_u = (uint32_t)__cvta_generic_to_shared(sm);

    int tid  = threadIdx.x;
    int lane = tid & 31;
    int wid  = tid >> 5;
    int warp_m = wid & 1;
    int warp_n = wid >> 1;
    int m0 = blockIdx.x * GBM;
    int b  = m0 >> 10;

    int r0 = tid >> 3;
    int c8 = tid & 7;
    uint32_t cxor = (uint32_t)((c8 ^ (r0 & 7)) << 4);

    // prefetch B tile 0 (overlaps attn prologue)
#pragma unroll
    for (int i = 0; i < 4; i++) {
        int r = r0 + i * 32;
        cp_async16(smem_u + OP_B_OFF + (r << 7) + cxor, Wt + (size_t)r * E + c8 * 4);
    }
    CP_COMMIT();

    // ctx for this batch into smem
    float* ctxs = sm + OP_CTX_OFF / 4;
    for (int i = tid; i < 2048; i += 256) ctxs[i] = g_ctx[b * 2048 + i];
    __syncthreads();

    // ---- attention prologue: A[128][128] = rna(softmax_q(q) @ ctx) ----
    {
        int row = tid >> 1, half = tid & 1;
        const float* qrow = g_qkv + (size_t)(m0 + row) * QKV_N;
#pragma unroll
        for (int hh = 0; hh < 4; hh++) {
            int h = half * 4 + hh;
            float qv[16];
            const float4* q4 = (const float4*)(qrow + h * 16);
#pragma unroll
            for (int j = 0; j < 4; j++) {
                float4 t = q4[j];
                qv[4 * j] = t.x; qv[4 * j + 1] = t.y; qv[4 * j + 2] = t.z; qv[4 * j + 3] = t.w;
            }
            float mxv = -1e30f;
#pragma unroll
            for (int d = 0; d < 16; d++) mxv = fmaxf(mxv, qv[d]);
            float s = 0.f;
#pragma unroll
            for (int d = 0; d < 16; d++) { qv[d] = expf(qv[d] - mxv); s += qv[d]; }
            float r = 0.25f / s;
            const float* cb = ctxs + h * 256;
#pragma unroll
            for (int e2 = 0; e2 < 16; e2 += 2) {
                float a0 = 0.f, a1 = 0.f;
#pragma unroll
                for (int d = 0; d < 16; d++) {
                    float qq = qv[d];
                    a0 += qq * cb[d * 16 + e2];
                    a1 += qq * cb[d * 16 + e2 + 1];
                }
                int col = h * 16 + e2;
                int chunk = col >> 2, stage = chunk >> 3, c8a = chunk & 7, w = col & 3;
                float2* p = (float2*)(sm + stage * 4096 + row * 32 + ((c8a ^ (row & 7)) << 2) + w);
                *p = make_float2(rna_tf32(a0 * r), rna_tf32(a1 * r));
            }
        }
    }

    int sub = lane >> 3;
    int l7  = lane & 7;
    int selA = sub >> 1;
    int rowAoff = ((sub & 1) << 3) + l7;
    int selB = sub & 1;
    int rowBoff = ((sub >> 1) << 3) + l7;

    float acc[4][4][4];
#pragma unroll
    for (int i = 0; i < 4; i++)
#pragma unroll
        for (int j = 0; j < 4; j++)
#pragma unroll
            for (int k = 0; k < 4; k++) acc[i][j][k] = 0.f;

    for (int it = 0; it < 4; it++) {
        CP_WAIT0();
        __syncthreads();
        if (it + 1 < 4) {
#pragma unroll
            for (int i = 0; i < 4; i++) {
                int r = r0 + i * 32;
                cp_async16(smem_u + OP_B_OFF + ((it + 1) & 1) * 16384 + (r << 7) + cxor,
                           Wt + (size_t)r * E + (it + 1) * 32 + c8 * 4);
            }
            CP_COMMIT();
        }
        uint32_t baseA = smem_u + it * 16384;
        uint32_t baseB = smem_u + OP_B_OFF + (it & 1) * 16384;
#pragma unroll
        for (int ks = 0; ks < 4; ks++) {
            int cb = ks * 2;
            uint32_t a[4][4], bb[4][2];
#pragma unroll
            for (int mt = 0; mt < 4; mt++) {
                int row = warp_m * 64 + mt * 16 + rowAoff;
                uint32_t addr = baseA + (row << 7) + (uint32_t)(((cb + selA) ^ (row & 7)) << 4);
                LDSM4(a[mt][0], a[mt][1], a[mt][2], a[mt][3], addr);
            }
#pragma unroll
            for (int bt = 0; bt < 2; bt++) {
                int row = warp_n * 32 + bt * 16 + rowBoff;
                uint32_t addr = baseB + (row << 7) + (uint32_t)(((cb + selB) ^ (row & 7)) << 4);
                LDSM4(bb[2 * bt][0], bb[2 * bt][1], bb[2 * bt + 1][0], bb[2 * bt + 1][1], addr);
            }
#pragma unroll
            for (int mt = 0; mt < 4; mt++)
#pragma unroll
                for (int nt = 0; nt < 4; nt++)
                    MMA_TF32(acc[mt][nt], a[mt], bb[nt]);
        }
    }

    // ---- epilogue: bias + residual into g_t, stage for LN ----
    int g  = lane >> 2;
    int t4 = lane & 3;
    __syncthreads();
#pragma unroll
    for (int mt = 0; mt < 4; mt++) {
        int rowl0 = warp_m * 64 + mt * 16 + g;
#pragma unroll
        for (int nt = 0; nt < 4; nt++) {
            int col = warp_n * 32 + nt * 8 + t4 * 2;
            float b0 = bias[col], b1 = bias[col + 1];
#pragma unroll
            for (int half = 0; half < 2; half++) {
                int rowl = rowl0 + half * 8;
                float2* p = (float2*)(g_t + (size_t)(m0 + rowl) * E + col);
                float2 o = *p;
                float f0 = acc[mt][nt][half * 2]     + b0 + o.x;
                float f1 = acc[mt][nt][half * 2 + 1] + b1 + o.y;
                *p = make_float2(f0, f1);
                sm[rowl * 132 + col]     = f0;
                sm[rowl * 132 + col + 1] = f1;
            }
        }
    }
    __syncthreads();
    // ---- LN over staged rows -> g_y ----
    float g4[4], b4[4];
#pragma unroll
    for (int j = 0; j < 4; j++) { g4[j] = gamma[lane + 32 * j]; b4[j] = beta[lane + 32 * j]; }
    for (int rr = 0; rr < 16; rr++) {
        int row = wid * 16 + rr;
        float x[4];
#pragma unroll
        for (int j = 0; j < 4; j++) x[j] = sm[row * 132 + lane + 32 * j];
        float s = x[0] + x[1] + x[2] + x[3];
#pragma unroll
        for (int o = 16; o > 0; o >>= 1) s += __shfl_xor_sync(0xffffffffu, s, o);
        float mu = s * (1.0f / E);
        float s2 = 0.f;
#pragma unroll
        for (int j = 0; j < 4; j++) { float d = x[j] - mu; s2 += d * d; }
#pragma unroll
        for (int o = 16; o > 0; o >>= 1) s2 += __shfl_xor_sync(0xffffffffu, s2, o);
        float rs = rsqrtf(s2 * (1.0f / E) + LN_EPS);
#pragma unroll
        for (int j = 0; j < 4; j++)
            g_y[(size_t)(m0 + row) * E + lane + 32 * j] =
                rna_tf32((x[j] - mu) * rs * g4[j] + b4[j]);
    }
}

// ---------------- fused FF: t += gelu(y@W1+b1)@W2 + b2; y = LN(t) -----------
// 64-row tiles, hidden computed in 128-col chunks staged in smem.
#define FF_H_OFF 32768          // bytes: H region
#define FF_B_OFF 65536          // bytes: B double buffer
#define FF_SMEM 98304

__global__ __launch_bounds__(256, 2) void fused_ff_kernel(
    const float* __restrict__ W1t,   // [512][128]
    const float* __restrict__ b1,
    const float* __restrict__ W2t,   // [128][512]
    const float* __restrict__ b2,
    const float* __restrict__ gamma, const float* __restrict__ beta)
{
    extern __shared__ float sm[];
    uint32_t smem_u = (uint32_t)__cvta_generic_to_shared(sm);

    int tid  = threadIdx.x;
    int lane = tid & 31;
    int wid  = tid >> 5;
    int warp_m = wid & 1;            // 2 x 32-row slabs
    int warp_n = wid >> 1;           // 4 x 32-col slabs
    int m0 = blockIdx.x * 64;

    int r0 = tid >> 3;
    int c8 = tid & 7;
    uint32_t cxor = (uint32_t)((c8 ^ (r0 & 7)) << 4);

    // prefetch first B tile (w1 chunk0 kt0)
#pragma unroll
    for (int i = 0; i < 4; i++) {
        int r = r0 + i * 32;
        cp_async16(smem_u + FF_B_OFF + (r << 7) + cxor, W1t + (size_t)r * E + c8 * 4);
    }
    CP_COMMIT();

    // load Y tile (64x128) into swizzled stages [0,32768)
    for (int l = tid; l < 64 * 32; l += 256) {   // 2048 chunks
        int row = l >> 5, chunk = l & 31;
        int stage = chunk >> 3, cc = chunk & 7;
        float4 v = *(const float4*)(g_y + (size_t)(m0 + row) * E + chunk * 4);
        *(float4*)(sm + stage * 2048 + row * 32 + ((cc ^ (row & 7)) << 2)) = v;
    }

    int sub = lane >> 3;
    int l7  = lane & 7;
    int selA = sub >> 1;
    int rowAoff = ((sub & 1) << 3) + l7;
    int selB = sub & 1;
    int rowBoff = ((sub >> 1) << 3) + l7;
    int g  = lane >> 2;
    int t4 = lane & 3;

    float out_acc[2][4][4];
#pragma unroll
    for (int i = 0; i < 2; i++)
#pragma unroll
        for (int j = 0; j < 4; j++)
#pragma unroll
            for (int k = 0; k < 4; k++) out_acc[i][j][k] = 0.f;

    float acc1[2][4][4];

    for (int t = 0; t < 32; t++) {
        int phase = (t >> 2) & 1;    // 0=FF1, 1=FF2
        int c     = t >> 3;
        int kt    = t & 3;

        CP_WAIT0();
        __syncthreads();

        // prefetch next tile
        if (t + 1 < 32) {
            int np = ((t + 1) >> 2) & 1, nc = (t + 1) >> 3, nk = (t + 1) & 3;
#pragma unroll
            for (int i = 0; i < 4; i++) {
                int r = r0 + i * 32;
                const float* src = np
                    ? (W2t + (size_t)r * DFF + nc * 128 + nk * 32 + c8 * 4)
                    : (W1t + (size_t)(nc * 128 + r) * E + nk * 32 + c8 * 4);
                cp_async16(smem_u + FF_B_OFF + ((t + 1) & 1) * 16384 + (r << 7) + cxor, src);
            }
            CP_COMMIT();
        }

        if (phase == 0 && kt == 0) {
#pragma unroll
            for (int i = 0; i < 2; i++)
#pragma unroll
                for (int j = 0; j < 4; j++)
#pragma unroll
                    for (int k = 0; k < 4; k++) acc1[i][j][k] = 0.f;
        }

        uint32_t baseA = smem_u + (phase ? FF_H_OFF : 0) + kt * 8192;
        uint32_t baseB = smem_u + FF_B_OFF + (t & 1) * 16384;
        float (*accp)[4][4] = phase ? out_acc : acc1;

#pragma unroll
        for (int ks = 0; ks < 4; ks++) {
            int cb = ks * 2;
            uint32_t a[2][4], bb[4][2];
#pragma unroll
            for (int mt = 0; mt < 2; mt++) {
                int row = warp_m * 32 + mt * 16 + rowAoff;
                uint32_t addr = baseA + (row << 7) + (uint32_t)(((cb + selA) ^ (row & 7)) << 4);
                LDSM4(a[mt][0], a[mt][1], a[mt][2], a[mt][3], addr);
            }
#pragma unroll
            for (int bt = 0; bt < 2; bt++) {
                int row = warp_n * 32 + bt * 16 + rowBoff;
                uint32_t addr = baseB + (row << 7) + (uint32_t)(((cb + selB) ^ (row & 7)) << 4);
                LDSM4(bb[2 * bt][0], bb[2 * bt][1], bb[2 * bt + 1][0], bb[2 * bt + 1][1], addr);
            }
#pragma unroll
            for (int mt = 0; mt < 2; mt++)
#pragma unroll
                for (int nt = 0; nt < 4; nt++)
                    MMA_TF32(accp[mt][nt], a[mt], bb[nt]);
        }

        // end of FF1 phase for chunk c: gelu + bias -> H smem (tf32)
        if (phase == 0 && kt == 3) {
#pragma unroll
            for (int mt = 0; mt < 2; mt++) {
                int rowl0 = warp_m * 32 + mt * 16 + g;
#pragma unroll
                for (int nt = 0; nt < 4; nt++) {
                    int coll = warp_n * 32 + nt * 8 + t4 * 2;
                    float bb0 = b1[c * 128 + coll], bb1 = b1[c * 128 + coll + 1];
                    int chunk = coll >> 2, stage = chunk >> 3, cch = chunk & 7, w = coll & 3;
#pragma unroll
                    for (int half = 0; half < 2; half++) {
                        int row = rowl0 + half * 8;
                        float v0 = rna_tf32(gelu_f(acc1[mt][nt][half * 2]     + bb0));
                        float v1 = rna_tf32(gelu_f(acc1[mt][nt][half * 2 + 1] + bb1));
                        *(float2*)(sm + FF_H_OFF / 4 + stage * 2048 + row * 32 +
                                   ((cch ^ (row & 7)) << 2) + w) = make_float2(v0, v1);
                    }
                }
            }
        }
    }

    // ---- epilogue: bias + residual into g_t (+ optional LN -> g_y) ----
    bool do_ln = (gamma != nullptr);
    __syncthreads();
#pragma unroll
    for (int mt = 0; mt < 2; mt++) {
        int rowl0 = warp_m * 32 + mt * 16 + g;
#pragma unroll
        for (int nt = 0; nt < 4; nt++) {
            int col = warp_n * 32 + nt * 8 + t4 * 2;
            float bb0 = b2[col], bb1 = b2[col + 1];
#pragma unroll
            for (int half = 0; half < 2; half++) {
                int rowl = rowl0 + half * 8;
                float2* p = (float2*)(g_t + (size_t)(m0 + rowl) * E + col);
                float2 o = *p;
                float f0 = out_acc[mt][nt][half * 2]     + bb0 + o.x;
                float f1 = out_acc[mt][nt][half * 2 + 1] + bb1 + o.y;
                *p = make_float2(f0, f1);
                if (do_ln) {
                    sm[rowl * 132 + col]     = f0;
                    sm[rowl * 132 + col + 1] = f1;
                }
            }
        }
    }
    if (do_ln) {
        __syncthreads();
        float g4[4], b4[4];
#pragma unroll
        for (int j = 0; j < 4; j++) { g4[j] = gamma[lane + 32 * j]; b4[j] = beta[lane + 32 * j]; }
        for (int rr = 0; rr < 8; rr++) {
            int row = wid * 8 + rr;
            float x[4];
#pragma unroll
            for (int j = 0; j < 4; j++) x[j] = sm[row * 132 + lane + 32 * j];
            float s = x[0] + x[1] + x[2] + x[3];
#pragma unroll
            for (int o = 16; o > 0; o >>= 1) s += __shfl_xor_sync(0xffffffffu, s, o);
            float mu = s * (1.0f / E);
            float s2 = 0.f;
#pragma unroll
            for (int j = 0; j < 4; j++) { float d = x[j] - mu; s2 += d * d; }
#pragma unroll
            for (int o = 16; o > 0; o >>= 1) s2 += __shfl_xor_sync(0xffffffffu, s2, o);
            float rs = rsqrtf(s2 * (1.0f / E) + LN_EPS);
#pragma unroll
            for (int j = 0; j < 4; j++)
                g_y[(size_t)(m0 + row) * E + lane + 32 * j] =
                    rna_tf32((x[j] - mu) * rs * g4[j] + b4[j]);
        }
    }
}

// ---------------- final mean over sequence ----------------------------------
__global__ void mean_kernel(float* __restrict__ out) {
    int b = blockIdx.x, e = threadIdx.x;
    const float* p = g_t + (size_t)b * NSEQ * E + e;
    float s = 0.f;
#pragma unroll 8
    for (int n = 0; n < NSEQ; n++) s += p[(size_t)n * E];
    out[b * E + e] = s * (1.0f / NSEQ);
}

// ---------------- launch -----------------------------------------------------
extern "C" void kernel_launch(void* const* d_in, const int* in_sizes, int n_in,
                              void* d_out, int out_size) {
    const float* x     = (const float*)d_in[0];
    const float* q_w   = (const float*)d_in[1];
    const float* k_w   = (const float*)d_in[2];
    const float* v_w   = (const float*)d_in[3];
    const float* o_w   = (const float*)d_in[4];
    const float* o_b   = (const float*)d_in[5];
    const float* ln1_g = (const float*)d_in[6];
    const float* ln1_b = (const float*)d_in[7];
    const float* ff_w1 = (const float*)d_in[8];
    const float* ff_b1 = (const float*)d_in[9];
    const float* ff_w2 = (const float*)d_in[10];
    const float* ff_b2 = (const float*)d_in[11];
    const float* ln2_g = (const float*)d_in[12];
    const float* ln2_b = (const float*)d_in[13];
    float* out = (float*)d_out;

    float *py, *pqkv, *pwt;
    cudaGetSymbolAddress((void**)&py,   g_y);
    cudaGetSymbolAddress((void**)&pqkv, g_qkv);
    cudaGetSymbolAddress((void**)&pwt,  g_wt);

    cudaFuncSetAttribute(qkv_gemm, cudaFuncAttributeMaxDynamicSharedMemorySize, QKV_SMEM);
    cudaFuncSetAttribute(oproj_kernel, cudaFuncAttributeMaxDynamicSharedMemorySize, OP_SMEM);
    cudaFuncSetAttribute(fused_ff_kernel, cudaFuncAttributeMaxDynamicSharedMemorySize, FF_SMEM);

    dim3 tb(32, 8);
    for (int l = 0; l < NLAYERS; l++) {
        float* wl = pwt + (size_t)l * WT_LAYER;
        wt_cvt_kernel<<<dim3(E / 32, E / 32), tb>>>(q_w + (size_t)l * E * E, wl, E, E);
        wt_cvt_kernel<<<dim3(E / 32, E / 32), tb>>>(k_w + (size_t)l * E * E, wl + 16384, E, E);
        wt_cvt_kernel<<<dim3(E / 32, E / 32), tb>>>(v_w + (size_t)l * E * E, wl + 32768, E, E);
        wt_cvt_kernel<<<dim3(E / 32, E / 32), tb>>>(o_w + (size_t)l * E * E, wl + 49152, E, E);
        wt_cvt_kernel<<<dim3(DFF / 32, E / 32), tb>>>(ff_w1 + (size_t)l * E * DFF, wl + 65536, E, DFF);
        wt_cvt_kernel<<<dim3(E / 32, DFF / 32), tb>>>(ff_w2 + (size_t)l * DFF * E, wl + 131072, DFF, E);
    }
    transpose_kernel<<<dim3(NSEQ / 32, E / 32, BATCH), tb>>>(x);
    ln_kernel<<<MROWS, E>>>(ln1_g, ln1_b);

    for (int l = 0; l < NLAYERS; l++) {
        const float* wl = pwt + (size_t)l * WT_LAYER;
        qkv_gemm<<<dim3(QKV_N / GBN, MROWS / GBM), 256, QKV_SMEM>>>(py, wl, pqkv);
        ctx_kernel<<<BATCH * NHEADS, 256>>>();
        oproj_kernel<<<MROWS / GBM, 256, OP_SMEM>>>(wl + 49152, o_b + l * E,
                                                    ln2_g + l * E, ln2_b + l * E);
        if (l < NLAYERS - 1) {
            fused_ff_kernel<<<MROWS / 64, 256, FF_SMEM>>>(
                wl + 65536, ff_b1 + l * DFF, wl + 131072, ff_b2 + l * E,
                ln1_g + (l + 1) * E, ln1_b + (l + 1) * E);
        } else {
            fused_ff_kernel<<<MROWS / 64, 256, FF_SMEM>>>(
                wl + 65536, ff_b1 + l * DFF, wl + 131072, ff_b2 + l * E,
                nullptr, nullptr);
        }
    }

    mean_kernel<<<BATCH, E>>>(out);
}

// round 5
// speedup vs baseline: 1.4328x; 1.4328x over previous
#include <cuda_runtime.h>
#include <math.h>
#include <stdint.h>

#define BATCH 64
#define E 128
#define NSEQ 1024
#define NHEADS 8
#define DH 16
#define DFF 512
#define MROWS (BATCH * NSEQ)   // 65536
#define NLAYERS 4
#define LN_EPS 1e-5f
#define QKV_N 384

// ---------------- scratch (static device globals; allocation-free) ----------
__device__ float g_t[MROWS * E];          // residual stream fp32
__device__ float g_y[MROWS * E];          // layernorm output (tf32-rounded)
__device__ float g_qkv[MROWS * QKV_N];    // fused q|k|v, row stride 384
__device__ float g_ctx[BATCH * NHEADS * DH * DH];
__device__ float g_ff[MROWS * DFF];       // gelu out (tf32-rounded)
// transposed+tf32 weights per layer: qkv^T(49152), o^T(16384), ff1^T(65536), ff2^T(65536)
#define WT_LAYER 196608
__device__ float g_wt[NLAYERS * WT_LAYER];

__device__ __forceinline__ float rna_tf32(float x) {
    uint32_t u;
    asm("cvt.rna.tf32.f32 %0, %1;" : "=r"(u) : "f"(x));
    return __uint_as_float(u);
}

__device__ __forceinline__ float gelu_f(float x) {
    float x3 = x * x * x;
    return 0.5f * x * (1.0f + tanhf(0.7978845608028654f * (x + 0.044715f * x3)));
}

#define LDSM4(d0, d1, d2, d3, addr) \
    asm volatile("ldmatrix.sync.aligned.m8n8.x4.shared.b16 {%0,%1,%2,%3}, [%4];" \
                 : "=r"(d0), "=r"(d1), "=r"(d2), "=r"(d3) : "r"(addr))

#define MMA_TF32(c, a, b) \
    asm volatile("mma.sync.aligned.m16n8k8.row.col.f32.tf32.tf32.f32 " \
                 "{%0,%1,%2,%3},{%4,%5,%6,%7},{%8,%9},{%0,%1,%2,%3};" \
                 : "+f"((c)[0]), "+f"((c)[1]), "+f"((c)[2]), "+f"((c)[3]) \
                 : "r"((a)[0]), "r"((a)[1]), "r"((a)[2]), "r"((a)[3]), \
                   "r"((b)[0]), "r"((b)[1]))

__device__ __forceinline__ void cp_async16(uint32_t dst, const void* src) {
    asm volatile("cp.async.cg.shared.global [%0], [%1], 16;" :: "r"(dst), "l"(src));
}
#define CP_COMMIT() asm volatile("cp.async.commit_group;")
#define CP_WAIT0()  asm volatile("cp.async.wait_group 0;")
#define CP_WAIT1()  asm volatile("cp.async.wait_group 1;")

// ---------------- transpose x:(B,E,N) -> t:(B,N,E) --------------------------
__global__ void transpose_kernel(const float* __restrict__ x) {
    __shared__ float tile[32][33];
    int b  = blockIdx.z;
    int n0 = blockIdx.x * 32;
    int e0 = blockIdx.y * 32;
    int tx = threadIdx.x, ty = threadIdx.y;   // (32,8)
#pragma unroll
    for (int i = 0; i < 32; i += 8)
        tile[ty + i][tx] = x[(size_t)b * E * NSEQ + (size_t)(e0 + ty + i) * NSEQ + n0 + tx];
    __syncthreads();
#pragma unroll
    for (int i = 0; i < 32; i += 8)
        g_t[(size_t)b * NSEQ * E + (size_t)(n0 + ty + i) * E + e0 + tx] = tile[tx][ty + i];
}

// ---------------- fused weight convert (ALL layers/matrices, one launch) ----
__global__ void wt_cvt_all(const float* __restrict__ q_w, const float* __restrict__ k_w,
                           const float* __restrict__ v_w, const float* __restrict__ o_w,
                           const float* __restrict__ ff_w1, const float* __restrict__ ff_w2) {
    __shared__ float tile[32][33];
    int l  = blockIdx.y;
    int id = blockIdx.x;
    float* wl = g_wt + (size_t)l * WT_LAYER;

    const float* src;
    float* dst;
    int K, N, tn, tk;
    if (id < 64) {
        int m = id >> 4;
        const float* srcs[4] = { q_w, k_w, v_w, o_w };
        src = srcs[m] + (size_t)l * E * E;
        dst = wl + m * 16384;
        K = E; N = E;
        int t = id & 15; tn = t & 3; tk = t >> 2;
    } else if (id < 128) {
        src = ff_w1 + (size_t)l * E * DFF;
        dst = wl + 65536;
        K = E; N = DFF;
        int t = id - 64; tn = t & 15; tk = t >> 4;
    } else {
        src = ff_w2 + (size_t)l * DFF * E;
        dst = wl + 131072;
        K = DFF; N = E;
        int t = id - 128; tn = t & 3; tk = t >> 2;
    }
    int n0 = tn * 32, k0 = tk * 32;
    int tx = threadIdx.x, ty = threadIdx.y;   // (32,8)
#pragma unroll
    for (int i = 0; i < 32; i += 8)
        tile[ty + i][tx] = src[(size_t)(k0 + ty + i) * N + n0 + tx];
    __syncthreads();
#pragma unroll
    for (int i = 0; i < 32; i += 8)
        dst[(size_t)(n0 + ty + i) * K + k0 + tx] = rna_tf32(tile[tx][ty + i]);
}

// ---------------- standalone layernorm (layer-0 entry only) -----------------
__global__ void ln_kernel(const float* __restrict__ gamma, const float* __restrict__ beta) {
    int m = blockIdx.x;
    int e = threadIdx.x;
    float v = g_t[(size_t)m * E + e];
    __shared__ float red[4];
    float s = v;
#pragma unroll
    for (int o = 16; o > 0; o >>= 1) s += __shfl_down_sync(0xffffffffu, s, o);
    if ((e & 31) == 0) red[e >> 5] = s;
    __syncthreads();
    float mu = (red[0] + red[1] + red[2] + red[3]) * (1.0f / E);
    __syncthreads();
    float d = v - mu;
    float s2 = d * d;
#pragma unroll
    for (int o = 16; o > 0; o >>= 1) s2 += __shfl_down_sync(0xffffffffu, s2, o);
    if ((e & 31) == 0) red[e >> 5] = s2;
    __syncthreads();
    float var = (red[0] + red[1] + red[2] + red[3]) * (1.0f / E);
    g_y[(size_t)m * E + e] = rna_tf32(d * rsqrtf(var + LN_EPS) * gamma[e] + beta[e]);
}

// ---------------- generic TF32 GEMM, 3-stage pipeline -----------------------
// flags: 1=gelu, 2=residual add, 4=tf32-round C, 8=fused LN -> Y (N=128, grid.x=1)
#define GBM 128
#define GBN 128
#define NSTAGE 3
#define STAGE_BYTES 16384
#define BSMEM_OFF (NSTAGE * STAGE_BYTES)
#define SMEM_BYTES (2 * NSTAGE * STAGE_BYTES)   // 98304

__global__ __launch_bounds__(256, 2) void mma_gemm(
    const float* __restrict__ A, const float* __restrict__ Wt,
    const float* __restrict__ bias, float* __restrict__ C,
    const float* __restrict__ gamma, const float* __restrict__ beta,
    float* __restrict__ Y,
    int K, int N, int flags)
{
    extern __shared__ float sm[];
    uint32_t smem_u = (uint32_t)__cvta_generic_to_shared(sm);

    int tid  = threadIdx.x;
    int lane = tid & 31;
    int wid  = tid >> 5;
    int warp_m = wid & 1;
    int warp_n = wid >> 1;
    int bm0 = blockIdx.y * GBM;
    int bn0 = blockIdx.x * GBN;

    int r0 = tid >> 3;
    int c8 = tid & 7;
    uint32_t cxor = (uint32_t)((c8 ^ (r0 & 7)) << 4);

    int sub = lane >> 3;
    int l7  = lane & 7;
    int selA = sub >> 1;
    int rowAoff = ((sub & 1) << 3) + l7;
    int selB = sub & 1;
    int rowBoff = ((sub >> 1) << 3) + l7;

    float acc[4][4][4];
#pragma unroll
    for (int i = 0; i < 4; i++)
#pragma unroll
        for (int j = 0; j < 4; j++)
#pragma unroll
            for (int k = 0; k < 4; k++) acc[i][j][k] = 0.f;

    int nIter = K >> 5;

    auto load_tile = [&](int s, int k0) {
#pragma unroll
        for (int i = 0; i < 4; i++) {
            int r = r0 + i * 32;
            uint32_t doff = (uint32_t)(r << 7) + cxor;
            cp_async16(smem_u + s * STAGE_BYTES + doff, A + (size_t)(bm0 + r) * K + k0 + c8 * 4);
            cp_async16(smem_u + BSMEM_OFF + s * STAGE_BYTES + doff, Wt + (size_t)(bn0 + r) * K + k0 + c8 * 4);
        }
    };

    load_tile(0, 0);  CP_COMMIT();
    load_tile(1, 32); CP_COMMIT();

    for (int it = 0; it < nIter; it++) {
        if (it < nIter - 1) CP_WAIT1(); else CP_WAIT0();
        __syncthreads();

        int s = it % NSTAGE;
        uint32_t baseA = smem_u + s * STAGE_BYTES;
        uint32_t baseB = smem_u + BSMEM_OFF + s * STAGE_BYTES;

#pragma unroll
        for (int ks = 0; ks < 4; ks++) {
            int cb = ks * 2;
            uint32_t a[4][4], b[4][2];
#pragma unroll
            for (int mt = 0; mt < 4; mt++) {
                int row = warp_m * 64 + mt * 16 + rowAoff;
                uint32_t addr = baseA + (row << 7) + (uint32_t)(((cb + selA) ^ (row & 7)) << 4);
                LDSM4(a[mt][0], a[mt][1], a[mt][2], a[mt][3], addr);
            }
#pragma unroll
            for (int bt = 0; bt < 2; bt++) {
                int row = warp_n * 32 + bt * 16 + rowBoff;
                uint32_t addr = baseB + (row << 7) + (uint32_t)(((cb + selB) ^ (row & 7)) << 4);
                LDSM4(b[2 * bt][0], b[2 * bt][1], b[2 * bt + 1][0], b[2 * bt + 1][1], addr);
            }
#pragma unroll
            for (int mt = 0; mt < 4; mt++)
#pragma unroll
                for (int nt = 0; nt < 4; nt++)
                    MMA_TF32(acc[mt][nt], a[mt], b[nt]);
        }

        if (it + 2 < nIter) { load_tile((it + 2) % NSTAGE, (it + 2) * 32); CP_COMMIT(); }
    }

    int g  = lane >> 2;
    int t4 = lane & 3;
    bool do_ln = (flags & 8) != 0;
    if (do_ln) __syncthreads();

#pragma unroll
    for (int mt = 0; mt < 4; mt++) {
        int rowl0 = warp_m * 64 + mt * 16 + g;
#pragma unroll
        for (int nt = 0; nt < 4; nt++) {
            int coll = warp_n * 32 + nt * 8 + t4 * 2;
            int col  = bn0 + coll;
            float v[4] = { acc[mt][nt][0], acc[mt][nt][1], acc[mt][nt][2], acc[mt][nt][3] };
            if (bias) {
                float b0 = bias[col], b1 = bias[col + 1];
                v[0] += b0; v[1] += b1; v[2] += b0; v[3] += b1;
            }
            if (flags & 1) {
#pragma unroll
                for (int z = 0; z < 4; z++) v[z] = gelu_f(v[z]);
            }
            if (flags & 4) {
#pragma unroll
                for (int z = 0; z < 4; z++) v[z] = rna_tf32(v[z]);
            }
#pragma unroll
            for (int half = 0; half < 2; half++) {
                int rowl = rowl0 + half * 8;
                float2* p = (float2*)(C + (size_t)(bm0 + rowl) * N + col);
                float f0 = v[half * 2], f1 = v[half * 2 + 1];
                if (flags & 2) {
                    float2 o = *p;
                    f0 += o.x; f1 += o.y;
                }
                *p = make_float2(f0, f1);
                if (do_ln) {
                    sm[rowl * 132 + coll]     = f0;
                    sm[rowl * 132 + coll + 1] = f1;
                }
            }
        }
    }

    if (do_ln) {
        __syncthreads();
        float g4[4], b4[4];
#pragma unroll
        for (int j = 0; j < 4; j++) {
            g4[j] = gamma[lane + 32 * j];
            b4[j] = beta[lane + 32 * j];
        }
        for (int r = 0; r < 16; r++) {
            int row = wid * 16 + r;
            float x[4];
#pragma unroll
            for (int j = 0; j < 4; j++) x[j] = sm[row * 132 + lane + 32 * j];
            float s = x[0] + x[1] + x[2] + x[3];
#pragma unroll
            for (int o = 16; o > 0; o >>= 1) s += __shfl_xor_sync(0xffffffffu, s, o);
            float mu = s * (1.0f / E);
            float s2 = 0.f;
#pragma unroll
            for (int j = 0; j < 4; j++) { float d = x[j] - mu; s2 += d * d; }
#pragma unroll
            for (int o = 16; o > 0; o >>= 1) s2 += __shfl_xor_sync(0xffffffffu, s2, o);
            float rs = rsqrtf(s2 * (1.0f / E) + LN_EPS);
#pragma unroll
            for (int j = 0; j < 4; j++)
                Y[(size_t)(bm0 + row) * E + lane + 32 * j] =
                    rna_tf32((x[j] - mu) * rs * g4[j] + b4[j]);
        }
    }
}

// ---------------- fused softmax_k + ctx per (b,h) ---------------------------
__global__ void ctx_kernel() {
    int bh = blockIdx.x;
    int b = bh >> 3, h = bh & 7;
    const float* kbase = g_qkv + (size_t)b * NSEQ * QKV_N + E + h * DH;
    const float* vbase = kbase + E;
    int tid = threadIdx.x;

    __shared__ float smax[16][17];
    __shared__ float mx[16];
    int d0 = tid & 15, i0 = tid >> 4;
    float m = -1e30f;
    for (int i = 0; i < 64; i++) {
        int n = i0 + i * 16;
        m = fmaxf(m, kbase[(size_t)n * QKV_N + d0]);
    }
    smax[d0][i0] = m;
    __syncthreads();
    if (tid < 16) {
        float t = smax[tid][0];
#pragma unroll
        for (int i = 1; i < 16; i++) t = fmaxf(t, smax[tid][i]);
        mx[tid] = t;
    }
    __syncthreads();

    __shared__ float ks[128][17];
    __shared__ float vs[128][17];
    int d = tid >> 4, e = tid & 15;
    float acc = 0.f, ssum = 0.f;
    for (int n0 = 0; n0 < NSEQ; n0 += 128) {
        __syncthreads();
        for (int l = tid; l < 128 * 16; l += 256) {
            int nl = l >> 4, c = l & 15;
            ks[nl][c] = expf(kbase[(size_t)(n0 + nl) * QKV_N + c] - mx[c]);
            vs[nl][c] = vbase[(size_t)(n0 + nl) * QKV_N + c];
        }
        __syncthreads();
#pragma unroll 8
        for (int nl = 0; nl < 128; nl++) {
            float kk = ks[nl][d];
            acc += kk * vs[nl][e];
            ssum += kk;
        }
    }
    g_ctx[bh * 256 + d * 16 + e] = acc / ssum;
}

// ---------------- o-proj: fused attn-A prologue + GEMM + residual + LN ------
#define OP_B_OFF 65536
#define OP_CTX_OFF 98304
#define OP_SMEM 106496

__global__ __launch_bounds__(256, 2) void oproj_kernel(
    const float* __restrict__ Wt, const float* __restrict__ bias,
    const float* __restrict__ gamma, const float* __restrict__ beta)
{
    extern __shared__ float sm[];
    uint32_t smem_u = (uint32_t)__cvta_generic_to_shared(sm);

    int tid  = threadIdx.x;
    int lane = tid & 31;
    int wid  = tid >> 5;
    int warp_m = wid & 1;
    int warp_n = wid >> 1;
    int m0 = blockIdx.x * GBM;
    int b  = m0 >> 10;

    int r0 = tid >> 3;
    int c8 = tid & 7;
    uint32_t cxor = (uint32_t)((c8 ^ (r0 & 7)) << 4);

#pragma unroll
    for (int i = 0; i < 4; i++) {
        int r = r0 + i * 32;
        cp_async16(smem_u + OP_B_OFF + (r << 7) + cxor, Wt + (size_t)r * E + c8 * 4);
    }
    CP_COMMIT();

    float* ctxs = sm + OP_CTX_OFF / 4;
    for (int i = tid; i < 2048; i += 256) ctxs[i] = g_ctx[b * 2048 + i];
    __syncthreads();

    {
        int row = tid >> 1, half = tid & 1;
        const float* qrow = g_qkv + (size_t)(m0 + row) * QKV_N;
#pragma unroll
        for (int hh = 0; hh < 4; hh++) {
            int h = half * 4 + hh;
            float qv[16];
            const float4* q4 = (const float4*)(qrow + h * 16);
#pragma unroll
            for (int j = 0; j < 4; j++) {
                float4 t = q4[j];
                qv[4 * j] = t.x; qv[4 * j + 1] = t.y; qv[4 * j + 2] = t.z; qv[4 * j + 3] = t.w;
            }
            float mxv = -1e30f;
#pragma unroll
            for (int d = 0; d < 16; d++) mxv = fmaxf(mxv, qv[d]);
            float s = 0.f;
#pragma unroll
            for (int d = 0; d < 16; d++) { qv[d] = expf(qv[d] - mxv); s += qv[d]; }
            float r = 0.25f / s;
            const float* cb = ctxs + h * 256;
#pragma unroll
            for (int e2 = 0; e2 < 16; e2 += 2) {
                float a0 = 0.f, a1 = 0.f;
#pragma unroll
                for (int d = 0; d < 16; d++) {
                    float qq = qv[d];
                    a0 += qq * cb[d * 16 + e2];
                    a1 += qq * cb[d * 16 + e2 + 1];
                }
                int col = h * 16 + e2;
                int chunk = col >> 2, stage = chunk >> 3, c8a = chunk & 7, w = col & 3;
                float2* p = (float2*)(sm + stage * 4096 + row * 32 + ((c8a ^ (row & 7)) << 2) + w);
                *p = make_float2(rna_tf32(a0 * r), rna_tf32(a1 * r));
            }
        }
    }

    int sub = lane >> 3;
    int l7  = lane & 7;
    int selA = sub >> 1;
    int rowAoff = ((sub & 1) << 3) + l7;
    int selB = sub & 1;
    int rowBoff = ((sub >> 1) << 3) + l7;

    float acc[4][4][4];
#pragma unroll
    for (int i = 0; i < 4; i++)
#pragma unroll
        for (int j = 0; j < 4; j++)
#pragma unroll
            for (int k = 0; k < 4; k++) acc[i][j][k] = 0.f;

    for (int it = 0; it < 4; it++) {
        CP_WAIT0();
        __syncthreads();
        if (it + 1 < 4) {
#pragma unroll
            for (int i = 0; i < 4; i++) {
                int r = r0 + i * 32;
                cp_async16(smem_u + OP_B_OFF + ((it + 1) & 1) * 16384 + (r << 7) + cxor,
                           Wt + (size_t)r * E + (it + 1) * 32 + c8 * 4);
            }
            CP_COMMIT();
        }
        uint32_t baseA = smem_u + it * 16384;
        uint32_t baseB = smem_u + OP_B_OFF + (it & 1) * 16384;
#pragma unroll
        for (int ks = 0; ks < 4; ks++) {
            int cb = ks * 2;
            uint32_t a[4][4], bb[4][2];
#pragma unroll
            for (int mt = 0; mt < 4; mt++) {
                int row = warp_m * 64 + mt * 16 + rowAoff;
                uint32_t addr = baseA + (row << 7) + (uint32_t)(((cb + selA) ^ (row & 7)) << 4);
                LDSM4(a[mt][0], a[mt][1], a[mt][2], a[mt][3], addr);
            }
#pragma unroll
            for (int bt = 0; bt < 2; bt++) {
                int row = warp_n * 32 + bt * 16 + rowBoff;
                uint32_t addr = baseB + (row << 7) + (uint32_t)(((cb + selB) ^ (row & 7)) << 4);
                LDSM4(bb[2 * bt][0], bb[2 * bt][1], bb[2 * bt + 1][0], bb[2 * bt + 1][1], addr);
            }
#pragma unroll
            for (int mt = 0; mt < 4; mt++)
#pragma unroll
                for (int nt = 0; nt < 4; nt++)
                    MMA_TF32(acc[mt][nt], a[mt], bb[nt]);
        }
    }

    int g  = lane >> 2;
    int t4 = lane & 3;
    __syncthreads();
#pragma unroll
    for (int mt = 0; mt < 4; mt++) {
        int rowl0 = warp_m * 64 + mt * 16 + g;
#pragma unroll
        for (int nt = 0; nt < 4; nt++) {
            int col = warp_n * 32 + nt * 8 + t4 * 2;
            float b0 = bias[col], b1 = bias[col + 1];
#pragma unroll
            for (int half = 0; half < 2; half++) {
                int rowl = rowl0 + half * 8;
                float2* p = (float2*)(g_t + (size_t)(m0 + rowl) * E + col);
                float2 o = *p;
                float f0 = acc[mt][nt][half * 2]     + b0 + o.x;
                float f1 = acc[mt][nt][half * 2 + 1] + b1 + o.y;
                *p = make_float2(f0, f1);
                sm[rowl * 132 + col]     = f0;
                sm[rowl * 132 + col + 1] = f1;
            }
        }
    }
    __syncthreads();
    float g4[4], b4[4];
#pragma unroll
    for (int j = 0; j < 4; j++) { g4[j] = gamma[lane + 32 * j]; b4[j] = beta[lane + 32 * j]; }
    for (int rr = 0; rr < 16; rr++) {
        int row = wid * 16 + rr;
        float x[4];
#pragma unroll
        for (int j = 0; j < 4; j++) x[j] = sm[row * 132 + lane + 32 * j];
        float s = x[0] + x[1] + x[2] + x[3];
#pragma unroll
        for (int o = 16; o > 0; o >>= 1) s += __shfl_xor_sync(0xffffffffu, s, o);
        float mu = s * (1.0f / E);
        float s2 = 0.f;
#pragma unroll
        for (int j = 0; j < 4; j++) { float d = x[j] - mu; s2 += d * d; }
#pragma unroll
        for (int o = 16; o > 0; o >>= 1) s2 += __shfl_xor_sync(0xffffffffu, s2, o);
        float rs = rsqrtf(s2 * (1.0f / E) + LN_EPS);
#pragma unroll
        for (int j = 0; j < 4; j++)
            g_y[(size_t)(m0 + row) * E + lane + 32 * j] =
                rna_tf32((x[j] - mu) * rs * g4[j] + b4[j]);
    }
}

// ---------------- final mean over sequence ----------------------------------
__global__ void mean_kernel(float* __restrict__ out) {
    int b = blockIdx.x, e = threadIdx.x;
    const float* p = g_t + (size_t)b * NSEQ * E + e;
    float s = 0.f;
#pragma unroll 8
    for (int n = 0; n < NSEQ; n++) s += p[(size_t)n * E];
    out[b * E + e] = s * (1.0f / NSEQ);
}

// ---------------- launch -----------------------------------------------------
extern "C" void kernel_launch(void* const* d_in, const int* in_sizes, int n_in,
                              void* d_out, int out_size) {
    const float* x     = (const float*)d_in[0];
    const float* q_w   = (const float*)d_in[1];
    const float* k_w   = (const float*)d_in[2];
    const float* v_w   = (const float*)d_in[3];
    const float* o_w   = (const float*)d_in[4];
    const float* o_b   = (const float*)d_in[5];
    const float* ln1_g = (const float*)d_in[6];
    const float* ln1_b = (const float*)d_in[7];
    const float* ff_w1 = (const float*)d_in[8];
    const float* ff_b1 = (const float*)d_in[9];
    const float* ff_w2 = (const float*)d_in[10];
    const float* ff_b2 = (const float*)d_in[11];
    const float* ln2_g = (const float*)d_in[12];
    const float* ln2_b = (const float*)d_in[13];
    float* out = (float*)d_out;

    float *pt, *py, *pqkv, *pff, *pwt;
    cudaGetSymbolAddress((void**)&pt,   g_t);
    cudaGetSymbolAddress((void**)&py,   g_y);
    cudaGetSymbolAddress((void**)&pqkv, g_qkv);
    cudaGetSymbolAddress((void**)&pff,  g_ff);
    cudaGetSymbolAddress((void**)&pwt,  g_wt);

    cudaFuncSetAttribute(mma_gemm, cudaFuncAttributeMaxDynamicSharedMemorySize, SMEM_BYTES);
    cudaFuncSetAttribute(oproj_kernel, cudaFuncAttributeMaxDynamicSharedMemorySize, OP_SMEM);

    // prepass: ONE fused weight-convert launch, input transpose, entry LN
    wt_cvt_all<<<dim3(192, NLAYERS), dim3(32, 8)>>>(q_w, k_w, v_w, o_w, ff_w1, ff_w2);
    transpose_kernel<<<dim3(NSEQ / 32, E / 32, BATCH), dim3(32, 8)>>>(x);
    ln_kernel<<<MROWS, E>>>(ln1_g, ln1_b);

    for (int l = 0; l < NLAYERS; l++) {
        const float* wl = pwt + (size_t)l * WT_LAYER;
        // fused QKV GEMM (N=384)
        mma_gemm<<<dim3(QKV_N / GBN, MROWS / GBM), 256, SMEM_BYTES>>>(
            py, wl, nullptr, pqkv, nullptr, nullptr, nullptr, E, QKV_N, 0);
        // fused softmax_k + ctx
        ctx_kernel<<<BATCH * NHEADS, 256>>>();
        // fused attn prologue + o-proj + residual + LN2 -> y
        oproj_kernel<<<MROWS / GBM, 256, OP_SMEM>>>(wl + 49152, o_b + l * E,
                                                    ln2_g + l * E, ln2_b + l * E);
        // FF1 + gelu (tf32-rounded)
        mma_gemm<<<dim3(DFF / GBN, MROWS / GBM), 256, SMEM_BYTES>>>(
            py, wl + 65536, ff_b1 + l * DFF, pff, nullptr, nullptr, nullptr, E, DFF, 1 | 4);
        // FF2 + residual (+ next-layer LN1 -> y)
        if (l < NLAYERS - 1) {
            mma_gemm<<<dim3(1, MROWS / GBM), 256, SMEM_BYTES>>>(
                pff, wl + 131072, ff_b2 + l * E, pt,
                ln1_g + (l + 1) * E, ln1_b + (l + 1) * E, py, DFF, E, 2 | 8);
        } else {
            mma_gemm<<<dim3(1, MROWS / GBM), 256, SMEM_BYTES>>>(
                pff, wl + 131072, ff_b2 + l * E, pt,
                nullptr, nullptr, nullptr, DFF, E, 2);
        }
    }

    mean_kernel<<<BATCH, E>>>(out);
}

// round 6
// speedup vs baseline: 1.4347x; 1.0013x over previous
#include <cuda_runtime.h>
#include <math.h>
#include <stdint.h>

#define BATCH 64
#define E 128
#define NSEQ 1024
#define NHEADS 8
#define DH 16
#define DFF 512
#define MROWS (BATCH * NSEQ)   // 65536
#define NLAYERS 4
#define LN_EPS 1e-5f
#define QKV_N 384

// ---------------- scratch (static device globals; allocation-free) ----------
__device__ float g_t[MROWS * E];          // residual stream fp32
__device__ float g_y[MROWS * E];          // layernorm output (tf32-rounded)
__device__ float g_qkv[MROWS * QKV_N];    // fused q|k|v, row stride 384
__device__ float g_ctx[BATCH * NHEADS * DH * DH];
__device__ float g_ff[MROWS * DFF];       // gelu out (tf32-rounded)
// transposed+tf32 weights per layer: qkv^T(49152), o^T(16384), ff1^T(65536), ff2^T(65536)
#define WT_LAYER 196608
__device__ float g_wt[NLAYERS * WT_LAYER];

__device__ __forceinline__ float rna_tf32(float x) {
    uint32_t u;
    asm("cvt.rna.tf32.f32 %0, %1;" : "=r"(u) : "f"(x));
    return __uint_as_float(u);
}

__device__ __forceinline__ float gelu_f(float x) {
    float x3 = x * x * x;
    return 0.5f * x * (1.0f + tanhf(0.7978845608028654f * (x + 0.044715f * x3)));
}

#define LDSM4(d0, d1, d2, d3, addr) \
    asm volatile("ldmatrix.sync.aligned.m8n8.x4.shared.b16 {%0,%1,%2,%3}, [%4];" \
                 : "=r"(d0), "=r"(d1), "=r"(d2), "=r"(d3) : "r"(addr))

#define MMA_TF32(c, a, b) \
    asm volatile("mma.sync.aligned.m16n8k8.row.col.f32.tf32.tf32.f32 " \
                 "{%0,%1,%2,%3},{%4,%5,%6,%7},{%8,%9},{%0,%1,%2,%3};" \
                 : "+f"((c)[0]), "+f"((c)[1]), "+f"((c)[2]), "+f"((c)[3]) \
                 : "r"((a)[0]), "r"((a)[1]), "r"((a)[2]), "r"((a)[3]), \
                   "r"((b)[0]), "r"((b)[1]))

__device__ __forceinline__ void cp_async16(uint32_t dst, const void* src) {
    asm volatile("cp.async.cg.shared.global [%0], [%1], 16;" :: "r"(dst), "l"(src));
}
#define CP_COMMIT() asm volatile("cp.async.commit_group;")
#define CP_WAIT0()  asm volatile("cp.async.wait_group 0;")
#define CP_WAIT1()  asm volatile("cp.async.wait_group 1;")

// ---------------- transpose x:(B,E,N) -> t:(B,N,E) --------------------------
__global__ void transpose_kernel(const float* __restrict__ x) {
    __shared__ float tile[32][33];
    int b  = blockIdx.z;
    int n0 = blockIdx.x * 32;
    int e0 = blockIdx.y * 32;
    int tx = threadIdx.x, ty = threadIdx.y;   // (32,8)
#pragma unroll
    for (int i = 0; i < 32; i += 8)
        tile[ty + i][tx] = x[(size_t)b * E * NSEQ + (size_t)(e0 + ty + i) * NSEQ + n0 + tx];
    __syncthreads();
#pragma unroll
    for (int i = 0; i < 32; i += 8)
        g_t[(size_t)b * NSEQ * E + (size_t)(n0 + ty + i) * E + e0 + tx] = tile[tx][ty + i];
}

// ---------------- fused weight convert (ALL layers/matrices, one launch) ----
__global__ void wt_cvt_all(const float* __restrict__ q_w, const float* __restrict__ k_w,
                           const float* __restrict__ v_w, const float* __restrict__ o_w,
                           const float* __restrict__ ff_w1, const float* __restrict__ ff_w2) {
    __shared__ float tile[32][33];
    int l  = blockIdx.y;
    int id = blockIdx.x;
    float* wl = g_wt + (size_t)l * WT_LAYER;

    const float* src;
    float* dst;
    int K, N, tn, tk;
    if (id < 64) {
        int m = id >> 4;
        const float* srcs[4] = { q_w, k_w, v_w, o_w };
        src = srcs[m] + (size_t)l * E * E;
        dst = wl + m * 16384;
        K = E; N = E;
        int t = id & 15; tn = t & 3; tk = t >> 2;
    } else if (id < 128) {
        src = ff_w1 + (size_t)l * E * DFF;
        dst = wl + 65536;
        K = E; N = DFF;
        int t = id - 64; tn = t & 15; tk = t >> 4;
    } else {
        src = ff_w2 + (size_t)l * DFF * E;
        dst = wl + 131072;
        K = DFF; N = E;
        int t = id - 128; tn = t & 3; tk = t >> 2;
    }
    int n0 = tn * 32, k0 = tk * 32;
    int tx = threadIdx.x, ty = threadIdx.y;   // (32,8)
#pragma unroll
    for (int i = 0; i < 32; i += 8)
        tile[ty + i][tx] = src[(size_t)(k0 + ty + i) * N + n0 + tx];
    __syncthreads();
#pragma unroll
    for (int i = 0; i < 32; i += 8)
        dst[(size_t)(n0 + ty + i) * K + k0 + tx] = rna_tf32(tile[tx][ty + i]);
}

// ---------------- standalone layernorm (layer-0 entry only) -----------------
__global__ void ln_kernel(const float* __restrict__ gamma, const float* __restrict__ beta) {
    int m = blockIdx.x;
    int e = threadIdx.x;
    float v = g_t[(size_t)m * E + e];
    __shared__ float red[4];
    float s = v;
#pragma unroll
    for (int o = 16; o > 0; o >>= 1) s += __shfl_down_sync(0xffffffffu, s, o);
    if ((e & 31) == 0) red[e >> 5] = s;
    __syncthreads();
    float mu = (red[0] + red[1] + red[2] + red[3]) * (1.0f / E);
    __syncthreads();
    float d = v - mu;
    float s2 = d * d;
#pragma unroll
    for (int o = 16; o > 0; o >>= 1) s2 += __shfl_down_sync(0xffffffffu, s2, o);
    if ((e & 31) == 0) red[e >> 5] = s2;
    __syncthreads();
    float var = (red[0] + red[1] + red[2] + red[3]) * (1.0f / E);
    g_y[(size_t)m * E + e] = rna_tf32(d * rsqrtf(var + LN_EPS) * gamma[e] + beta[e]);
}

// ---------------- generic TF32 GEMM, 3-stage pipeline -----------------------
// flags: 1=gelu, 2=residual add, 4=tf32-round C, 8=fused LN -> Y (N=128, grid.x=1)
#define GBM 128
#define GBN 128
#define NSTAGE 3
#define STAGE_BYTES 16384
#define BSMEM_OFF (NSTAGE * STAGE_BYTES)
#define SMEM_BYTES (2 * NSTAGE * STAGE_BYTES)   // 98304

__global__ __launch_bounds__(256, 2) void mma_gemm(
    const float* __restrict__ A, const float* __restrict__ Wt,
    const float* __restrict__ bias, float* __restrict__ C,
    const float* __restrict__ gamma, const float* __restrict__ beta,
    float* __restrict__ Y,
    int K, int N, int flags)
{
    extern __shared__ float sm[];
    uint32_t smem_u = (uint32_t)__cvta_generic_to_shared(sm);

    int tid  = threadIdx.x;
    int lane = tid & 31;
    int wid  = tid >> 5;
    int warp_m = wid & 1;
    int warp_n = wid >> 1;
    int bm0 = blockIdx.y * GBM;
    int bn0 = blockIdx.x * GBN;

    int r0 = tid >> 3;
    int c8 = tid & 7;
    uint32_t cxor = (uint32_t)((c8 ^ (r0 & 7)) << 4);

    int sub = lane >> 3;
    int l7  = lane & 7;
    int selA = sub >> 1;
    int rowAoff = ((sub & 1) << 3) + l7;
    int selB = sub & 1;
    int rowBoff = ((sub >> 1) << 3) + l7;

    float acc[4][4][4];
#pragma unroll
    for (int i = 0; i < 4; i++)
#pragma unroll
        for (int j = 0; j < 4; j++)
#pragma unroll
            for (int k = 0; k < 4; k++) acc[i][j][k] = 0.f;

    int nIter = K >> 5;

    auto load_tile = [&](int s, int k0) {
#pragma unroll
        for (int i = 0; i < 4; i++) {
            int r = r0 + i * 32;
            uint32_t doff = (uint32_t)(r << 7) + cxor;
            cp_async16(smem_u + s * STAGE_BYTES + doff, A + (size_t)(bm0 + r) * K + k0 + c8 * 4);
            cp_async16(smem_u + BSMEM_OFF + s * STAGE_BYTES + doff, Wt + (size_t)(bn0 + r) * K + k0 + c8 * 4);
        }
    };

    load_tile(0, 0);  CP_COMMIT();
    load_tile(1, 32); CP_COMMIT();

    for (int it = 0; it < nIter; it++) {
        if (it < nIter - 1) CP_WAIT1(); else CP_WAIT0();
        __syncthreads();

        int s = it % NSTAGE;
        uint32_t baseA = smem_u + s * STAGE_BYTES;
        uint32_t baseB = smem_u + BSMEM_OFF + s * STAGE_BYTES;

#pragma unroll
        for (int ks = 0; ks < 4; ks++) {
            int cb = ks * 2;
            uint32_t a[4][4], b[4][2];
#pragma unroll
            for (int mt = 0; mt < 4; mt++) {
                int row = warp_m * 64 + mt * 16 + rowAoff;
                uint32_t addr = baseA + (row << 7) + (uint32_t)(((cb + selA) ^ (row & 7)) << 4);
                LDSM4(a[mt][0], a[mt][1], a[mt][2], a[mt][3], addr);
            }
#pragma unroll
            for (int bt = 0; bt < 2; bt++) {
                int row = warp_n * 32 + bt * 16 + rowBoff;
                uint32_t addr = baseB + (row << 7) + (uint32_t)(((cb + selB) ^ (row & 7)) << 4);
                LDSM4(b[2 * bt][0], b[2 * bt][1], b[2 * bt + 1][0], b[2 * bt + 1][1], addr);
            }
#pragma unroll
            for (int mt = 0; mt < 4; mt++)
#pragma unroll
                for (int nt = 0; nt < 4; nt++)
                    MMA_TF32(acc[mt][nt], a[mt], b[nt]);
        }

        if (it + 2 < nIter) { load_tile((it + 2) % NSTAGE, (it + 2) * 32); CP_COMMIT(); }
    }

    int g  = lane >> 2;
    int t4 = lane & 3;
    bool do_ln = (flags & 8) != 0;
    if (do_ln) __syncthreads();

#pragma unroll
    for (int mt = 0; mt < 4; mt++) {
        int rowl0 = warp_m * 64 + mt * 16 + g;
#pragma unroll
        for (int nt = 0; nt < 4; nt++) {
            int coll = warp_n * 32 + nt * 8 + t4 * 2;
            int col  = bn0 + coll;
            float v[4] = { acc[mt][nt][0], acc[mt][nt][1], acc[mt][nt][2], acc[mt][nt][3] };
            if (bias) {
                float b0 = bias[col], b1 = bias[col + 1];
                v[0] += b0; v[1] += b1; v[2] += b0; v[3] += b1;
            }
            if (flags & 1) {
#pragma unroll
                for (int z = 0; z < 4; z++) v[z] = gelu_f(v[z]);
            }
            if (flags & 4) {
#pragma unroll
                for (int z = 0; z < 4; z++) v[z] = rna_tf32(v[z]);
            }
#pragma unroll
            for (int half = 0; half < 2; half++) {
                int rowl = rowl0 + half * 8;
                float2* p = (float2*)(C + (size_t)(bm0 + rowl) * N + col);
                float f0 = v[half * 2], f1 = v[half * 2 + 1];
                if (flags & 2) {
                    float2 o = *p;
                    f0 += o.x; f1 += o.y;
                }
                *p = make_float2(f0, f1);
                if (do_ln) {
                    sm[rowl * 132 + coll]     = f0;
                    sm[rowl * 132 + coll + 1] = f1;
                }
            }
        }
    }

    if (do_ln) {
        __syncthreads();
        float g4[4], b4[4];
#pragma unroll
        for (int j = 0; j < 4; j++) {
            g4[j] = gamma[lane + 32 * j];
            b4[j] = beta[lane + 32 * j];
        }
        for (int r = 0; r < 16; r++) {
            int row = wid * 16 + r;
            float x[4];
#pragma unroll
            for (int j = 0; j < 4; j++) x[j] = sm[row * 132 + lane + 32 * j];
            float s = x[0] + x[1] + x[2] + x[3];
#pragma unroll
            for (int o = 16; o > 0; o >>= 1) s += __shfl_xor_sync(0xffffffffu, s, o);
            float mu = s * (1.0f / E);
            float s2 = 0.f;
#pragma unroll
            for (int j = 0; j < 4; j++) { float d = x[j] - mu; s2 += d * d; }
#pragma unroll
            for (int o = 16; o > 0; o >>= 1) s2 += __shfl_xor_sync(0xffffffffu, s2, o);
            float rs = rsqrtf(s2 * (1.0f / E) + LN_EPS);
#pragma unroll
            for (int j = 0; j < 4; j++)
                Y[(size_t)(bm0 + row) * E + lane + 32 * j] =
                    rna_tf32((x[j] - mu) * rs * g4[j] + b4[j]);
        }
    }
}

// ---------------- fused softmax_k + ctx per (b,h) ---------------------------
__global__ void ctx_kernel() {
    int bh = blockIdx.x;
    int b = bh >> 3, h = bh & 7;
    const float* kbase = g_qkv + (size_t)b * NSEQ * QKV_N + E + h * DH;
    const float* vbase = kbase + E;
    int tid = threadIdx.x;

    __shared__ float smax[16][17];
    __shared__ float mx[16];
    int d0 = tid & 15, i0 = tid >> 4;
    float m = -1e30f;
    for (int i = 0; i < 64; i++) {
        int n = i0 + i * 16;
        m = fmaxf(m, kbase[(size_t)n * QKV_N + d0]);
    }
    smax[d0][i0] = m;
    __syncthreads();
    if (tid < 16) {
        float t = smax[tid][0];
#pragma unroll
        for (int i = 1; i < 16; i++) t = fmaxf(t, smax[tid][i]);
        mx[tid] = t;
    }
    __syncthreads();

    __shared__ float ks[128][17];
    __shared__ float vs[128][17];
    int d = tid >> 4, e = tid & 15;
    float acc = 0.f, ssum = 0.f;
    for (int n0 = 0; n0 < NSEQ; n0 += 128) {
        __syncthreads();
        for (int l = tid; l < 128 * 16; l += 256) {
            int nl = l >> 4, c = l & 15;
            ks[nl][c] = expf(kbase[(size_t)(n0 + nl) * QKV_N + c] - mx[c]);
            vs[nl][c] = vbase[(size_t)(n0 + nl) * QKV_N + c];
        }
        __syncthreads();
#pragma unroll 8
        for (int nl = 0; nl < 128; nl++) {
            float kk = ks[nl][d];
            acc += kk * vs[nl][e];
            ssum += kk;
        }
    }
    g_ctx[bh * 256 + d * 16 + e] = acc / ssum;
}

// ---------------- o-proj: fused attn-A prologue + GEMM + residual + LN ------
#define OP_B_OFF 65536
#define OP_CTX_OFF 98304
#define OP_SMEM 106496

__global__ __launch_bounds__(256, 2) void oproj_kernel(
    const float* __restrict__ Wt, const float* __restrict__ bias,
    const float* __restrict__ gamma, const float* __restrict__ beta)
{
    extern __shared__ float sm[];
    uint32_t smem_u = (uint32_t)__cvta_generic_to_shared(sm);

    int tid  = threadIdx.x;
    int lane = tid & 31;
    int wid  = tid >> 5;
    int warp_m = wid & 1;
    int warp_n = wid >> 1;
    int m0 = blockIdx.x * GBM;
    int b  = m0 >> 10;

    int r0 = tid >> 3;
    int c8 = tid & 7;
    uint32_t cxor = (uint32_t)((c8 ^ (r0 & 7)) << 4);

#pragma unroll
    for (int i = 0; i < 4; i++) {
        int r = r0 + i * 32;
        cp_async16(smem_u + OP_B_OFF + (r << 7) + cxor, Wt + (size_t)r * E + c8 * 4);
    }
    CP_COMMIT();

    float* ctxs = sm + OP_CTX_OFF / 4;
    for (int i = tid; i < 2048; i += 256) ctxs[i] = g_ctx[b * 2048 + i];
    __syncthreads();

    {
        int row = tid >> 1, half = tid & 1;
        const float* qrow = g_qkv + (size_t)(m0 + row) * QKV_N;
#pragma unroll
        for (int hh = 0; hh < 4; hh++) {
            int h = half * 4 + hh;
            float qv[16];
            const float4* q4 = (const float4*)(qrow + h * 16);
#pragma unroll
            for (int j = 0; j < 4; j++) {
                float4 t = q4[j];
                qv[4 * j] = t.x; qv[4 * j + 1] = t.y; qv[4 * j + 2] = t.z; qv[4 * j + 3] = t.w;
            }
            float mxv = -1e30f;
#pragma unroll
            for (int d = 0; d < 16; d++) mxv = fmaxf(mxv, qv[d]);
            float s = 0.f;
#pragma unroll
            for (int d = 0; d < 16; d++) { qv[d] = expf(qv[d] - mxv); s += qv[d]; }
            float r = 0.25f / s;
            const float* cb = ctxs + h * 256;
#pragma unroll
            for (int e2 = 0; e2 < 16; e2 += 2) {
                float a0 = 0.f, a1 = 0.f;
#pragma unroll
                for (int d = 0; d < 16; d++) {
                    float qq = qv[d];
                    a0 += qq * cb[d * 16 + e2];
                    a1 += qq * cb[d * 16 + e2 + 1];
                }
                int col = h * 16 + e2;
                int chunk = col >> 2, stage = chunk >> 3, c8a = chunk & 7, w = col & 3;
                float2* p = (float2*)(sm + stage * 4096 + row * 32 + ((c8a ^ (row & 7)) << 2) + w);
                *p = make_float2(rna_tf32(a0 * r), rna_tf32(a1 * r));
            }
        }
    }

    int sub = lane >> 3;
    int l7  = lane & 7;
    int selA = sub >> 1;
    int rowAoff = ((sub & 1) << 3) + l7;
    int selB = sub & 1;
    int rowBoff = ((sub >> 1) << 3) + l7;

    float acc[4][4][4];
#pragma unroll
    for (int i = 0; i < 4; i++)
#pragma unroll
        for (int j = 0; j < 4; j++)
#pragma unroll
            for (int k = 0; k < 4; k++) acc[i][j][k] = 0.f;

    for (int it = 0; it < 4; it++) {
        CP_WAIT0();
        __syncthreads();
        if (it + 1 < 4) {
#pragma unroll
            for (int i = 0; i < 4; i++) {
                int r = r0 + i * 32;
                cp_async16(smem_u + OP_B_OFF + ((it + 1) & 1) * 16384 + (r << 7) + cxor,
                           Wt + (size_t)r * E + (it + 1) * 32 + c8 * 4);
            }
            CP_COMMIT();
        }
        uint32_t baseA = smem_u + it * 16384;
        uint32_t baseB = smem_u + OP_B_OFF + (it & 1) * 16384;
#pragma unroll
        for (int ks = 0; ks < 4; ks++) {
            int cb = ks * 2;
            uint32_t a[4][4], bb[4][2];
#pragma unroll
            for (int mt = 0; mt < 4; mt++) {
                int row = warp_m * 64 + mt * 16 + rowAoff;
                uint32_t addr = baseA + (row << 7) + (uint32_t)(((cb + selA) ^ (row & 7)) << 4);
                LDSM4(a[mt][0], a[mt][1], a[mt][2], a[mt][3], addr);
            }
#pragma unroll
            for (int bt = 0; bt < 2; bt++) {
                int row = warp_n * 32 + bt * 16 + rowBoff;
                uint32_t addr = baseB + (row << 7) + (uint32_t)(((cb + selB) ^ (row & 7)) << 4);
                LDSM4(bb[2 * bt][0], bb[2 * bt][1], bb[2 * bt + 1][0], bb[2 * bt + 1][1], addr);
            }
#pragma unroll
            for (int mt = 0; mt < 4; mt++)
#pragma unroll
                for (int nt = 0; nt < 4; nt++)
                    MMA_TF32(acc[mt][nt], a[mt], bb[nt]);
        }
    }

    int g  = lane >> 2;
    int t4 = lane & 3;
    __syncthreads();
#pragma unroll
    for (int mt = 0; mt < 4; mt++) {
        int rowl0 = warp_m * 64 + mt * 16 + g;
#pragma unroll
        for (int nt = 0; nt < 4; nt++) {
            int col = warp_n * 32 + nt * 8 + t4 * 2;
            float b0 = bias[col], b1 = bias[col + 1];
#pragma unroll
            for (int half = 0; half < 2; half++) {
                int rowl = rowl0 + half * 8;
                float2* p = (float2*)(g_t + (size_t)(m0 + rowl) * E + col);
                float2 o = *p;
                float f0 = acc[mt][nt][half * 2]     + b0 + o.x;
                float f1 = acc[mt][nt][half * 2 + 1] + b1 + o.y;
                *p = make_float2(f0, f1);
                sm[rowl * 132 + col]     = f0;
                sm[rowl * 132 + col + 1] = f1;
            }
        }
    }
    __syncthreads();
    float g4[4], b4[4];
#pragma unroll
    for (int j = 0; j < 4; j++) { g4[j] = gamma[lane + 32 * j]; b4[j] = beta[lane + 32 * j]; }
    for (int rr = 0; rr < 16; rr++) {
        int row = wid * 16 + rr;
        float x[4];
#pragma unroll
        for (int j = 0; j < 4; j++) x[j] = sm[row * 132 + lane + 32 * j];
        float s = x[0] + x[1] + x[2] + x[3];
#pragma unroll
        for (int o = 16; o > 0; o >>= 1) s += __shfl_xor_sync(0xffffffffu, s, o);
        float mu = s * (1.0f / E);
        float s2 = 0.f;
#pragma unroll
        for (int j = 0; j < 4; j++) { float d = x[j] - mu; s2 += d * d; }
#pragma unroll
        for (int o = 16; o > 0; o >>= 1) s2 += __shfl_xor_sync(0xffffffffu, s2, o);
        float rs = rsqrtf(s2 * (1.0f / E) + LN_EPS);
#pragma unroll
        for (int j = 0; j < 4; j++)
            g_y[(size_t)(m0 + row) * E + lane + 32 * j] =
                rna_tf32((x[j] - mu) * rs * g4[j] + b4[j]);
    }
}

// ---------------- final mean over sequence ----------------------------------
__global__ void mean_kernel(float* __restrict__ out) {
    int b = blockIdx.x, e = threadIdx.x;
    const float* p = g_t + (size_t)b * NSEQ * E + e;
    float s = 0.f;
#pragma unroll 8
    for (int n = 0; n < NSEQ; n++) s += p[(size_t)n * E];
    out[b * E + e] = s * (1.0f / NSEQ);
}

// ---------------- launch -----------------------------------------------------
extern "C" void kernel_launch(void* const* d_in, const int* in_sizes, int n_in,
                              void* d_out, int out_size) {
    const float* x     = (const float*)d_in[0];
    const float* q_w   = (const float*)d_in[1];
    const float* k_w   = (const float*)d_in[2];
    const float* v_w   = (const float*)d_in[3];
    const float* o_w   = (const float*)d_in[4];
    const float* o_b   = (const float*)d_in[5];
    const float* ln1_g = (const float*)d_in[6];
    const float* ln1_b = (const float*)d_in[7];
    const float* ff_w1 = (const float*)d_in[8];
    const float* ff_b1 = (const float*)d_in[9];
    const float* ff_w2 = (const float*)d_in[10];
    const float* ff_b2 = (const float*)d_in[11];
    const float* ln2_g = (const float*)d_in[12];
    const float* ln2_b = (const float*)d_in[13];
    float* out = (float*)d_out;

    float *pt, *py, *pqkv, *pff, *pwt;
    cudaGetSymbolAddress((void**)&pt,   g_t);
    cudaGetSymbolAddress((void**)&py,   g_y);
    cudaGetSymbolAddress((void**)&pqkv, g_qkv);
    cudaGetSymbolAddress((void**)&pff,  g_ff);
    cudaGetSymbolAddress((void**)&pwt,  g_wt);

    cudaFuncSetAttribute(mma_gemm, cudaFuncAttributeMaxDynamicSharedMemorySize, SMEM_BYTES);
    cudaFuncSetAttribute(oproj_kernel, cudaFuncAttributeMaxDynamicSharedMemorySize, OP_SMEM);

    // prepass: ONE fused weight-convert launch, input transpose, entry LN
    wt_cvt_all<<<dim3(192, NLAYERS), dim3(32, 8)>>>(q_w, k_w, v_w, o_w, ff_w1, ff_w2);
    transpose_kernel<<<dim3(NSEQ / 32, E / 32, BATCH), dim3(32, 8)>>>(x);
    ln_kernel<<<MROWS, E>>>(ln1_g, ln1_b);

    for (int l = 0; l < NLAYERS; l++) {
        const float* wl = pwt + (size_t)l * WT_LAYER;
        // fused QKV GEMM (N=384)
        mma_gemm<<<dim3(QKV_N / GBN, MROWS / GBM), 256, SMEM_BYTES>>>(
            py, wl, nullptr, pqkv, nullptr, nullptr, nullptr, E, QKV_N, 0);
        // fused softmax_k + ctx
        ctx_kernel<<<BATCH * NHEADS, 256>>>();
        // fused attn prologue + o-proj + residual + LN2 -> y
        oproj_kernel<<<MROWS / GBM, 256, OP_SMEM>>>(wl + 49152, o_b + l * E,
                                                    ln2_g + l * E, ln2_b + l * E);
        // FF1 + gelu (tf32-rounded)
        mma_gemm<<<dim3(DFF / GBN, MROWS / GBM), 256, SMEM_BYTES>>>(
            py, wl + 65536, ff_b1 + l * DFF, pff, nullptr, nullptr, nullptr, E, DFF, 1 | 4);
        // FF2 + residual (+ next-layer LN1 -> y)
        if (l < NLAYERS - 1) {
            mma_gemm<<<dim3(1, MROWS / GBM), 256, SMEM_BYTES>>>(
                pff, wl + 131072, ff_b2 + l * E, pt,
                ln1_g + (l + 1) * E, ln1_b + (l + 1) * E, py, DFF, E, 2 | 8);
        } else {
            mma_gemm<<<dim3(1, MROWS / GBM), 256, SMEM_BYTES>>>(
                pff, wl + 131072, ff_b2 + l * E, pt,
                nullptr, nullptr, nullptr, DFF, E, 2);
        }
    }

    mean_kernel<<<BATCH, E>>>(out);
}

// round 7
// speedup vs baseline: 1.8684x; 1.3023x over previous
#include <cuda_runtime.h>
#include <cuda_fp16.h>
#include <math.h>
#include <stdint.h>

#define BATCH 64
#define E 128
#define NSEQ 1024
#define NHEADS 8
#define DH 16
#define DFF 512
#define MROWS (BATCH * NSEQ)   // 65536
#define NLAYERS 4
#define LN_EPS 1e-5f
#define QKV_N 384

// ---------------- scratch (static device globals; allocation-free) ----------
__device__ float  g_t[MROWS * E];          // residual stream fp32
__device__ __half g_y[MROWS * E];          // layernorm output (fp16)
__device__ float  g_qkv[MROWS * QKV_N];    // fused q|k|v fp32, row stride 384
__device__ float  g_ctx[BATCH * NHEADS * DH * DH];
__device__ __half g_ff[MROWS * DFF];       // gelu out (fp16)
// transposed fp16 weights per layer: qkv^T(49152), o^T(16384), ff1^T(65536), ff2^T(65536)
#define WT_LAYER 196608
__device__ __half g_wt[NLAYERS * WT_LAYER];

__device__ __forceinline__ float gelu_f(float x) {
    float x3 = x * x * x;
    return 0.5f * x * (1.0f + tanhf(0.7978845608028654f * (x + 0.044715f * x3)));
}

#define LDSM4(d0, d1, d2, d3, addr) \
    asm volatile("ldmatrix.sync.aligned.m8n8.x4.shared.b16 {%0,%1,%2,%3}, [%4];" \
                 : "=r"(d0), "=r"(d1), "=r"(d2), "=r"(d3) : "r"(addr))

#define MMA_F16(c, a, b) \
    asm volatile("mma.sync.aligned.m16n8k16.row.col.f32.f16.f16.f32 " \
                 "{%0,%1,%2,%3},{%4,%5,%6,%7},{%8,%9},{%0,%1,%2,%3};" \
                 : "+f"((c)[0]), "+f"((c)[1]), "+f"((c)[2]), "+f"((c)[3]) \
                 : "r"((a)[0]), "r"((a)[1]), "r"((a)[2]), "r"((a)[3]), \
                   "r"((b)[0]), "r"((b)[1]))

__device__ __forceinline__ void cp_async16(uint32_t dst, const void* src) {
    asm volatile("cp.async.cg.shared.global [%0], [%1], 16;" :: "r"(dst), "l"(src));
}
#define CP_COMMIT() asm volatile("cp.async.commit_group;")
#define CP_WAIT0()  asm volatile("cp.async.wait_group 0;")
#define CP_WAIT1()  asm volatile("cp.async.wait_group 1;")

// ---------------- transpose x:(B,E,N) -> t:(B,N,E) --------------------------
__global__ void transpose_kernel(const float* __restrict__ x) {
    __shared__ float tile[32][33];
    int b  = blockIdx.z;
    int n0 = blockIdx.x * 32;
    int e0 = blockIdx.y * 32;
    int tx = threadIdx.x, ty = threadIdx.y;   // (32,8)
#pragma unroll
    for (int i = 0; i < 32; i += 8)
        tile[ty + i][tx] = x[(size_t)b * E * NSEQ + (size_t)(e0 + ty + i) * NSEQ + n0 + tx];
    __syncthreads();
#pragma unroll
    for (int i = 0; i < 32; i += 8)
        g_t[(size_t)b * NSEQ * E + (size_t)(n0 + ty + i) * E + e0 + tx] = tile[tx][ty + i];
}

// ---------------- fused weight convert (ALL layers, one launch), fp16 -------
__global__ void wt_cvt_all(const float* __restrict__ q_w, const float* __restrict__ k_w,
                           const float* __restrict__ v_w, const float* __restrict__ o_w,
                           const float* __restrict__ ff_w1, const float* __restrict__ ff_w2) {
    __shared__ float tile[32][33];
    int l  = blockIdx.y;
    int id = blockIdx.x;
    __half* wl = g_wt + (size_t)l * WT_LAYER;

    const float* src;
    __half* dst;
    int K, N, tn, tk;
    if (id < 64) {
        int m = id >> 4;
        const float* srcs[4] = { q_w, k_w, v_w, o_w };
        src = srcs[m] + (size_t)l * E * E;
        dst = wl + m * 16384;
        K = E; N = E;
        int t = id & 15; tn = t & 3; tk = t >> 2;
    } else if (id < 128) {
        src = ff_w1 + (size_t)l * E * DFF;
        dst = wl + 65536;
        K = E; N = DFF;
        int t = id - 64; tn = t & 15; tk = t >> 4;
    } else {
        src = ff_w2 + (size_t)l * DFF * E;
        dst = wl + 131072;
        K = DFF; N = E;
        int t = id - 128; tn = t & 3; tk = t >> 2;
    }
    int n0 = tn * 32, k0 = tk * 32;
    int tx = threadIdx.x, ty = threadIdx.y;   // (32,8)
#pragma unroll
    for (int i = 0; i < 32; i += 8)
        tile[ty + i][tx] = src[(size_t)(k0 + ty + i) * N + n0 + tx];
    __syncthreads();
#pragma unroll
    for (int i = 0; i < 32; i += 8)
        dst[(size_t)(n0 + ty + i) * K + k0 + tx] = __float2half_rn(tile[tx][ty + i]);
}

// ---------------- standalone layernorm (layer-0 entry only), fp16 out -------
__global__ void ln_kernel(const float* __restrict__ gamma, const float* __restrict__ beta) {
    int m = blockIdx.x;
    int e = threadIdx.x;
    float v = g_t[(size_t)m * E + e];
    __shared__ float red[4];
    float s = v;
#pragma unroll
    for (int o = 16; o > 0; o >>= 1) s += __shfl_down_sync(0xffffffffu, s, o);
    if ((e & 31) == 0) red[e >> 5] = s;
    __syncthreads();
    float mu = (red[0] + red[1] + red[2] + red[3]) * (1.0f / E);
    __syncthreads();
    float d = v - mu;
    float s2 = d * d;
#pragma unroll
    for (int o = 16; o > 0; o >>= 1) s2 += __shfl_down_sync(0xffffffffu, s2, o);
    if ((e & 31) == 0) red[e >> 5] = s2;
    __syncthreads();
    float var = (red[0] + red[1] + red[2] + red[3]) * (1.0f / E);
    g_y[(size_t)m * E + e] = __float2half_rn(d * rsqrtf(var + LN_EPS) * gamma[e] + beta[e]);
}

// ---------------- generic FP16 GEMM (fp32 accum), pipelined -----------------
// C = op(A[M,K] @ Wt[N,K]^T + bias). Tiles: 128x128x(64 halfs).
// flags: 1=gelu, 2=residual add (C float), 8=fused LN -> Y (N=128, grid.x=1),
//        16 = C is half (direct half store)
#define GBM 128
#define GBN 128
#define NSTAGE 3
#define STAGE_BYTES 16384          // 128 rows * 128 bytes (64 halfs)
#define BSMEM_OFF (NSTAGE * STAGE_BYTES)
#define SMEM_BYTES (2 * NSTAGE * STAGE_BYTES)   // 98304

__global__ __launch_bounds__(256, 2) void mma_gemm(
    const __half* __restrict__ A, const __half* __restrict__ Wt,
    const float* __restrict__ bias, void* __restrict__ Cv,
    const float* __restrict__ gamma, const float* __restrict__ beta,
    __half* __restrict__ Y,
    int K, int N, int flags)
{
    extern __shared__ float sm[];
    uint32_t smem_u = (uint32_t)__cvta_generic_to_shared(sm);

    int tid  = threadIdx.x;
    int lane = tid & 31;
    int wid  = tid >> 5;
    int warp_m = wid & 1;
    int warp_n = wid >> 1;
    int bm0 = blockIdx.y * GBM;
    int bn0 = blockIdx.x * GBN;

    int r0 = tid >> 3;               // row (0..31), 4 iterations cover 128
    int c8 = tid & 7;                // 16B chunk in 128B row
    uint32_t cxor = (uint32_t)((c8 ^ (r0 & 7)) << 4);

    int sub = lane >> 3;
    int l7  = lane & 7;
    int selA = sub >> 1;
    int rowAoff = ((sub & 1) << 3) + l7;
    int selB = sub & 1;
    int rowBoff = ((sub >> 1) << 3) + l7;

    float acc[4][4][4];
#pragma unroll
    for (int i = 0; i < 4; i++)
#pragma unroll
        for (int j = 0; j < 4; j++)
#pragma unroll
            for (int k = 0; k < 4; k++) acc[i][j][k] = 0.f;

    int nIter = K >> 6;              // K halfs per tile = 64

    auto load_tile = [&](int s, int k0) {
#pragma unroll
        for (int i = 0; i < 4; i++) {
            int r = r0 + i * 32;
            uint32_t doff = (uint32_t)(r << 7) + cxor;
            cp_async16(smem_u + s * STAGE_BYTES + doff, A + (size_t)(bm0 + r) * K + k0 + c8 * 8);
            cp_async16(smem_u + BSMEM_OFF + s * STAGE_BYTES + doff, Wt + (size_t)(bn0 + r) * K + k0 + c8 * 8);
        }
    };

    load_tile(0, 0);  CP_COMMIT();
    if (nIter > 1) { load_tile(1, 64); CP_COMMIT(); }

    for (int it = 0; it < nIter; it++) {
        if (it < nIter - 1) CP_WAIT1(); else CP_WAIT0();
        __syncthreads();

        int s = it % NSTAGE;
        uint32_t baseA = smem_u + s * STAGE_BYTES;
        uint32_t baseB = smem_u + BSMEM_OFF + s * STAGE_BYTES;

#pragma unroll
        for (int ks = 0; ks < 4; ks++) {        // 4 x k16 = 64 halfs
            int cb = ks * 2;
            uint32_t a[4][4], b[4][2];
#pragma unroll
            for (int mt = 0; mt < 4; mt++) {
                int row = warp_m * 64 + mt * 16 + rowAoff;
                uint32_t addr = baseA + (row << 7) + (uint32_t)(((cb + selA) ^ (row & 7)) << 4);
                LDSM4(a[mt][0], a[mt][1], a[mt][2], a[mt][3], addr);
            }
#pragma unroll
            for (int bt = 0; bt < 2; bt++) {
                int row = warp_n * 32 + bt * 16 + rowBoff;
                uint32_t addr = baseB + (row << 7) + (uint32_t)(((cb + selB) ^ (row & 7)) << 4);
                LDSM4(b[2 * bt][0], b[2 * bt][1], b[2 * bt + 1][0], b[2 * bt + 1][1], addr);
            }
#pragma unroll
            for (int mt = 0; mt < 4; mt++)
#pragma unroll
                for (int nt = 0; nt < 4; nt++)
                    MMA_F16(acc[mt][nt], a[mt], b[nt]);
        }

        if (it + 2 < nIter) { load_tile((it + 2) % NSTAGE, (it + 2) * 64); CP_COMMIT(); }
    }

    int g  = lane >> 2;
    int t4 = lane & 3;
    bool do_ln = (flags & 8) != 0;
    if (do_ln) __syncthreads();

    float* Cf = (float*)Cv;
    __half* Ch = (__half*)Cv;

#pragma unroll
    for (int mt = 0; mt < 4; mt++) {
        int rowl0 = warp_m * 64 + mt * 16 + g;
#pragma unroll
        for (int nt = 0; nt < 4; nt++) {
            int coll = warp_n * 32 + nt * 8 + t4 * 2;
            int col  = bn0 + coll;
            float v[4] = { acc[mt][nt][0], acc[mt][nt][1], acc[mt][nt][2], acc[mt][nt][3] };
            if (bias) {
                float b0 = bias[col], b1 = bias[col + 1];
                v[0] += b0; v[1] += b1; v[2] += b0; v[3] += b1;
            }
            if (flags & 1) {
#pragma unroll
                for (int z = 0; z < 4; z++) v[z] = gelu_f(v[z]);
            }
#pragma unroll
            for (int half2i = 0; half2i < 2; half2i++) {
                int rowl = rowl0 + half2i * 8;
                float f0 = v[half2i * 2], f1 = v[half2i * 2 + 1];
                if (flags & 16) {
                    *(__half2*)(Ch + (size_t)(bm0 + rowl) * N + col) =
                        __halves2half2(__float2half_rn(f0), __float2half_rn(f1));
                } else {
                    float2* p = (float2*)(Cf + (size_t)(bm0 + rowl) * N + col);
                    if (flags & 2) {
                        float2 o = *p;
                        f0 += o.x; f1 += o.y;
                    }
                    *p = make_float2(f0, f1);
                }
                if (do_ln) {
                    sm[rowl * 132 + coll]     = f0;
                    sm[rowl * 132 + coll + 1] = f1;
                }
            }
        }
    }

    if (do_ln) {
        __syncthreads();
        float g4[4], b4[4];
#pragma unroll
        for (int j = 0; j < 4; j++) {
            g4[j] = gamma[lane + 32 * j];
            b4[j] = beta[lane + 32 * j];
        }
        for (int r = 0; r < 16; r++) {
            int row = wid * 16 + r;
            float x[4];
#pragma unroll
            for (int j = 0; j < 4; j++) x[j] = sm[row * 132 + lane + 32 * j];
            float s = x[0] + x[1] + x[2] + x[3];
#pragma unroll
            for (int o = 16; o > 0; o >>= 1) s += __shfl_xor_sync(0xffffffffu, s, o);
            float mu = s * (1.0f / E);
            float s2 = 0.f;
#pragma unroll
            for (int j = 0; j < 4; j++) { float d = x[j] - mu; s2 += d * d; }
#pragma unroll
            for (int o = 16; o > 0; o >>= 1) s2 += __shfl_xor_sync(0xffffffffu, s2, o);
            float rs = rsqrtf(s2 * (1.0f / E) + LN_EPS);
#pragma unroll
            for (int j = 0; j < 4; j++)
                Y[(size_t)(bm0 + row) * E + lane + 32 * j] =
                    __float2half_rn((x[j] - mu) * rs * g4[j] + b4[j]);
        }
    }
}

// ---------------- fused softmax_k + ctx per (b,h) ---------------------------
__global__ void ctx_kernel() {
    int bh = blockIdx.x;
    int b = bh >> 3, h = bh & 7;
    const float* kbase = g_qkv + (size_t)b * NSEQ * QKV_N + E + h * DH;
    const float* vbase = kbase + E;
    int tid = threadIdx.x;

    __shared__ float smax[16][17];
    __shared__ float mx[16];
    int d0 = tid & 15, i0 = tid >> 4;
    float m = -1e30f;
    for (int i = 0; i < 64; i++) {
        int n = i0 + i * 16;
        m = fmaxf(m, kbase[(size_t)n * QKV_N + d0]);
    }
    smax[d0][i0] = m;
    __syncthreads();
    if (tid < 16) {
        float t = smax[tid][0];
#pragma unroll
        for (int i = 1; i < 16; i++) t = fmaxf(t, smax[tid][i]);
        mx[tid] = t;
    }
    __syncthreads();

    __shared__ float ks[128][17];
    __shared__ float vs[128][17];
    int d = tid >> 4, e = tid & 15;
    float acc = 0.f, ssum = 0.f;
    for (int n0 = 0; n0 < NSEQ; n0 += 128) {
        __syncthreads();
        for (int l = tid; l < 128 * 16; l += 256) {
            int nl = l >> 4, c = l & 15;
            ks[nl][c] = expf(kbase[(size_t)(n0 + nl) * QKV_N + c] - mx[c]);
            vs[nl][c] = vbase[(size_t)(n0 + nl) * QKV_N + c];
        }
        __syncthreads();
#pragma unroll 8
        for (int nl = 0; nl < 128; nl++) {
            float kk = ks[nl][d];
            acc += kk * vs[nl][e];
            ssum += kk;
        }
    }
    g_ctx[bh * 256 + d * 16 + e] = acc / ssum;
}

// ---------------- o-proj: fused attn-A prologue + fp16 GEMM + resid + LN ----
// smem bytes: [A 2x16KB][B 2x16KB][ctx 8KB] = 73728; LN staging reuses front.
#define OP_B_OFF 32768
#define OP_CTX_OFF 65536
#define OP_SMEM 73728

__global__ __launch_bounds__(256, 2) void oproj_kernel(
    const __half* __restrict__ Wt, const float* __restrict__ bias,
    const float* __restrict__ gamma, const float* __restrict__ beta)
{
    extern __shared__ float sm[];
    uint32_t smem_u = (uint32_t)__cvta_generic_to_shared(sm);

    int tid  = threadIdx.x;
    int lane = tid & 31;
    int wid  = tid >> 5;
    int warp_m = wid & 1;
    int warp_n = wid >> 1;
    int m0 = blockIdx.x * GBM;
    int b  = m0 >> 10;

    int r0 = tid >> 3;
    int c8 = tid & 7;
    uint32_t cxor = (uint32_t)((c8 ^ (r0 & 7)) << 4);

    // prefetch B tile 0 (k halfs 0..63)
#pragma unroll
    for (int i = 0; i < 4; i++) {
        int r = r0 + i * 32;
        cp_async16(smem_u + OP_B_OFF + (r << 7) + cxor, Wt + (size_t)r * E + c8 * 8);
    }
    CP_COMMIT();

    float* ctxs = (float*)((char*)sm + OP_CTX_OFF);
    for (int i = tid; i < 2048; i += 256) ctxs[i] = g_ctx[b * 2048 + i];
    __syncthreads();

    // attention prologue: A[128][128] = f16(softmax_q(q) @ ctx * 0.25)
    {
        int row = tid >> 1, half = tid & 1;
        const float* qrow = g_qkv + (size_t)(m0 + row) * QKV_N;
#pragma unroll
        for (int hh = 0; hh < 4; hh++) {
            int h = half * 4 + hh;
            float qv[16];
            const float4* q4 = (const float4*)(qrow + h * 16);
#pragma unroll
            for (int j = 0; j < 4; j++) {
                float4 t = q4[j];
                qv[4 * j] = t.x; qv[4 * j + 1] = t.y; qv[4 * j + 2] = t.z; qv[4 * j + 3] = t.w;
            }
            float mxv = -1e30f;
#pragma unroll
            for (int d = 0; d < 16; d++) mxv = fmaxf(mxv, qv[d]);
            float s = 0.f;
#pragma unroll
            for (int d = 0; d < 16; d++) { qv[d] = expf(qv[d] - mxv); s += qv[d]; }
            float r = 0.25f / s;
            const float* cb = ctxs + h * 256;
#pragma unroll
            for (int e2 = 0; e2 < 16; e2 += 2) {
                float a0 = 0.f, a1 = 0.f;
#pragma unroll
                for (int d = 0; d < 16; d++) {
                    float qq = qv[d];
                    a0 += qq * cb[d * 16 + e2];
                    a1 += qq * cb[d * 16 + e2 + 1];
                }
                int col = h * 16 + e2;
                int t = col >> 6, chunk = (col >> 3) & 7, hi = col & 7;
                uint32_t off = (uint32_t)(t * 16384 + (row << 7) + (((chunk) ^ (row & 7)) << 4) + hi * 2);
                *(__half2*)((char*)sm + off) =
                    __halves2half2(__float2half_rn(a0 * r), __float2half_rn(a1 * r));
            }
        }
    }

    int sub = lane >> 3;
    int l7  = lane & 7;
    int selA = sub >> 1;
    int rowAoff = ((sub & 1) << 3) + l7;
    int selB = sub & 1;
    int rowBoff = ((sub >> 1) << 3) + l7;

    float acc[4][4][4];
#pragma unroll
    for (int i = 0; i < 4; i++)
#pragma unroll
        for (int j = 0; j < 4; j++)
#pragma unroll
            for (int k = 0; k < 4; k++) acc[i][j][k] = 0.f;

    for (int it = 0; it < 2; it++) {
        CP_WAIT0();
        __syncthreads();
        if (it == 0) {
#pragma unroll
            for (int i = 0; i < 4; i++) {
                int r = r0 + i * 32;
                cp_async16(smem_u + OP_B_OFF + 16384 + (r << 7) + cxor,
                           Wt + (size_t)r * E + 64 + c8 * 8);
            }
            CP_COMMIT();
        }
        uint32_t baseA = smem_u + it * 16384;
        uint32_t baseB = smem_u + OP_B_OFF + it * 16384;
#pragma unroll
        for (int ks = 0; ks < 4; ks++) {
            int cb = ks * 2;
            uint32_t a[4][4], bb[4][2];
#pragma unroll
            for (int mt = 0; mt < 4; mt++) {
                int row = warp_m * 64 + mt * 16 + rowAoff;
                uint32_t addr = baseA + (row << 7) + (uint32_t)(((cb + selA) ^ (row & 7)) << 4);
                LDSM4(a[mt][0], a[mt][1], a[mt][2], a[mt][3], addr);
            }
#pragma unroll
            for (int bt = 0; bt < 2; bt++) {
                int row = warp_n * 32 + bt * 16 + rowBoff;
                uint32_t addr = baseB + (row << 7) + (uint32_t)(((cb + selB) ^ (row & 7)) << 4);
                LDSM4(bb[2 * bt][0], bb[2 * bt][1], bb[2 * bt + 1][0], bb[2 * bt + 1][1], addr);
            }
#pragma unroll
            for (int mt = 0; mt < 4; mt++)
#pragma unroll
                for (int nt = 0; nt < 4; nt++)
                    MMA_F16(acc[mt][nt], a[mt], bb[nt]);
        }
    }

    int g  = lane >> 2;
    int t4 = lane & 3;
    __syncthreads();
#pragma unroll
    for (int mt = 0; mt < 4; mt++) {
        int rowl0 = warp_m * 64 + mt * 16 + g;
#pragma unroll
        for (int nt = 0; nt < 4; nt++) {
            int col = warp_n * 32 + nt * 8 + t4 * 2;
            float b0 = bias[col], b1 = bias[col + 1];
#pragma unroll
            for (int hf = 0; hf < 2; hf++) {
                int rowl = rowl0 + hf * 8;
                float2* p = (float2*)(g_t + (size_t)(m0 + rowl) * E + col);
                float2 o = *p;
                float f0 = acc[mt][nt][hf * 2]     + b0 + o.x;
                float f1 = acc[mt][nt][hf * 2 + 1] + b1 + o.y;
                *p = make_float2(f0, f1);
                sm[rowl * 132 + col]     = f0;
                sm[rowl * 132 + col + 1] = f1;
            }
        }
    }
    __syncthreads();
    float g4[4], b4[4];
#pragma unroll
    for (int j = 0; j < 4; j++) { g4[j] = gamma[lane + 32 * j]; b4[j] = beta[lane + 32 * j]; }
    for (int rr = 0; rr < 16; rr++) {
        int row = wid * 16 + rr;
        float x[4];
#pragma unroll
        for (int j = 0; j < 4; j++) x[j] = sm[row * 132 + lane + 32 * j];
        float s = x[0] + x[1] + x[2] + x[3];
#pragma unroll
        for (int o = 16; o > 0; o >>= 1) s += __shfl_xor_sync(0xffffffffu, s, o);
        float mu = s * (1.0f / E);
        float s2 = 0.f;
#pragma unroll
        for (int j = 0; j < 4; j++) { float d = x[j] - mu; s2 += d * d; }
#pragma unroll
        for (int o = 16; o > 0; o >>= 1) s2 += __shfl_xor_sync(0xffffffffu, s2, o);
        float rs = rsqrtf(s2 * (1.0f / E) + LN_EPS);
#pragma unroll
        for (int j = 0; j < 4; j++)
            g_y[(size_t)(m0 + row) * E + lane + 32 * j] =
                __float2half_rn((x[j] - mu) * rs * g4[j] + b4[j]);
    }
}

// ---------------- final mean over sequence ----------------------------------
__global__ void mean_kernel(float* __restrict__ out) {
    int b = blockIdx.x, e = threadIdx.x;
    const float* p = g_t + (size_t)b * NSEQ * E + e;
    float s = 0.f;
#pragma unroll 8
    for (int n = 0; n < NSEQ; n++) s += p[(size_t)n * E];
    out[b * E + e] = s * (1.0f / NSEQ);
}

// ---------------- launch -----------------------------------------------------
extern "C" void kernel_launch(void* const* d_in, const int* in_sizes, int n_in,
                              void* d_out, int out_size) {
    const float* x     = (const float*)d_in[0];
    const float* q_w   = (const float*)d_in[1];
    const float* k_w   = (const float*)d_in[2];
    const float* v_w   = (const float*)d_in[3];
    const float* o_w   = (const float*)d_in[4];
    const float* o_b   = (const float*)d_in[5];
    const float* ln1_g = (const float*)d_in[6];
    const float* ln1_b = (const float*)d_in[7];
    const float* ff_w1 = (const float*)d_in[8];
    const float* ff_b1 = (const float*)d_in[9];
    const float* ff_w2 = (const float*)d_in[10];
    const float* ff_b2 = (const float*)d_in[11];
    const float* ln2_g = (const float*)d_in[12];
    const float* ln2_b = (const float*)d_in[13];
    float* out = (float*)d_out;

    float *pt, *pqkv;
    __half *py, *pff, *pwt;
    cudaGetSymbolAddress((void**)&pt,   g_t);
    cudaGetSymbolAddress((void**)&py,   g_y);
    cudaGetSymbolAddress((void**)&pqkv, g_qkv);
    cudaGetSymbolAddress((void**)&pff,  g_ff);
    cudaGetSymbolAddress((void**)&pwt,  g_wt);

    cudaFuncSetAttribute(mma_gemm, cudaFuncAttributeMaxDynamicSharedMemorySize, SMEM_BYTES);
    cudaFuncSetAttribute(oproj_kernel, cudaFuncAttributeMaxDynamicSharedMemorySize, OP_SMEM);

    wt_cvt_all<<<dim3(192, NLAYERS), dim3(32, 8)>>>(q_w, k_w, v_w, o_w, ff_w1, ff_w2);
    transpose_kernel<<<dim3(NSEQ / 32, E / 32, BATCH), dim3(32, 8)>>>(x);
    ln_kernel<<<MROWS, E>>>(ln1_g, ln1_b);

    for (int l = 0; l < NLAYERS; l++) {
        const __half* wl = pwt + (size_t)l * WT_LAYER;
        // fused QKV GEMM (N=384), fp32 out
        mma_gemm<<<dim3(QKV_N / GBN, MROWS / GBM), 256, SMEM_BYTES>>>(
            py, wl, nullptr, pqkv, nullptr, nullptr, nullptr, E, QKV_N, 0);
        // fused softmax_k + ctx
        ctx_kernel<<<BATCH * NHEADS, 256>>>();
        // fused attn prologue + o-proj + residual + LN2 -> y
        oproj_kernel<<<MROWS / GBM, 256, OP_SMEM>>>(wl + 49152, o_b + l * E,
                                                    ln2_g + l * E, ln2_b + l * E);
        // FF1 + gelu -> half g_ff
        mma_gemm<<<dim3(DFF / GBN, MROWS / GBM), 256, SMEM_BYTES>>>(
            py, wl + 65536, ff_b1 + l * DFF, pff, nullptr, nullptr, nullptr, E, DFF, 1 | 16);
        // FF2 + residual (+ next-layer LN1 -> y)
        if (l < NLAYERS - 1) {
            mma_gemm<<<dim3(1, MROWS / GBM), 256, SMEM_BYTES>>>(
                pff, wl + 131072, ff_b2 + l * E, pt,
                ln1_g + (l + 1) * E, ln1_b + (l + 1) * E, py, DFF, E, 2 | 8);
        } else {
            mma_gemm<<<dim3(1, MROWS / GBM), 256, SMEM_BYTES>>>(
                pff, wl + 131072, ff_b2 + l * E, pt,
                nullptr, nullptr, nullptr, DFF, E, 2);
        }
    }

    mean_kernel<<<BATCH, E>>>(out);
}

// round 10
// speedup vs baseline: 1.9789x; 1.0591x over previous
#include <cuda_runtime.h>
#include <cuda_fp16.h>
#include <math.h>
#include <stdint.h>

#define BATCH 64
#define E 128
#define NSEQ 1024
#define NHEADS 8
#define DH 16
#define DFF 512
#define MROWS (BATCH * NSEQ)   // 65536
#define NLAYERS 4
#define LN_EPS 1e-5f
#define QKV_N 384

// ---------------- scratch (static device globals; allocation-free) ----------
__device__ float  g_t[MROWS * E];          // residual stream fp32
__device__ __half g_y[MROWS * E];          // layernorm output (fp16)
__device__ __half g_qkv[MROWS * QKV_N];    // fused q|k|v fp16, row stride 384
__device__ float  g_ctx[BATCH * NHEADS * DH * DH];
__device__ __half g_ff[MROWS * DFF];       // gelu out (fp16)
__device__ float  g_part[512 * E];         // mean partials
#define WT_LAYER 196608
__device__ __half g_wt[NLAYERS * WT_LAYER];

__device__ __forceinline__ float gelu_f(float x) {
    float x3 = x * x * x;
    return 0.5f * x * (1.0f + tanhf(0.7978845608028654f * (x + 0.044715f * x3)));
}

#define LDSM4(d0, d1, d2, d3, addr) \
    asm volatile("ldmatrix.sync.aligned.m8n8.x4.shared.b16 {%0,%1,%2,%3}, [%4];" \
                 : "=r"(d0), "=r"(d1), "=r"(d2), "=r"(d3) : "r"(addr))

#define MMA_F16(c, a, b) \
    asm volatile("mma.sync.aligned.m16n8k16.row.col.f32.f16.f16.f32 " \
                 "{%0,%1,%2,%3},{%4,%5,%6,%7},{%8,%9},{%0,%1,%2,%3};" \
                 : "+f"((c)[0]), "+f"((c)[1]), "+f"((c)[2]), "+f"((c)[3]) \
                 : "r"((a)[0]), "r"((a)[1]), "r"((a)[2]), "r"((a)[3]), \
                   "r"((b)[0]), "r"((b)[1]))

__device__ __forceinline__ void cp_async16(uint32_t dst, const void* src) {
    asm volatile("cp.async.cg.shared.global [%0], [%1], 16;" :: "r"(dst), "l"(src));
}
#define CP_COMMIT() asm volatile("cp.async.commit_group;")
#define CP_WAIT0()  asm volatile("cp.async.wait_group 0;")
#define CP_WAIT1()  asm volatile("cp.async.wait_group 1;")

// ---------------- transpose x:(B,E,N) -> t:(B,N,E) --------------------------
__global__ void transpose_kernel(const float* __restrict__ x) {
    __shared__ float tile[32][33];
    int b  = blockIdx.z;
    int n0 = blockIdx.x * 32;
    int e0 = blockIdx.y * 32;
    int tx = threadIdx.x, ty = threadIdx.y;   // (32,8)
#pragma unroll
    for (int i = 0; i < 32; i += 8)
        tile[ty + i][tx] = x[(size_t)b * E * NSEQ + (size_t)(e0 + ty + i) * NSEQ + n0 + tx];
    __syncthreads();
#pragma unroll
    for (int i = 0; i < 32; i += 8)
        g_t[(size_t)b * NSEQ * E + (size_t)(n0 + ty + i) * E + e0 + tx] = tile[tx][ty + i];
}

// ---------------- fused weight convert (ALL layers, one launch), fp16 -------
__global__ void wt_cvt_all(const float* __restrict__ q_w, const float* __restrict__ k_w,
                           const float* __restrict__ v_w, const float* __restrict__ o_w,
                           const float* __restrict__ ff_w1, const float* __restrict__ ff_w2) {
    __shared__ float tile[32][33];
    int l  = blockIdx.y;
    int id = blockIdx.x;
    __half* wl = g_wt + (size_t)l * WT_LAYER;

    const float* src;
    __half* dst;
    int K, N, tn, tk;
    if (id < 64) {
        int m = id >> 4;
        const float* srcs[4] = { q_w, k_w, v_w, o_w };
        src = srcs[m] + (size_t)l * E * E;
        dst = wl + m * 16384;
        K = E; N = E;
        int t = id & 15; tn = t & 3; tk = t >> 2;
    } else if (id < 128) {
        src = ff_w1 + (size_t)l * E * DFF;
        dst = wl + 65536;
        K = E; N = DFF;
        int t = id - 64; tn = t & 15; tk = t >> 4;
    } else {
        src = ff_w2 + (size_t)l * DFF * E;
        dst = wl + 131072;
        K = DFF; N = E;
        int t = id - 128; tn = t & 3; tk = t >> 2;
    }
    int n0 = tn * 32, k0 = tk * 32;
    int tx = threadIdx.x, ty = threadIdx.y;   // (32,8)
#pragma unroll
    for (int i = 0; i < 32; i += 8)
        tile[ty + i][tx] = src[(size_t)(k0 + ty + i) * N + n0 + tx];
    __syncthreads();
#pragma unroll
    for (int i = 0; i < 32; i += 8)
        dst[(size_t)(n0 + ty + i) * K + k0 + tx] = __float2half_rn(tile[tx][ty + i]);
}

// ---------------- standalone layernorm (layer-0 entry only), fp16 out -------
__global__ void ln_kernel(const float* __restrict__ gamma, const float* __restrict__ beta) {
    int m = blockIdx.x;
    int e = threadIdx.x;
    float v = g_t[(size_t)m * E + e];
    __shared__ float red[4];
    float s = v;
#pragma unroll
    for (int o = 16; o > 0; o >>= 1) s += __shfl_down_sync(0xffffffffu, s, o);
    if ((e & 31) == 0) red[e >> 5] = s;
    __syncthreads();
    float mu = (red[0] + red[1] + red[2] + red[3]) * (1.0f / E);
    __syncthreads();
    float d = v - mu;
    float s2 = d * d;
#pragma unroll
    for (int o = 16; o > 0; o >>= 1) s2 += __shfl_down_sync(0xffffffffu, s2, o);
    if ((e & 31) == 0) red[e >> 5] = s2;
    __syncthreads();
    float var = (red[0] + red[1] + red[2] + red[3]) * (1.0f / E);
    g_y[(size_t)m * E + e] = __float2half_rn(d * rsqrtf(var + LN_EPS) * gamma[e] + beta[e]);
}

// ---------------- generic FP16 GEMM (fp32 accum), pipelined -----------------
// C = op(A[M,K] @ Wt[N,K]^T + bias). Tiles: 128x128x(64 halfs).
// flags: 1=gelu, 2=residual add (C float), 8=fused LN -> Y (N=128, grid.x=1),
//        16 = C is half (direct half store)
#define GBM 128
#define GBN 128
#define NSTAGE 3
#define STAGE_BYTES 16384          // 128 rows * 128 bytes (64 halfs)
#define BSMEM_OFF (NSTAGE * STAGE_BYTES)
#define SMEM_BYTES (2 * NSTAGE * STAGE_BYTES)   // 98304

__global__ __launch_bounds__(256, 2) void mma_gemm(
    const __half* __restrict__ A, const __half* __restrict__ Wt,
    const float* __restrict__ bias, void* __restrict__ Cv,
    const float* __restrict__ gamma, const float* __restrict__ beta,
    __half* __restrict__ Y,
    int K, int N, int flags)
{
    extern __shared__ float sm[];
    uint32_t smem_u = (uint32_t)__cvta_generic_to_shared(sm);

    int tid  = threadIdx.x;
    int lane = tid & 31;
    int wid  = tid >> 5;
    int warp_m = wid & 1;
    int warp_n = wid >> 1;
    int bm0 = blockIdx.y * GBM;
    int bn0 = blockIdx.x * GBN;

    int r0 = tid >> 3;               // row (0..31), 4 iterations cover 128
    int c8 = tid & 7;                // 16B chunk in 128B row
    uint32_t cxor = (uint32_t)((c8 ^ (r0 & 7)) << 4);

    int sub = lane >> 3;
    int l7  = lane & 7;
    int selA = sub >> 1;
    int rowAoff = ((sub & 1) << 3) + l7;
    int selB = sub & 1;
    int rowBoff = ((sub >> 1) << 3) + l7;

    float acc[4][4][4];
#pragma unroll
    for (int i = 0; i < 4; i++)
#pragma unroll
        for (int j = 0; j < 4; j++)
#pragma unroll
            for (int k = 0; k < 4; k++) acc[i][j][k] = 0.f;

    int nIter = K >> 6;              // K halfs per tile = 64

    auto load_tile = [&](int s, int k0) {
#pragma unroll
        for (int i = 0; i < 4; i++) {
            int r = r0 + i * 32;
            uint32_t doff = (uint32_t)(r << 7) + cxor;
            cp_async16(smem_u + s * STAGE_BYTES + doff, A + (size_t)(bm0 + r) * K + k0 + c8 * 8);
            cp_async16(smem_u + BSMEM_OFF + s * STAGE_BYTES + doff, Wt + (size_t)(bn0 + r) * K + k0 + c8 * 8);
        }
    };

    load_tile(0, 0);  CP_COMMIT();
    if (nIter > 1) { load_tile(1, 64); CP_COMMIT(); }

    for (int it = 0; it < nIter; it++) {
        if (it < nIter - 1) CP_WAIT1(); else CP_WAIT0();
        __syncthreads();

        int s = it % NSTAGE;
        uint32_t baseA = smem_u + s * STAGE_BYTES;
        uint32_t baseB = smem_u + BSMEM_OFF + s * STAGE_BYTES;

#pragma unroll
        for (int ks = 0; ks < 4; ks++) {        // 4 x k16 = 64 halfs
            int cb = ks * 2;
            uint32_t a[4][4], b[4][2];
#pragma unroll
            for (int mt = 0; mt < 4; mt++) {
                int row = warp_m * 64 + mt * 16 + rowAoff;
                uint32_t addr = baseA + (row << 7) + (uint32_t)(((cb + selA) ^ (row & 7)) << 4);
                LDSM4(a[mt][0], a[mt][1], a[mt][2], a[mt][3], addr);
            }
#pragma unroll
            for (int bt = 0; bt < 2; bt++) {
                int row = warp_n * 32 + bt * 16 + rowBoff;
                uint32_t addr = baseB + (row << 7) + (uint32_t)(((cb + selB) ^ (row & 7)) << 4);
                LDSM4(b[2 * bt][0], b[2 * bt][1], b[2 * bt + 1][0], b[2 * bt + 1][1], addr);
            }
#pragma unroll
            for (int mt = 0; mt < 4; mt++)
#pragma unroll
                for (int nt = 0; nt < 4; nt++)
                    MMA_F16(acc[mt][nt], a[mt], b[nt]);
        }

        if (it + 2 < nIter) { load_tile((it + 2) % NSTAGE, (it + 2) * 64); CP_COMMIT(); }
    }

    int g  = lane >> 2;
    int t4 = lane & 3;
    bool do_ln = (flags & 8) != 0;
    if (do_ln) __syncthreads();

    float* Cf = (float*)Cv;
    __half* Ch = (__half*)Cv;

#pragma unroll
    for (int mt = 0; mt < 4; mt++) {
        int rowl0 = warp_m * 64 + mt * 16 + g;
#pragma unroll
        for (int nt = 0; nt < 4; nt++) {
            int coll = warp_n * 32 + nt * 8 + t4 * 2;
            int col  = bn0 + coll;
            float v[4] = { acc[mt][nt][0], acc[mt][nt][1], acc[mt][nt][2], acc[mt][nt][3] };
            if (bias) {
                float b0 = bias[col], b1 = bias[col + 1];
                v[0] += b0; v[1] += b1; v[2] += b0; v[3] += b1;
            }
            if (flags & 1) {
#pragma unroll
                for (int z = 0; z < 4; z++) v[z] = gelu_f(v[z]);
            }
#pragma unroll
            for (int half2i = 0; half2i < 2; half2i++) {
                int rowl = rowl0 + half2i * 8;
                float f0 = v[half2i * 2], f1 = v[half2i * 2 + 1];
                if (flags & 16) {
                    *(__half2*)(Ch + (size_t)(bm0 + rowl) * N + col) =
                        __halves2half2(__float2half_rn(f0), __float2half_rn(f1));
                } else {
                    float2* p = (float2*)(Cf + (size_t)(bm0 + rowl) * N + col);
                    if (flags & 2) {
                        float2 o = *p;
                        f0 += o.x; f1 += o.y;
                    }
                    *p = make_float2(f0, f1);
                }
                if (do_ln) {
                    sm[rowl * 132 + coll]     = f0;
                    sm[rowl * 132 + coll + 1] = f1;
                }
            }
        }
    }

    if (do_ln) {
        __syncthreads();
        float g4[4], b4[4];
#pragma unroll
        for (int j = 0; j < 4; j++) {
            g4[j] = gamma[lane + 32 * j];
            b4[j] = beta[lane + 32 * j];
        }
        for (int r = 0; r < 16; r++) {
            int row = wid * 16 + r;
            float x[4];
#pragma unroll
            for (int j = 0; j < 4; j++) x[j] = sm[row * 132 + lane + 32 * j];
            float s = x[0] + x[1] + x[2] + x[3];
#pragma unroll
            for (int o = 16; o > 0; o >>= 1) s += __shfl_xor_sync(0xffffffffu, s, o);
            float mu = s * (1.0f / E);
            float s2 = 0.f;
#pragma unroll
            for (int j = 0; j < 4; j++) { float d = x[j] - mu; s2 += d * d; }
#pragma unroll
            for (int o = 16; o > 0; o >>= 1) s2 += __shfl_xor_sync(0xffffffffu, s2, o);
            float rs = rsqrtf(s2 * (1.0f / E) + LN_EPS);
#pragma unroll
            for (int j = 0; j < 4; j++)
                Y[(size_t)(bm0 + row) * E + lane + 32 * j] =
                    __float2half_rn((x[j] - mu) * rs * g4[j] + b4[j]);
        }
    }
}

// ---------------- fused softmax_k + ctx per (b,h), fp16 inputs --------------
__global__ void ctx_kernel() {
    int bh = blockIdx.x;
    int b = bh >> 3, h = bh & 7;
    const __half* kbase = g_qkv + (size_t)b * NSEQ * QKV_N + E + h * DH;
    const __half* vbase = kbase + E;
    int tid = threadIdx.x;

    __shared__ float smax[16][17];
    __shared__ float mx[16];
    int d0 = tid & 15, i0 = tid >> 4;
    float m = -1e30f;
    for (int i = 0; i < 64; i++) {
        int n = i0 + i * 16;
        m = fmaxf(m, __half2float(kbase[(size_t)n * QKV_N + d0]));
    }
    smax[d0][i0] = m;
    __syncthreads();
    if (tid < 16) {
        float t = smax[tid][0];
#pragma unroll
        for (int i = 1; i < 16; i++) t = fmaxf(t, smax[tid][i]);
        mx[tid] = t;
    }
    __syncthreads();

    __shared__ float ks[128][17];
    __shared__ float vs[128][17];
    int d = tid >> 4, e = tid & 15;
    float acc = 0.f, ssum = 0.f;
    for (int n0 = 0; n0 < NSEQ; n0 += 128) {
        __syncthreads();
        // half2 loads: l in [0,1024): nl = l>>3, c2 = l&7 (pairs of columns)
        for (int l = tid; l < 128 * 8; l += 256) {
            int nl = l >> 3, c2 = l & 7;
            __half2 k2 = *(const __half2*)(kbase + (size_t)(n0 + nl) * QKV_N + c2 * 2);
            __half2 v2 = *(const __half2*)(vbase + (size_t)(n0 + nl) * QKV_N + c2 * 2);
            float2 kf = __half22float2(k2);
            float2 vf = __half22float2(v2);
            ks[nl][c2 * 2]     = expf(kf.x - mx[c2 * 2]);
            ks[nl][c2 * 2 + 1] = expf(kf.y - mx[c2 * 2 + 1]);
            vs[nl][c2 * 2]     = vf.x;
            vs[nl][c2 * 2 + 1] = vf.y;
        }
        __syncthreads();
#pragma unroll 8
        for (int nl = 0; nl < 128; nl++) {
            float kk = ks[nl][d];
            acc += kk * vs[nl][e];
            ssum += kk;
        }
    }
    g_ctx[bh * 256 + d * 16 + e] = acc / ssum;
}

// ---------------- o-proj: fused attn-A prologue + fp16 GEMM + resid + LN ----
#define OP_B_OFF 32768
#define OP_CTX_OFF 65536
#define OP_SMEM 73728

__global__ __launch_bounds__(256, 2) void oproj_kernel(
    const __half* __restrict__ Wt, const float* __restrict__ bias,
    const float* __restrict__ gamma, const float* __restrict__ beta)
{
    extern __shared__ float sm[];
    uint32_t smem_u = (uint32_t)__cvta_generic_to_shared(sm);

    int tid  = threadIdx.x;
    int lane = tid & 31;
    int wid  = tid >> 5;
    int warp_m = wid & 1;
    int warp_n = wid >> 1;
    int m0 = blockIdx.x * GBM;
    int b  = m0 >> 10;

    int r0 = tid >> 3;
    int c8 = tid & 7;
    uint32_t cxor = (uint32_t)((c8 ^ (r0 & 7)) << 4);

    // prefetch B tile 0 (k halfs 0..63)
#pragma unroll
    for (int i = 0; i < 4; i++) {
        int r = r0 + i * 32;
        cp_async16(smem_u + OP_B_OFF + (r << 7) + cxor, Wt + (size_t)r * E + c8 * 8);
    }
    CP_COMMIT();

    float* ctxs = (float*)((char*)sm + OP_CTX_OFF);
    for (int i = tid; i < 2048; i += 256) ctxs[i] = g_ctx[b * 2048 + i];
    __syncthreads();

    // attention prologue: A[128][128] = f16(softmax_q(q) @ ctx * 0.25)
    {
        int row = tid >> 1, half = tid & 1;
        const __half* qrow = g_qkv + (size_t)(m0 + row) * QKV_N;
#pragma unroll
        for (int hh = 0; hh < 4; hh++) {
            int h = half * 4 + hh;
            float qv[16];
            const __half2* q2 = (const __half2*)(qrow + h * 16);
#pragma unroll
            for (int j = 0; j < 8; j++) {
                float2 t = __half22float2(q2[j]);
                qv[2 * j] = t.x; qv[2 * j + 1] = t.y;
            }
            float mxv = -1e30f;
#pragma unroll
            for (int d = 0; d < 16; d++) mxv = fmaxf(mxv, qv[d]);
            float s = 0.f;
#pragma unroll
            for (int d = 0; d < 16; d++) { qv[d] = expf(qv[d] - mxv); s += qv[d]; }
            float r = 0.25f / s;
            const float* cb = ctxs + h * 256;
#pragma unroll
            for (int e2 = 0; e2 < 16; e2 += 2) {
                float a0 = 0.f, a1 = 0.f;
#pragma unroll
                for (int d = 0; d < 16; d++) {
                    float qq = qv[d];
                    a0 += qq * cb[d * 16 + e2];
                    a1 += qq * cb[d * 16 + e2 + 1];
                }
                int col = h * 16 + e2;
                int t = col >> 6, chunk = (col >> 3) & 7, hi = col & 7;
                uint32_t off = (uint32_t)(t * 16384 + (row << 7) + (((chunk) ^ (row & 7)) << 4) + hi * 2);
                *(__half2*)((char*)sm + off) =
                    __halves2half2(__float2half_rn(a0 * r), __float2half_rn(a1 * r));
            }
        }
    }

    int sub = lane >> 3;
    int l7  = lane & 7;
    int selA = sub >> 1;
    int rowAoff = ((sub & 1) << 3) + l7;
    int selB = sub & 1;
    int rowBoff = ((sub >> 1) << 3) + l7;

    float acc[4][4][4];
#pragma unroll
    for (int i = 0; i < 4; i++)
#pragma unroll
        for (int j = 0; j < 4; j++)
#pragma unroll
            for (int k = 0; k < 4; k++) acc[i][j][k] = 0.f;

    for (int it = 0; it < 2; it++) {
        CP_WAIT0();
        __syncthreads();
        if (it == 0) {
#pragma unroll
            for (int i = 0; i < 4; i++) {
                int r = r0 + i * 32;
                cp_async16(smem_u + OP_B_OFF + 16384 + (r << 7) + cxor,
                           Wt + (size_t)r * E + 64 + c8 * 8);
            }
            CP_COMMIT();
        }
        uint32_t baseA = smem_u + it * 16384;
        uint32_t baseB = smem_u + OP_B_OFF + it * 16384;
#pragma unroll
        for (int ks = 0; ks < 4; ks++) {
            int cb = ks * 2;
            uint32_t a[4][4], bb[4][2];
#pragma unroll
            for (int mt = 0; mt < 4; mt++) {
                int row = warp_m * 64 + mt * 16 + rowAoff;
                uint32_t addr = baseA + (row << 7) + (uint32_t)(((cb + selA) ^ (row & 7)) << 4);
                LDSM4(a[mt][0], a[mt][1], a[mt][2], a[mt][3], addr);
            }
#pragma unroll
            for (int bt = 0; bt < 2; bt++) {
                int row = warp_n * 32 + bt * 16 + rowBoff;
                uint32_t addr = baseB + (row << 7) + (uint32_t)(((cb + selB) ^ (row & 7)) << 4);
                LDSM4(bb[2 * bt][0], bb[2 * bt][1], bb[2 * bt + 1][0], bb[2 * bt + 1][1], addr);
            }
#pragma unroll
            for (int mt = 0; mt < 4; mt++)
#pragma unroll
                for (int nt = 0; nt < 4; nt++)
                    MMA_F16(acc[mt][nt], a[mt], bb[nt]);
        }
    }

    int g  = lane >> 2;
    int t4 = lane & 3;
    __syncthreads();
#pragma unroll
    for (int mt = 0; mt < 4; mt++) {
        int rowl0 = warp_m * 64 + mt * 16 + g;
#pragma unroll
        for (int nt = 0; nt < 4; nt++) {
            int col = warp_n * 32 + nt * 8 + t4 * 2;
            float b0 = bias[col], b1 = bias[col + 1];
#pragma unroll
            for (int hf = 0; hf < 2; hf++) {
                int rowl = rowl0 + hf * 8;
                float2* p = (float2*)(g_t + (size_t)(m0 + rowl) * E + col);
                float2 o = *p;
                float f0 = acc[mt][nt][hf * 2]     + b0 + o.x;
                float f1 = acc[mt][nt][hf * 2 + 1] + b1 + o.y;
                *p = make_float2(f0, f1);
                sm[rowl * 132 + col]     = f0;
                sm[rowl * 132 + col + 1] = f1;
            }
        }
    }
    __syncthreads();
    float g4[4], b4[4];
#pragma unroll
    for (int j = 0; j < 4; j++) { g4[j] = gamma[lane + 32 * j]; b4[j] = beta[lane + 32 * j]; }
    for (int rr = 0; rr < 16; rr++) {
        int row = wid * 16 + rr;
        float x[4];
#pragma unroll
        for (int j = 0; j < 4; j++) x[j] = sm[row * 132 + lane + 32 * j];
        float s = x[0] + x[1] + x[2] + x[3];
#pragma unroll
        for (int o = 16; o > 0; o >>= 1) s += __shfl_xor_sync(0xffffffffu, s, o);
        float mu = s * (1.0f / E);
        float s2 = 0.f;
#pragma unroll
        for (int j = 0; j < 4; j++) { float d = x[j] - mu; s2 += d * d; }
#pragma unroll
        for (int o = 16; o > 0; o >>= 1) s2 += __shfl_xor_sync(0xffffffffu, s2, o);
        float rs = rsqrtf(s2 * (1.0f / E) + LN_EPS);
#pragma unroll
        for (int j = 0; j < 4; j++)
            g_y[(size_t)(m0 + row) * E + lane + 32 * j] =
                __float2half_rn((x[j] - mu) * rs * g4[j] + b4[j]);
    }
}

// ---------------- two-stage mean over sequence ------------------------------
__global__ void mean1_kernel() {
    int blk = blockIdx.x;             // b*8 + chunk
    int b = blk >> 3, ch = blk & 7;
    int e = threadIdx.x;
    const float* p = g_t + (size_t)b * NSEQ * E + (size_t)ch * 128 * E + e;
    float s = 0.f;
#pragma unroll 8
    for (int n = 0; n < 128; n++) s += p[(size_t)n * E];
    g_part[blk * E + e] = s;
}

__global__ void mean2_kernel(float* __restrict__ out) {
    int b = blockIdx.x, e = threadIdx.x;
    float s = 0.f;
#pragma unroll
    for (int ch = 0; ch < 8; ch++) s += g_part[(b * 8 + ch) * E + e];
    out[b * E + e] = s * (1.0f / NSEQ);
}

// ---------------- launch -----------------------------------------------------
extern "C" void kernel_launch(void* const* d_in, const int* in_sizes, int n_in,
                              void* d_out, int out_size) {
    const float* x     = (const float*)d_in[0];
    const float* q_w   = (const float*)d_in[1];
    const float* k_w   = (const float*)d_in[2];
    const float* v_w   = (const float*)d_in[3];
    const float* o_w   = (const float*)d_in[4];
    const float* o_b   = (const float*)d_in[5];
    const float* ln1_g = (const float*)d_in[6];
    const float* ln1_b = (const float*)d_in[7];
    const float* ff_w1 = (const float*)d_in[8];
    const float* ff_b1 = (const float*)d_in[9];
    const float* ff_w2 = (const float*)d_in[10];
    const float* ff_b2 = (const float*)d_in[11];
    const float* ln2_g = (const float*)d_in[12];
    const float* ln2_b = (const float*)d_in[13];
    float* out = (float*)d_out;

    float *pt;
    __half *py, *pqkv, *pff, *pwt;
    cudaGetSymbolAddress((void**)&pt,   g_t);
    cudaGetSymbolAddress((void**)&py,   g_y);
    cudaGetSymbolAddress((void**)&pqkv, g_qkv);
    cudaGetSymbolAddress((void**)&pff,  g_ff);
    cudaGetSymbolAddress((void**)&pwt,  g_wt);

    cudaFuncSetAttribute(mma_gemm, cudaFuncAttributeMaxDynamicSharedMemorySize, SMEM_BYTES);
    cudaFuncSetAttribute(oproj_kernel, cudaFuncAttributeMaxDynamicSharedMemorySize, OP_SMEM);

    wt_cvt_all<<<dim3(192, NLAYERS), dim3(32, 8)>>>(q_w, k_w, v_w, o_w, ff_w1, ff_w2);
    transpose_kernel<<<dim3(NSEQ / 32, E / 32, BATCH), dim3(32, 8)>>>(x);
    ln_kernel<<<MROWS, E>>>(ln1_g, ln1_b);

    for (int l = 0; l < NLAYERS; l++) {
        const __half* wl = pwt + (size_t)l * WT_LAYER;
        // fused QKV GEMM (N=384), fp16 out
        mma_gemm<<<dim3(QKV_N / GBN, MROWS / GBM), 256, SMEM_BYTES>>>(
            py, wl, nullptr, pqkv, nullptr, nullptr, nullptr, E, QKV_N, 16);
        // fused softmax_k + ctx
        ctx_kernel<<<BATCH * NHEADS, 256>>>();
        // fused attn prologue + o-proj + residual + LN2 -> y
        oproj_kernel<<<MROWS / GBM, 256, OP_SMEM>>>(wl + 49152, o_b + l * E,
                                                    ln2_g + l * E, ln2_b + l * E);
        // FF1 + gelu -> half g_ff
        mma_gemm<<<dim3(DFF / GBN, MROWS / GBM), 256, SMEM_BYTES>>>(
            py, wl + 65536, ff_b1 + l * DFF, pff, nullptr, nullptr, nullptr, E, DFF, 1 | 16);
        // FF2 + residual (+ next-layer LN1 -> y)
        if (l < NLAYERS - 1) {
            mma_gemm<<<dim3(1, MROWS / GBM), 256, SMEM_BYTES>>>(
                pff, wl + 131072, ff_b2 + l * E, pt,
                ln1_g + (l + 1) * E, ln1_b + (l + 1) * E, py, DFF, E, 2 | 8);
        } else {
            mma_gemm<<<dim3(1, MROWS / GBM), 256, SMEM_BYTES>>>(
                pff, wl + 131072, ff_b2 + l * E, pt,
                nullptr, nullptr, nullptr, DFF, E, 2);
        }
    }

    mean1_kernel<<<512, E>>>();
    mean2_kernel<<<BATCH, E>>>(out);
}

// round 11
// speedup vs baseline: 2.0555x; 1.0387x over previous
#include <cuda_runtime.h>
#include <cuda_fp16.h>
#include <math.h>
#include <stdint.h>

#define BATCH 64
#define E 128
#define NSEQ 1024
#define NHEADS 8
#define DH 16
#define DFF 512
#define MROWS (BATCH * NSEQ)   // 65536
#define NLAYERS 4
#define LN_EPS 1e-5f
#define QKV_N 384

// ---------------- scratch (static device globals; allocation-free) ----------
__device__ float  g_t[MROWS * E];          // residual stream fp32
__device__ __half g_y[MROWS * E];          // layernorm output (fp16)
__device__ __half g_qkv[MROWS * QKV_N];    // fused q|k|v fp16, row stride 384
__device__ float  g_ctx[BATCH * NHEADS * DH * DH];
__device__ __half g_ff[MROWS * DFF];       // gelu out (fp16)
__device__ float  g_part[512 * E];         // mean partials
#define WT_LAYER 196608
__device__ __half g_wt[NLAYERS * WT_LAYER];

__device__ __forceinline__ float gelu_f(float x) {
    float x3 = x * x * x;
    return 0.5f * x * (1.0f + tanhf(0.7978845608028654f * (x + 0.044715f * x3)));
}

__device__ __forceinline__ void gdc_wait() {
    asm volatile("griddepcontrol.wait;" ::: "memory");
}

#define LDSM4(d0, d1, d2, d3, addr) \
    asm volatile("ldmatrix.sync.aligned.m8n8.x4.shared.b16 {%0,%1,%2,%3}, [%4];" \
                 : "=r"(d0), "=r"(d1), "=r"(d2), "=r"(d3) : "r"(addr))

#define MMA_F16(c, a, b) \
    asm volatile("mma.sync.aligned.m16n8k16.row.col.f32.f16.f16.f32 " \
                 "{%0,%1,%2,%3},{%4,%5,%6,%7},{%8,%9},{%0,%1,%2,%3};" \
                 : "+f"((c)[0]), "+f"((c)[1]), "+f"((c)[2]), "+f"((c)[3]) \
                 : "r"((a)[0]), "r"((a)[1]), "r"((a)[2]), "r"((a)[3]), \
                   "r"((b)[0]), "r"((b)[1]))

__device__ __forceinline__ void cp_async16(uint32_t dst, const void* src) {
    asm volatile("cp.async.cg.shared.global [%0], [%1], 16;" :: "r"(dst), "l"(src));
}
#define CP_COMMIT() asm volatile("cp.async.commit_group;")
#define CP_WAIT0()  asm volatile("cp.async.wait_group 0;")
#define CP_WAIT1()  asm volatile("cp.async.wait_group 1;")

// ---------------- fused transpose + layer-0 LN ------------------------------
// x:(B,E,N) -> g_t:(B,N,E), g_y = f16(LN(g_t)) with layer-0 params
__global__ void transpose_ln_kernel(const float* __restrict__ x,
                                    const float* __restrict__ gamma,
                                    const float* __restrict__ beta) {
    __shared__ float tile[32][129];
    int b  = blockIdx.y;
    int n0 = blockIdx.x * 32;
    int tx = threadIdx.x & 31;
    int ty = threadIdx.x >> 5;     // 0..7
#pragma unroll
    for (int e0 = 0; e0 < E; e0 += 32) {
#pragma unroll
        for (int i = 0; i < 32; i += 8)
            tile[tx][e0 + ty + i] =
                x[(size_t)b * E * NSEQ + (size_t)(e0 + ty + i) * NSEQ + n0 + tx];
    }
    __syncthreads();
    int lane = tx, wid = ty;
    float g4[4], b4[4];
#pragma unroll
    for (int j = 0; j < 4; j++) { g4[j] = gamma[lane + 32 * j]; b4[j] = beta[lane + 32 * j]; }
    for (int rr = 0; rr < 4; rr++) {
        int row = wid * 4 + rr;
        size_t grow = (size_t)b * NSEQ + n0 + row;
        float xv[4];
#pragma unroll
        for (int j = 0; j < 4; j++) {
            xv[j] = tile[row][lane + 32 * j];
            g_t[grow * E + lane + 32 * j] = xv[j];
        }
        float s = xv[0] + xv[1] + xv[2] + xv[3];
#pragma unroll
        for (int o = 16; o > 0; o >>= 1) s += __shfl_xor_sync(0xffffffffu, s, o);
        float mu = s * (1.0f / E);
        float s2 = 0.f;
#pragma unroll
        for (int j = 0; j < 4; j++) { float d = xv[j] - mu; s2 += d * d; }
#pragma unroll
        for (int o = 16; o > 0; o >>= 1) s2 += __shfl_xor_sync(0xffffffffu, s2, o);
        float rs = rsqrtf(s2 * (1.0f / E) + LN_EPS);
#pragma unroll
        for (int j = 0; j < 4; j++)
            g_y[grow * E + lane + 32 * j] =
                __float2half_rn((xv[j] - mu) * rs * g4[j] + b4[j]);
    }
}

// ---------------- fused weight convert (ALL layers, one launch), fp16 -------
__global__ void wt_cvt_all(const float* __restrict__ q_w, const float* __restrict__ k_w,
                           const float* __restrict__ v_w, const float* __restrict__ o_w,
                           const float* __restrict__ ff_w1, const float* __restrict__ ff_w2) {
    __shared__ float tile[32][33];
    int l  = blockIdx.y;
    int id = blockIdx.x;
    __half* wl = g_wt + (size_t)l * WT_LAYER;

    const float* src;
    __half* dst;
    int K, N, tn, tk;
    if (id < 64) {
        int m = id >> 4;
        const float* srcs[4] = { q_w, k_w, v_w, o_w };
        src = srcs[m] + (size_t)l * E * E;
        dst = wl + m * 16384;
        K = E; N = E;
        int t = id & 15; tn = t & 3; tk = t >> 2;
    } else if (id < 128) {
        src = ff_w1 + (size_t)l * E * DFF;
        dst = wl + 65536;
        K = E; N = DFF;
        int t = id - 64; tn = t & 15; tk = t >> 4;
    } else {
        src = ff_w2 + (size_t)l * DFF * E;
        dst = wl + 131072;
        K = DFF; N = E;
        int t = id - 128; tn = t & 3; tk = t >> 2;
    }
    int n0 = tn * 32, k0 = tk * 32;
    int tx = threadIdx.x, ty = threadIdx.y;   // (32,8)
#pragma unroll
    for (int i = 0; i < 32; i += 8)
        tile[ty + i][tx] = src[(size_t)(k0 + ty + i) * N + n0 + tx];
    __syncthreads();
#pragma unroll
    for (int i = 0; i < 32; i += 8)
        dst[(size_t)(n0 + ty + i) * K + k0 + tx] = __float2half_rn(tile[tx][ty + i]);
}

// ---------------- generic FP16 GEMM (fp32 accum), pipelined, PDL-aware ------
// C = op(A[M,K] @ Wt[N,K]^T + bias). Tiles: 128x128x(64 halfs).
// flags: 1=gelu, 2=residual add (C float), 8=fused LN -> Y (N=128, grid.x=1),
//        16 = C is half (direct half store)
#define GBM 128
#define GBN 128
#define NSTAGE 3
#define STAGE_BYTES 16384          // 128 rows * 128 bytes (64 halfs)
#define BSMEM_OFF (NSTAGE * STAGE_BYTES)
#define SMEM_BYTES (2 * NSTAGE * STAGE_BYTES)   // 98304

__global__ __launch_bounds__(256, 2) void mma_gemm(
    const __half* __restrict__ A, const __half* __restrict__ Wt,
    const float* __restrict__ bias, void* __restrict__ Cv,
    const float* __restrict__ gamma, const float* __restrict__ beta,
    __half* __restrict__ Y,
    int K, int N, int flags)
{
    extern __shared__ float sm[];
    uint32_t smem_u = (uint32_t)__cvta_generic_to_shared(sm);

    int tid  = threadIdx.x;
    int lane = tid & 31;
    int wid  = tid >> 5;
    int warp_m = wid & 1;
    int warp_n = wid >> 1;
    int bm0 = blockIdx.y * GBM;
    int bn0 = blockIdx.x * GBN;

    int r0 = tid >> 3;
    int c8 = tid & 7;
    uint32_t cxor = (uint32_t)((c8 ^ (r0 & 7)) << 4);

    auto load_A = [&](int s, int k0) {
#pragma unroll
        for (int i = 0; i < 4; i++) {
            int r = r0 + i * 32;
            uint32_t doff = (uint32_t)(r << 7) + cxor;
            cp_async16(smem_u + s * STAGE_BYTES + doff, A + (size_t)(bm0 + r) * K + k0 + c8 * 8);
        }
    };
    auto load_B = [&](int s, int k0) {
#pragma unroll
        for (int i = 0; i < 4; i++) {
            int r = r0 + i * 32;
            uint32_t doff = (uint32_t)(r << 7) + cxor;
            cp_async16(smem_u + BSMEM_OFF + s * STAGE_BYTES + doff, Wt + (size_t)(bn0 + r) * K + k0 + c8 * 8);
        }
    };

    // prefetch weight tile BEFORE the PDL dependency wait (g_wt is >=2 kernels upstream)
    load_B(0, 0); CP_COMMIT();
    gdc_wait();

    int nIter = K >> 6;
    load_A(0, 0); CP_COMMIT();
    if (nIter > 1) { load_A(1, 64); load_B(1, 64); CP_COMMIT(); }

    int sub = lane >> 3;
    int l7  = lane & 7;
    int selA = sub >> 1;
    int rowAoff = ((sub & 1) << 3) + l7;
    int selB = sub & 1;
    int rowBoff = ((sub >> 1) << 3) + l7;

    float acc[4][4][4];
#pragma unroll
    for (int i = 0; i < 4; i++)
#pragma unroll
        for (int j = 0; j < 4; j++)
#pragma unroll
            for (int k = 0; k < 4; k++) acc[i][j][k] = 0.f;

    for (int it = 0; it < nIter; it++) {
        if (it < nIter - 1) CP_WAIT1(); else CP_WAIT0();
        __syncthreads();

        int s = it % NSTAGE;
        uint32_t baseA = smem_u + s * STAGE_BYTES;
        uint32_t baseB = smem_u + BSMEM_OFF + s * STAGE_BYTES;

#pragma unroll
        for (int ks = 0; ks < 4; ks++) {
            int cb = ks * 2;
            uint32_t a[4][4], b[4][2];
#pragma unroll
            for (int mt = 0; mt < 4; mt++) {
                int row = warp_m * 64 + mt * 16 + rowAoff;
                uint32_t addr = baseA + (row << 7) + (uint32_t)(((cb + selA) ^ (row & 7)) << 4);
                LDSM4(a[mt][0], a[mt][1], a[mt][2], a[mt][3], addr);
            }
#pragma unroll
            for (int bt = 0; bt < 2; bt++) {
                int row = warp_n * 32 + bt * 16 + rowBoff;
                uint32_t addr = baseB + (row << 7) + (uint32_t)(((cb + selB) ^ (row & 7)) << 4);
                LDSM4(b[2 * bt][0], b[2 * bt][1], b[2 * bt + 1][0], b[2 * bt + 1][1], addr);
            }
#pragma unroll
            for (int mt = 0; mt < 4; mt++)
#pragma unroll
                for (int nt = 0; nt < 4; nt++)
                    MMA_F16(acc[mt][nt], a[mt], b[nt]);
        }

        if (it + 2 < nIter) {
            load_A((it + 2) % NSTAGE, (it + 2) * 64);
            load_B((it + 2) % NSTAGE, (it + 2) * 64);
            CP_COMMIT();
        }
    }

    int g  = lane >> 2;
    int t4 = lane & 3;
    bool do_ln = (flags & 8) != 0;
    if (do_ln) __syncthreads();

    float* Cf = (float*)Cv;
    __half* Ch = (__half*)Cv;

#pragma unroll
    for (int mt = 0; mt < 4; mt++) {
        int rowl0 = warp_m * 64 + mt * 16 + g;
#pragma unroll
        for (int nt = 0; nt < 4; nt++) {
            int coll = warp_n * 32 + nt * 8 + t4 * 2;
            int col  = bn0 + coll;
            float v[4] = { acc[mt][nt][0], acc[mt][nt][1], acc[mt][nt][2], acc[mt][nt][3] };
            if (bias) {
                float b0 = bias[col], b1 = bias[col + 1];
                v[0] += b0; v[1] += b1; v[2] += b0; v[3] += b1;
            }
            if (flags & 1) {
#pragma unroll
                for (int z = 0; z < 4; z++) v[z] = gelu_f(v[z]);
            }
#pragma unroll
            for (int half2i = 0; half2i < 2; half2i++) {
                int rowl = rowl0 + half2i * 8;
                float f0 = v[half2i * 2], f1 = v[half2i * 2 + 1];
                if (flags & 16) {
                    *(__half2*)(Ch + (size_t)(bm0 + rowl) * N + col) =
                        __halves2half2(__float2half_rn(f0), __float2half_rn(f1));
                } else {
                    float2* p = (float2*)(Cf + (size_t)(bm0 + rowl) * N + col);
                    if (flags & 2) {
                        float2 o = *p;
                        f0 += o.x; f1 += o.y;
                    }
                    *p = make_float2(f0, f1);
                }
                if (do_ln) {
                    sm[rowl * 132 + coll]     = f0;
                    sm[rowl * 132 + coll + 1] = f1;
                }
            }
        }
    }

    if (do_ln) {
        __syncthreads();
        float g4[4], b4[4];
#pragma unroll
        for (int j = 0; j < 4; j++) {
            g4[j] = gamma[lane + 32 * j];
            b4[j] = beta[lane + 32 * j];
        }
        for (int r = 0; r < 16; r++) {
            int row = wid * 16 + r;
            float x[4];
#pragma unroll
            for (int j = 0; j < 4; j++) x[j] = sm[row * 132 + lane + 32 * j];
            float s = x[0] + x[1] + x[2] + x[3];
#pragma unroll
            for (int o = 16; o > 0; o >>= 1) s += __shfl_xor_sync(0xffffffffu, s, o);
            float mu = s * (1.0f / E);
            float s2 = 0.f;
#pragma unroll
            for (int j = 0; j < 4; j++) { float d = x[j] - mu; s2 += d * d; }
#pragma unroll
            for (int o = 16; o > 0; o >>= 1) s2 += __shfl_xor_sync(0xffffffffu, s2, o);
            float rs = rsqrtf(s2 * (1.0f / E) + LN_EPS);
#pragma unroll
            for (int j = 0; j < 4; j++)
                Y[(size_t)(bm0 + row) * E + lane + 32 * j] =
                    __float2half_rn((x[j] - mu) * rs * g4[j] + b4[j]);
        }
    }
}

// ---------------- fused softmax_k + ctx per (b,h), fp16 inputs --------------
__global__ void ctx_kernel() {
    gdc_wait();
    int bh = blockIdx.x;
    int b = bh >> 3, h = bh & 7;
    const __half* kbase = g_qkv + (size_t)b * NSEQ * QKV_N + E + h * DH;
    const __half* vbase = kbase + E;
    int tid = threadIdx.x;

    __shared__ float smax[16][17];
    __shared__ float mx[16];
    int d0 = tid & 15, i0 = tid >> 4;
    float m = -1e30f;
#pragma unroll 8
    for (int i = 0; i < 64; i++) {
        int n = i0 + i * 16;
        m = fmaxf(m, __half2float(kbase[(size_t)n * QKV_N + d0]));
    }
    smax[d0][i0] = m;
    __syncthreads();
    if (tid < 16) {
        float t = smax[tid][0];
#pragma unroll
        for (int i = 1; i < 16; i++) t = fmaxf(t, smax[tid][i]);
        mx[tid] = t;
    }
    __syncthreads();

    __shared__ float ks[128][17];
    __shared__ float vs[128][17];
    int d = tid >> 4, e = tid & 15;
    float acc = 0.f, ssum = 0.f;
    for (int n0 = 0; n0 < NSEQ; n0 += 128) {
        __syncthreads();
        for (int l = tid; l < 128 * 8; l += 256) {
            int nl = l >> 3, c2 = l & 7;
            __half2 k2 = *(const __half2*)(kbase + (size_t)(n0 + nl) * QKV_N + c2 * 2);
            __half2 v2 = *(const __half2*)(vbase + (size_t)(n0 + nl) * QKV_N + c2 * 2);
            float2 kf = __half22float2(k2);
            float2 vf = __half22float2(v2);
            ks[nl][c2 * 2]     = expf(kf.x - mx[c2 * 2]);
            ks[nl][c2 * 2 + 1] = expf(kf.y - mx[c2 * 2 + 1]);
            vs[nl][c2 * 2]     = vf.x;
            vs[nl][c2 * 2 + 1] = vf.y;
        }
        __syncthreads();
#pragma unroll 8
        for (int nl = 0; nl < 128; nl++) {
            float kk = ks[nl][d];
            acc += kk * vs[nl][e];
            ssum += kk;
        }
    }
    g_ctx[bh * 256 + d * 16 + e] = acc / ssum;
}

// ---------------- o-proj: fused attn-A prologue + fp16 GEMM + resid + LN ----
#define OP_B_OFF 32768
#define OP_CTX_OFF 65536
#define OP_SMEM 73728

__global__ __launch_bounds__(256, 2) void oproj_kernel(
    const __half* __restrict__ Wt, const float* __restrict__ bias,
    const float* __restrict__ gamma, const float* __restrict__ beta)
{
    extern __shared__ float sm[];
    uint32_t smem_u = (uint32_t)__cvta_generic_to_shared(sm);

    int tid  = threadIdx.x;
    int lane = tid & 31;
    int wid  = tid >> 5;
    int warp_m = wid & 1;
    int warp_n = wid >> 1;
    int m0 = blockIdx.x * GBM;
    int b  = m0 >> 10;

    int r0 = tid >> 3;
    int c8 = tid & 7;
    uint32_t cxor = (uint32_t)((c8 ^ (r0 & 7)) << 4);

    // prefetch BOTH weight B tiles before PDL wait (weights are upstream-complete)
#pragma unroll
    for (int i = 0; i < 4; i++) {
        int r = r0 + i * 32;
        cp_async16(smem_u + OP_B_OFF + (r << 7) + cxor, Wt + (size_t)r * E + c8 * 8);
    }
    CP_COMMIT();
#pragma unroll
    for (int i = 0; i < 4; i++) {
        int r = r0 + i * 32;
        cp_async16(smem_u + OP_B_OFF + 16384 + (r << 7) + cxor, Wt + (size_t)r * E + 64 + c8 * 8);
    }
    CP_COMMIT();
    gdc_wait();

    float* ctxs = (float*)((char*)sm + OP_CTX_OFF);
    for (int i = tid; i < 2048; i += 256) ctxs[i] = g_ctx[b * 2048 + i];
    __syncthreads();

    // attention prologue: A[128][128] = f16(softmax_q(q) @ ctx * 0.25)
    {
        int row = tid >> 1, half = tid & 1;
        const __half* qrow = g_qkv + (size_t)(m0 + row) * QKV_N;
#pragma unroll
        for (int hh = 0; hh < 4; hh++) {
            int h = half * 4 + hh;
            float qv[16];
            const __half2* q2 = (const __half2*)(qrow + h * 16);
#pragma unroll
            for (int j = 0; j < 8; j++) {
                float2 t = __half22float2(q2[j]);
                qv[2 * j] = t.x; qv[2 * j + 1] = t.y;
            }
            float mxv = -1e30f;
#pragma unroll
            for (int d = 0; d < 16; d++) mxv = fmaxf(mxv, qv[d]);
            float s = 0.f;
#pragma unroll
            for (int d = 0; d < 16; d++) { qv[d] = expf(qv[d] - mxv); s += qv[d]; }
            float r = 0.25f / s;
            const float* cb = ctxs + h * 256;
#pragma unroll
            for (int e2 = 0; e2 < 16; e2 += 2) {
                float a0 = 0.f, a1 = 0.f;
#pragma unroll
                for (int d = 0; d < 16; d++) {
                    float qq = qv[d];
                    a0 += qq * cb[d * 16 + e2];
                    a1 += qq * cb[d * 16 + e2 + 1];
                }
                int col = h * 16 + e2;
                int t = col >> 6, chunk = (col >> 3) & 7, hi = col & 7;
                uint32_t off = (uint32_t)(t * 16384 + (row << 7) + (((chunk) ^ (row & 7)) << 4) + hi * 2);
                *(__half2*)((char*)sm + off) =
                    __halves2half2(__float2half_rn(a0 * r), __float2half_rn(a1 * r));
            }
        }
    }

    int sub = lane >> 3;
    int l7  = lane & 7;
    int selA = sub >> 1;
    int rowAoff = ((sub & 1) << 3) + l7;
    int selB = sub & 1;
    int rowBoff = ((sub >> 1) << 3) + l7;

    float acc[4][4][4];
#pragma unroll
    for (int i = 0; i < 4; i++)
#pragma unroll
        for (int j = 0; j < 4; j++)
#pragma unroll
            for (int k = 0; k < 4; k++) acc[i][j][k] = 0.f;

    for (int it = 0; it < 2; it++) {
        if (it == 0) CP_WAIT1(); else CP_WAIT0();
        __syncthreads();
        uint32_t baseA = smem_u + it * 16384;
        uint32_t baseB = smem_u + OP_B_OFF + it * 16384;
#pragma unroll
        for (int ks = 0; ks < 4; ks++) {
            int cb = ks * 2;
            uint32_t a[4][4], bb[4][2];
#pragma unroll
            for (int mt = 0; mt < 4; mt++) {
                int row = warp_m * 64 + mt * 16 + rowAoff;
                uint32_t addr = baseA + (row << 7) + (uint32_t)(((cb + selA) ^ (row & 7)) << 4);
                LDSM4(a[mt][0], a[mt][1], a[mt][2], a[mt][3], addr);
            }
#pragma unroll
            for (int bt = 0; bt < 2; bt++) {
                int row = warp_n * 32 + bt * 16 + rowBoff;
                uint32_t addr = baseB + (row << 7) + (uint32_t)(((cb + selB) ^ (row & 7)) << 4);
                LDSM4(bb[2 * bt][0], bb[2 * bt][1], bb[2 * bt + 1][0], bb[2 * bt + 1][1], addr);
            }
#pragma unroll
            for (int mt = 0; mt < 4; mt++)
#pragma unroll
                for (int nt = 0; nt < 4; nt++)
                    MMA_F16(acc[mt][nt], a[mt], bb[nt]);
        }
    }

    int g  = lane >> 2;
    int t4 = lane & 3;
    __syncthreads();
#pragma unroll
    for (int mt = 0; mt < 4; mt++) {
        int rowl0 = warp_m * 64 + mt * 16 + g;
#pragma unroll
        for (int nt = 0; nt < 4; nt++) {
            int col = warp_n * 32 + nt * 8 + t4 * 2;
            float b0 = bias[col], b1 = bias[col + 1];
#pragma unroll
            for (int hf = 0; hf < 2; hf++) {
                int rowl = rowl0 + hf * 8;
                float2* p = (float2*)(g_t + (size_t)(m0 + rowl) * E + col);
                float2 o = *p;
                float f0 = acc[mt][nt][hf * 2]     + b0 + o.x;
                float f1 = acc[mt][nt][hf * 2 + 1] + b1 + o.y;
                *p = make_float2(f0, f1);
                sm[rowl * 132 + col]     = f0;
                sm[rowl * 132 + col + 1] = f1;
            }
        }
    }
    __syncthreads();
    float g4[4], b4[4];
#pragma unroll
    for (int j = 0; j < 4; j++) { g4[j] = gamma[lane + 32 * j]; b4[j] = beta[lane + 32 * j]; }
    for (int rr = 0; rr < 16; rr++) {
        int row = wid * 16 + rr;
        float x[4];
#pragma unroll
        for (int j = 0; j < 4; j++) x[j] = sm[row * 132 + lane + 32 * j];
        float s = x[0] + x[1] + x[2] + x[3];
#pragma unroll
        for (int o = 16; o > 0; o >>= 1) s += __shfl_xor_sync(0xffffffffu, s, o);
        float mu = s * (1.0f / E);
        float s2 = 0.f;
#pragma unroll
        for (int j = 0; j < 4; j++) { float d = x[j] - mu; s2 += d * d; }
#pragma unroll
        for (int o = 16; o > 0; o >>= 1) s2 += __shfl_xor_sync(0xffffffffu, s2, o);
        float rs = rsqrtf(s2 * (1.0f / E) + LN_EPS);
#pragma unroll
        for (int j = 0; j < 4; j++)
            g_y[(size_t)(m0 + row) * E + lane + 32 * j] =
                __float2half_rn((x[j] - mu) * rs * g4[j] + b4[j]);
    }
}

// ---------------- two-stage mean over sequence ------------------------------
__global__ void mean1_kernel() {
    gdc_wait();
    int blk = blockIdx.x;             // b*8 + chunk
    int b = blk >> 3, ch = blk & 7;
    int e = threadIdx.x;
    const float* p = g_t + (size_t)b * NSEQ * E + (size_t)ch * 128 * E + e;
    float s = 0.f;
#pragma unroll 8
    for (int n = 0; n < 128; n++) s += p[(size_t)n * E];
    g_part[blk * E + e] = s;
}

__global__ void mean2_kernel(float* __restrict__ out) {
    gdc_wait();
    int b = blockIdx.x, e = threadIdx.x;
    float s = 0.f;
#pragma unroll
    for (int ch = 0; ch < 8; ch++) s += g_part[(b * 8 + ch) * E + e];
    out[b * E + e] = s * (1.0f / NSEQ);
}

// ---------------- PDL launch helper ------------------------------------------
template <typename F, typename... A>
static inline void launchPDL(F f, dim3 grid, dim3 block, size_t smem, A... args) {
    cudaLaunchConfig_t cfg = {};
    cfg.gridDim = grid;
    cfg.blockDim = block;
    cfg.dynamicSmemBytes = smem;
    cfg.stream = 0;
    cudaLaunchAttribute at[1];
    at[0].id = cudaLaunchAttributeProgrammaticStreamSerialization;
    at[0].val.programmaticStreamSerializationAllowed = 1;
    cfg.attrs = at;
    cfg.numAttrs = 1;
    cudaLaunchKernelEx(&cfg, f, args...);
}

// ---------------- launch -----------------------------------------------------
extern "C" void kernel_launch(void* const* d_in, const int* in_sizes, int n_in,
                              void* d_out, int out_size) {
    const float* x     = (const float*)d_in[0];
    const float* q_w   = (const float*)d_in[1];
    const float* k_w   = (const float*)d_in[2];
    const float* v_w   = (const float*)d_in[3];
    const float* o_w   = (const float*)d_in[4];
    const float* o_b   = (const float*)d_in[5];
    const float* ln1_g = (const float*)d_in[6];
    const float* ln1_b = (const float*)d_in[7];
    const float* ff_w1 = (const float*)d_in[8];
    const float* ff_b1 = (const float*)d_in[9];
    const float* ff_w2 = (const float*)d_in[10];
    const float* ff_b2 = (const float*)d_in[11];
    const float* ln2_g = (const float*)d_in[12];
    const float* ln2_b = (const float*)d_in[13];
    float* out = (float*)d_out;

    float* pt;
    __half *py, *pqkv, *pff, *pwt;
    cudaGetSymbolAddress((void**)&pt,   g_t);
    cudaGetSymbolAddress((void**)&py,   g_y);
    cudaGetSymbolAddress((void**)&pqkv, g_qkv);
    cudaGetSymbolAddress((void**)&pff,  g_ff);
    cudaGetSymbolAddress((void**)&pwt,  g_wt);

    cudaFuncSetAttribute(mma_gemm, cudaFuncAttributeMaxDynamicSharedMemorySize, SMEM_BYTES);
    cudaFuncSetAttribute(oproj_kernel, cudaFuncAttributeMaxDynamicSharedMemorySize, OP_SMEM);

    wt_cvt_all<<<dim3(192, NLAYERS), dim3(32, 8)>>>(q_w, k_w, v_w, o_w, ff_w1, ff_w2);
    transpose_ln_kernel<<<dim3(NSEQ / 32, BATCH), 256>>>(x, ln1_g, ln1_b);

    for (int l = 0; l < NLAYERS; l++) {
        const __half* wl = pwt + (size_t)l * WT_LAYER;
        // fused QKV GEMM (N=384), fp16 out
        launchPDL(mma_gemm, dim3(QKV_N / GBN, MROWS / GBM), dim3(256), SMEM_BYTES,
                  (const __half*)py, wl, (const float*)nullptr, (void*)pqkv,
                  (const float*)nullptr, (const float*)nullptr, (__half*)nullptr,
                  (int)E, (int)QKV_N, (int)16);
        // fused softmax_k + ctx
        launchPDL(ctx_kernel, dim3(BATCH * NHEADS), dim3(256), 0);
        // fused attn prologue + o-proj + residual + LN2 -> y
        launchPDL(oproj_kernel, dim3(MROWS / GBM), dim3(256), OP_SMEM,
                  wl + 49152, (const float*)(o_b + l * E),
                  (const float*)(ln2_g + l * E), (const float*)(ln2_b + l * E));
        // FF1 + gelu -> half g_ff
        launchPDL(mma_gemm, dim3(DFF / GBN, MROWS / GBM), dim3(256), SMEM_BYTES,
                  (const __half*)py, wl + 65536, (const float*)(ff_b1 + l * DFF), (void*)pff,
                  (const float*)nullptr, (const float*)nullptr, (__half*)nullptr,
                  (int)E, (int)DFF, (int)(1 | 16));
        // FF2 + residual (+ next-layer LN1 -> y)
        if (l < NLAYERS - 1) {
            launchPDL(mma_gemm, dim3(1, MROWS / GBM), dim3(256), SMEM_BYTES,
                      (const __half*)pff, wl + 131072, (const float*)(ff_b2 + l * E), (void*)pt,
                      (const float*)(ln1_g + (l + 1) * E), (const float*)(ln1_b + (l + 1) * E),
                      py, (int)DFF, (int)E, (int)(2 | 8));
        } else {
            launchPDL(mma_gemm, dim3(1, MROWS / GBM), dim3(256), SMEM_BYTES,
                      (const __half*)pff, wl + 131072, (const float*)(ff_b2 + l * E), (void*)pt,
                      (const float*)nullptr, (const float*)nullptr, (__half*)nullptr,
                      (int)DFF, (int)E, (int)2);
        }
    }

    launchPDL(mean1_kernel, dim3(512), dim3(E), 0);
    launchPDL(mean2_kernel, dim3(BATCH), dim3(E), 0, out);
}

// round 12
// speedup vs baseline: 2.1594x; 1.0505x over previous
#include <cuda_runtime.h>
#include <cuda_fp16.h>
#include <math.h>
#include <stdint.h>

#define BATCH 64
#define E 128
#define NSEQ 1024
#define NHEADS 8
#define DH 16
#define DFF 512
#define MROWS (BATCH * NSEQ)   // 65536
#define NLAYERS 4
#define LN_EPS 1e-5f
#define QKV_N 384
#define NCHUNK 4
#define CHUNK_N (NSEQ / NCHUNK)   // 256

// ---------------- scratch (static device globals; allocation-free) ----------
__device__ float  g_t[MROWS * E];          // residual stream fp32
__device__ __half g_y[MROWS * E];          // layernorm output (fp16)
__device__ __half g_qkv[MROWS * QKV_N];    // fused q|k|v fp16, row stride 384
__device__ float  g_ctxp[BATCH * NHEADS * NCHUNK * 256];  // ctx partials
__device__ float  g_ssum[BATCH * NHEADS * NCHUNK * 16];   // exp-sum partials
__device__ __half g_ff[MROWS * DFF];       // gelu out (fp16)
__device__ float  g_part[512 * E];         // mean partials
#define WT_LAYER 196608
__device__ __half g_wt[NLAYERS * WT_LAYER];

__device__ __forceinline__ float gelu_f(float x) {
    float x3 = x * x * x;
    return 0.5f * x * (1.0f + tanhf(0.7978845608028654f * (x + 0.044715f * x3)));
}

__device__ __forceinline__ void gdc_wait() {
    asm volatile("griddepcontrol.wait;" ::: "memory");
}

#define LDSM4(d0, d1, d2, d3, addr) \
    asm volatile("ldmatrix.sync.aligned.m8n8.x4.shared.b16 {%0,%1,%2,%3}, [%4];" \
                 : "=r"(d0), "=r"(d1), "=r"(d2), "=r"(d3) : "r"(addr))

#define MMA_F16(c, a, b) \
    asm volatile("mma.sync.aligned.m16n8k16.row.col.f32.f16.f16.f32 " \
                 "{%0,%1,%2,%3},{%4,%5,%6,%7},{%8,%9},{%0,%1,%2,%3};" \
                 : "+f"((c)[0]), "+f"((c)[1]), "+f"((c)[2]), "+f"((c)[3]) \
                 : "r"((a)[0]), "r"((a)[1]), "r"((a)[2]), "r"((a)[3]), \
                   "r"((b)[0]), "r"((b)[1]))

__device__ __forceinline__ void cp_async16(uint32_t dst, const void* src) {
    asm volatile("cp.async.cg.shared.global [%0], [%1], 16;" :: "r"(dst), "l"(src));
}
#define CP_COMMIT() asm volatile("cp.async.commit_group;")
#define CP_WAIT0()  asm volatile("cp.async.wait_group 0;")
#define CP_WAIT1()  asm volatile("cp.async.wait_group 1;")

// ---------------- fused transpose + layer-0 LN ------------------------------
__global__ void transpose_ln_kernel(const float* __restrict__ x,
                                    const float* __restrict__ gamma,
                                    const float* __restrict__ beta) {
    __shared__ float tile[32][129];
    int b  = blockIdx.y;
    int n0 = blockIdx.x * 32;
    int tx = threadIdx.x & 31;
    int ty = threadIdx.x >> 5;     // 0..7
#pragma unroll
    for (int e0 = 0; e0 < E; e0 += 32) {
#pragma unroll
        for (int i = 0; i < 32; i += 8)
            tile[tx][e0 + ty + i] =
                x[(size_t)b * E * NSEQ + (size_t)(e0 + ty + i) * NSEQ + n0 + tx];
    }
    __syncthreads();
    int lane = tx, wid = ty;
    float g4[4], b4[4];
#pragma unroll
    for (int j = 0; j < 4; j++) { g4[j] = gamma[lane + 32 * j]; b4[j] = beta[lane + 32 * j]; }
    for (int rr = 0; rr < 4; rr++) {
        int row = wid * 4 + rr;
        size_t grow = (size_t)b * NSEQ + n0 + row;
        float xv[4];
#pragma unroll
        for (int j = 0; j < 4; j++) {
            xv[j] = tile[row][lane + 32 * j];
            g_t[grow * E + lane + 32 * j] = xv[j];
        }
        float s = xv[0] + xv[1] + xv[2] + xv[3];
#pragma unroll
        for (int o = 16; o > 0; o >>= 1) s += __shfl_xor_sync(0xffffffffu, s, o);
        float mu = s * (1.0f / E);
        float s2 = 0.f;
#pragma unroll
        for (int j = 0; j < 4; j++) { float d = xv[j] - mu; s2 += d * d; }
#pragma unroll
        for (int o = 16; o > 0; o >>= 1) s2 += __shfl_xor_sync(0xffffffffu, s2, o);
        float rs = rsqrtf(s2 * (1.0f / E) + LN_EPS);
#pragma unroll
        for (int j = 0; j < 4; j++)
            g_y[grow * E + lane + 32 * j] =
                __float2half_rn((xv[j] - mu) * rs * g4[j] + b4[j]);
    }
}

// ---------------- fused weight convert (ALL layers, one launch), fp16 -------
__global__ void wt_cvt_all(const float* __restrict__ q_w, const float* __restrict__ k_w,
                           const float* __restrict__ v_w, const float* __restrict__ o_w,
                           const float* __restrict__ ff_w1, const float* __restrict__ ff_w2) {
    __shared__ float tile[32][33];
    int l  = blockIdx.y;
    int id = blockIdx.x;
    __half* wl = g_wt + (size_t)l * WT_LAYER;

    const float* src;
    __half* dst;
    int K, N, tn, tk;
    if (id < 64) {
        int m = id >> 4;
        const float* srcs[4] = { q_w, k_w, v_w, o_w };
        src = srcs[m] + (size_t)l * E * E;
        dst = wl + m * 16384;
        K = E; N = E;
        int t = id & 15; tn = t & 3; tk = t >> 2;
    } else if (id < 128) {
        src = ff_w1 + (size_t)l * E * DFF;
        dst = wl + 65536;
        K = E; N = DFF;
        int t = id - 64; tn = t & 15; tk = t >> 4;
    } else {
        src = ff_w2 + (size_t)l * DFF * E;
        dst = wl + 131072;
        K = DFF; N = E;
        int t = id - 128; tn = t & 3; tk = t >> 2;
    }
    int n0 = tn * 32, k0 = tk * 32;
    int tx = threadIdx.x, ty = threadIdx.y;   // (32,8)
#pragma unroll
    for (int i = 0; i < 32; i += 8)
        tile[ty + i][tx] = src[(size_t)(k0 + ty + i) * N + n0 + tx];
    __syncthreads();
#pragma unroll
    for (int i = 0; i < 32; i += 8)
        dst[(size_t)(n0 + ty + i) * K + k0 + tx] = __float2half_rn(tile[tx][ty + i]);
}

// ---------------- generic FP16 GEMM (fp32 accum), pipelined, PDL-aware ------
#define GBM 128
#define GBN 128
#define NSTAGE 3
#define STAGE_BYTES 16384
#define BSMEM_OFF (NSTAGE * STAGE_BYTES)
#define SMEM_BYTES (2 * NSTAGE * STAGE_BYTES)   // 98304

__global__ __launch_bounds__(256, 2) void mma_gemm(
    const __half* __restrict__ A, const __half* __restrict__ Wt,
    const float* __restrict__ bias, void* __restrict__ Cv,
    const float* __restrict__ gamma, const float* __restrict__ beta,
    __half* __restrict__ Y,
    int K, int N, int flags)
{
    extern __shared__ float sm[];
    uint32_t smem_u = (uint32_t)__cvta_generic_to_shared(sm);

    int tid  = threadIdx.x;
    int lane = tid & 31;
    int wid  = tid >> 5;
    int warp_m = wid & 1;
    int warp_n = wid >> 1;
    int bm0 = blockIdx.y * GBM;
    int bn0 = blockIdx.x * GBN;

    int r0 = tid >> 3;
    int c8 = tid & 7;
    uint32_t cxor = (uint32_t)((c8 ^ (r0 & 7)) << 4);

    auto load_A = [&](int s, int k0) {
#pragma unroll
        for (int i = 0; i < 4; i++) {
            int r = r0 + i * 32;
            uint32_t doff = (uint32_t)(r << 7) + cxor;
            cp_async16(smem_u + s * STAGE_BYTES + doff, A + (size_t)(bm0 + r) * K + k0 + c8 * 8);
        }
    };
    auto load_B = [&](int s, int k0) {
#pragma unroll
        for (int i = 0; i < 4; i++) {
            int r = r0 + i * 32;
            uint32_t doff = (uint32_t)(r << 7) + cxor;
            cp_async16(smem_u + BSMEM_OFF + s * STAGE_BYTES + doff, Wt + (size_t)(bn0 + r) * K + k0 + c8 * 8);
        }
    };

    load_B(0, 0); CP_COMMIT();
    gdc_wait();

    int nIter = K >> 6;
    load_A(0, 0); CP_COMMIT();
    if (nIter > 1) { load_A(1, 64); load_B(1, 64); CP_COMMIT(); }

    int sub = lane >> 3;
    int l7  = lane & 7;
    int selA = sub >> 1;
    int rowAoff = ((sub & 1) << 3) + l7;
    int selB = sub & 1;
    int rowBoff = ((sub >> 1) << 3) + l7;

    float acc[4][4][4];
#pragma unroll
    for (int i = 0; i < 4; i++)
#pragma unroll
        for (int j = 0; j < 4; j++)
#pragma unroll
            for (int k = 0; k < 4; k++) acc[i][j][k] = 0.f;

    for (int it = 0; it < nIter; it++) {
        if (it < nIter - 1) CP_WAIT1(); else CP_WAIT0();
        __syncthreads();

        int s = it % NSTAGE;
        uint32_t baseA = smem_u + s * STAGE_BYTES;
        uint32_t baseB = smem_u + BSMEM_OFF + s * STAGE_BYTES;

#pragma unroll
        for (int ks = 0; ks < 4; ks++) {
            int cb = ks * 2;
            uint32_t a[4][4], b[4][2];
#pragma unroll
            for (int mt = 0; mt < 4; mt++) {
                int row = warp_m * 64 + mt * 16 + rowAoff;
                uint32_t addr = baseA + (row << 7) + (uint32_t)(((cb + selA) ^ (row & 7)) << 4);
                LDSM4(a[mt][0], a[mt][1], a[mt][2], a[mt][3], addr);
            }
#pragma unroll
            for (int bt = 0; bt < 2; bt++) {
                int row = warp_n * 32 + bt * 16 + rowBoff;
                uint32_t addr = baseB + (row << 7) + (uint32_t)(((cb + selB) ^ (row & 7)) << 4);
                LDSM4(b[2 * bt][0], b[2 * bt][1], b[2 * bt + 1][0], b[2 * bt + 1][1], addr);
            }
#pragma unroll
            for (int mt = 0; mt < 4; mt++)
#pragma unroll
                for (int nt = 0; nt < 4; nt++)
                    MMA_F16(acc[mt][nt], a[mt], b[nt]);
        }

        if (it + 2 < nIter) {
            load_A((it + 2) % NSTAGE, (it + 2) * 64);
            load_B((it + 2) % NSTAGE, (it + 2) * 64);
            CP_COMMIT();
        }
    }

    int g  = lane >> 2;
    int t4 = lane & 3;
    bool do_ln = (flags & 8) != 0;
    if (do_ln) __syncthreads();

    float* Cf = (float*)Cv;
    __half* Ch = (__half*)Cv;

#pragma unroll
    for (int mt = 0; mt < 4; mt++) {
        int rowl0 = warp_m * 64 + mt * 16 + g;
#pragma unroll
        for (int nt = 0; nt < 4; nt++) {
            int coll = warp_n * 32 + nt * 8 + t4 * 2;
            int col  = bn0 + coll;
            float v[4] = { acc[mt][nt][0], acc[mt][nt][1], acc[mt][nt][2], acc[mt][nt][3] };
            if (bias) {
                float b0 = bias[col], b1 = bias[col + 1];
                v[0] += b0; v[1] += b1; v[2] += b0; v[3] += b1;
            }
            if (flags & 1) {
#pragma unroll
                for (int z = 0; z < 4; z++) v[z] = gelu_f(v[z]);
            }
#pragma unroll
            for (int half2i = 0; half2i < 2; half2i++) {
                int rowl = rowl0 + half2i * 8;
                float f0 = v[half2i * 2], f1 = v[half2i * 2 + 1];
                if (flags & 16) {
                    *(__half2*)(Ch + (size_t)(bm0 + rowl) * N + col) =
                        __halves2half2(__float2half_rn(f0), __float2half_rn(f1));
                } else {
                    float2* p = (float2*)(Cf + (size_t)(bm0 + rowl) * N + col);
                    if (flags & 2) {
                        float2 o = *p;
                        f0 += o.x; f1 += o.y;
                    }
                    *p = make_float2(f0, f1);
                }
                if (do_ln) {
                    sm[rowl * 132 + coll]     = f0;
                    sm[rowl * 132 + coll + 1] = f1;
                }
            }
        }
    }

    if (do_ln) {
        __syncthreads();
        float g4[4], b4[4];
#pragma unroll
        for (int j = 0; j < 4; j++) {
            g4[j] = gamma[lane + 32 * j];
            b4[j] = beta[lane + 32 * j];
        }
        for (int r = 0; r < 16; r++) {
            int row = wid * 16 + r;
            float x[4];
#pragma unroll
            for (int j = 0; j < 4; j++) x[j] = sm[row * 132 + lane + 32 * j];
            float s = x[0] + x[1] + x[2] + x[3];
#pragma unroll
            for (int o = 16; o > 0; o >>= 1) s += __shfl_xor_sync(0xffffffffu, s, o);
            float mu = s * (1.0f / E);
            float s2 = 0.f;
#pragma unroll
            for (int j = 0; j < 4; j++) { float d = x[j] - mu; s2 += d * d; }
#pragma unroll
            for (int o = 16; o > 0; o >>= 1) s2 += __shfl_xor_sync(0xffffffffu, s2, o);
            float rs = rsqrtf(s2 * (1.0f / E) + LN_EPS);
#pragma unroll
            for (int j = 0; j < 4; j++)
                Y[(size_t)(bm0 + row) * E + lane + 32 * j] =
                    __float2half_rn((x[j] - mu) * rs * g4[j] + b4[j]);
        }
    }
}

// ---------------- ctx partial: exp(k)-weighted v over a 256-row chunk -------
// grid = BATCH*NHEADS*NCHUNK. No max subtraction (softmax shift-invariance;
// |k| <~ 1.5 so exp is well-conditioned). Partials summed in oproj prologue.
__global__ void ctx_part_kernel() {
    gdc_wait();
    int blk = blockIdx.x;              // bh*NCHUNK + c
    int bh = blk >> 2, c = blk & 3;
    int b = bh >> 3, h = bh & 7;
    const __half* kbase = g_qkv + (size_t)b * NSEQ * QKV_N + (size_t)c * CHUNK_N * QKV_N + E + h * DH;
    const __half* vbase = kbase + E;
    int tid = threadIdx.x;

    __shared__ float ks[128][17];
    __shared__ float vs[128][17];
    int d = tid >> 4, e = tid & 15;
    float acc = 0.f, ssum = 0.f;
    for (int n0 = 0; n0 < CHUNK_N; n0 += 128) {
        __syncthreads();
        for (int l = tid; l < 128 * 8; l += 256) {
            int nl = l >> 3, c2 = l & 7;
            __half2 k2 = *(const __half2*)(kbase + (size_t)(n0 + nl) * QKV_N + c2 * 2);
            __half2 v2 = *(const __half2*)(vbase + (size_t)(n0 + nl) * QKV_N + c2 * 2);
            float2 kf = __half22float2(k2);
            float2 vf = __half22float2(v2);
            ks[nl][c2 * 2]     = expf(kf.x);
            ks[nl][c2 * 2 + 1] = expf(kf.y);
            vs[nl][c2 * 2]     = vf.x;
            vs[nl][c2 * 2 + 1] = vf.y;
        }
        __syncthreads();
#pragma unroll 16
        for (int nl = 0; nl < 128; nl++) {
            float kk = ks[nl][d];
            acc += kk * vs[nl][e];
            ssum += kk;
        }
    }
    g_ctxp[blk * 256 + d * 16 + e] = acc;
    if (e == 0) g_ssum[blk * 16 + d] = ssum;
}

// ---------------- o-proj: partial-reduce + attn prologue + GEMM + LN --------
#define OP_B_OFF 32768
#define OP_CTX_OFF 65536
#define OP_SMEM 73728

__global__ __launch_bounds__(256, 2) void oproj_kernel(
    const __half* __restrict__ Wt, const float* __restrict__ bias,
    const float* __restrict__ gamma, const float* __restrict__ beta)
{
    extern __shared__ float sm[];
    uint32_t smem_u = (uint32_t)__cvta_generic_to_shared(sm);

    int tid  = threadIdx.x;
    int lane = tid & 31;
    int wid  = tid >> 5;
    int warp_m = wid & 1;
    int warp_n = wid >> 1;
    int m0 = blockIdx.x * GBM;
    int b  = m0 >> 10;

    int r0 = tid >> 3;
    int c8 = tid & 7;
    uint32_t cxor = (uint32_t)((c8 ^ (r0 & 7)) << 4);

    // prefetch BOTH weight tiles before PDL wait (weights upstream-complete)
#pragma unroll
    for (int i = 0; i < 4; i++) {
        int r = r0 + i * 32;
        cp_async16(smem_u + OP_B_OFF + (r << 7) + cxor, Wt + (size_t)r * E + c8 * 8);
    }
    CP_COMMIT();
#pragma unroll
    for (int i = 0; i < 4; i++) {
        int r = r0 + i * 32;
        cp_async16(smem_u + OP_B_OFF + 16384 + (r << 7) + cxor, Wt + (size_t)r * E + 64 + c8 * 8);
    }
    CP_COMMIT();
    gdc_wait();

    // reduce ctx partials into smem: ctx = (Σ_c acc) / (Σ_c ssum)
    float* ctxs = (float*)((char*)sm + OP_CTX_OFF);
    for (int i = tid; i < 2048; i += 256) {
        int h = i >> 8, de = i & 255, d = de >> 4;
        int bh4 = ((b * NHEADS + h) << 2);
        float a = 0.f, ss = 0.f;
#pragma unroll
        for (int c = 0; c < 4; c++) {
            a  += g_ctxp[(bh4 + c) * 256 + de];
            ss += g_ssum[(bh4 + c) * 16 + d];
        }
        ctxs[i] = a / ss;
    }
    __syncthreads();

    // attention prologue: A[128][128] = f16(softmax_q(q) @ ctx * 0.25)
    {
        int row = tid >> 1, half = tid & 1;
        const __half* qrow = g_qkv + (size_t)(m0 + row) * QKV_N;
#pragma unroll
        for (int hh = 0; hh < 4; hh++) {
            int h = half * 4 + hh;
            float qv[16];
            const __half2* q2 = (const __half2*)(qrow + h * 16);
#pragma unroll
            for (int j = 0; j < 8; j++) {
                float2 t = __half22float2(q2[j]);
                qv[2 * j] = t.x; qv[2 * j + 1] = t.y;
            }
            float mxv = -1e30f;
#pragma unroll
            for (int d = 0; d < 16; d++) mxv = fmaxf(mxv, qv[d]);
            float s = 0.f;
#pragma unroll
            for (int d = 0; d < 16; d++) { qv[d] = expf(qv[d] - mxv); s += qv[d]; }
            float r = 0.25f / s;
            const float* cb = ctxs + h * 256;
#pragma unroll
            for (int e2 = 0; e2 < 16; e2 += 2) {
                float a0 = 0.f, a1 = 0.f;
#pragma unroll
                for (int d = 0; d < 16; d++) {
                    float qq = qv[d];
                    a0 += qq * cb[d * 16 + e2];
                    a1 += qq * cb[d * 16 + e2 + 1];
                }
                int col = h * 16 + e2;
                int t = col >> 6, chunk = (col >> 3) & 7, hi = col & 7;
                uint32_t off = (uint32_t)(t * 16384 + (row << 7) + (((chunk) ^ (row & 7)) << 4) + hi * 2);
                *(__half2*)((char*)sm + off) =
                    __halves2half2(__float2half_rn(a0 * r), __float2half_rn(a1 * r));
            }
        }
    }

    int sub = lane >> 3;
    int l7  = lane & 7;
    int selA = sub >> 1;
    int rowAoff = ((sub & 1) << 3) + l7;
    int selB = sub & 1;
    int rowBoff = ((sub >> 1) << 3) + l7;

    float acc[4][4][4];
#pragma unroll
    for (int i = 0; i < 4; i++)
#pragma unroll
        for (int j = 0; j < 4; j++)
#pragma unroll
            for (int k = 0; k < 4; k++) acc[i][j][k] = 0.f;

    for (int it = 0; it < 2; it++) {
        if (it == 0) CP_WAIT1(); else CP_WAIT0();
        __syncthreads();
        uint32_t baseA = smem_u + it * 16384;
        uint32_t baseB = smem_u + OP_B_OFF + it * 16384;
#pragma unroll
        for (int ks = 0; ks < 4; ks++) {
            int cb = ks * 2;
            uint32_t a[4][4], bb[4][2];
#pragma unroll
            for (int mt = 0; mt < 4; mt++) {
                int row = warp_m * 64 + mt * 16 + rowAoff;
                uint32_t addr = baseA + (row << 7) + (uint32_t)(((cb + selA) ^ (row & 7)) << 4);
                LDSM4(a[mt][0], a[mt][1], a[mt][2], a[mt][3], addr);
            }
#pragma unroll
            for (int bt = 0; bt < 2; bt++) {
                int row = warp_n * 32 + bt * 16 + rowBoff;
                uint32_t addr = baseB + (row << 7) + (uint32_t)(((cb + selB) ^ (row & 7)) << 4);
                LDSM4(bb[2 * bt][0], bb[2 * bt][1], bb[2 * bt + 1][0], bb[2 * bt + 1][1], addr);
            }
#pragma unroll
            for (int mt = 0; mt < 4; mt++)
#pragma unroll
                for (int nt = 0; nt < 4; nt++)
                    MMA_F16(acc[mt][nt], a[mt], bb[nt]);
        }
    }

    int g  = lane >> 2;
    int t4 = lane & 3;
    __syncthreads();
#pragma unroll
    for (int mt = 0; mt < 4; mt++) {
        int rowl0 = warp_m * 64 + mt * 16 + g;
#pragma unroll
        for (int nt = 0; nt < 4; nt++) {
            int col = warp_n * 32 + nt * 8 + t4 * 2;
            float b0 = bias[col], b1 = bias[col + 1];
#pragma unroll
            for (int hf = 0; hf < 2; hf++) {
                int rowl = rowl0 + hf * 8;
                float2* p = (float2*)(g_t + (size_t)(m0 + rowl) * E + col);
                float2 o = *p;
                float f0 = acc[mt][nt][hf * 2]     + b0 + o.x;
                float f1 = acc[mt][nt][hf * 2 + 1] + b1 + o.y;
                *p = make_float2(f0, f1);
                sm[rowl * 132 + col]     = f0;
                sm[rowl * 132 + col + 1] = f1;
            }
        }
    }
    __syncthreads();
    float g4[4], b4[4];
#pragma unroll
    for (int j = 0; j < 4; j++) { g4[j] = gamma[lane + 32 * j]; b4[j] = beta[lane + 32 * j]; }
    for (int rr = 0; rr < 16; rr++) {
        int row = wid * 16 + rr;
        float x[4];
#pragma unroll
        for (int j = 0; j < 4; j++) x[j] = sm[row * 132 + lane + 32 * j];
        float s = x[0] + x[1] + x[2] + x[3];
#pragma unroll
        for (int o = 16; o > 0; o >>= 1) s += __shfl_xor_sync(0xffffffffu, s, o);
        float mu = s * (1.0f / E);
        float s2 = 0.f;
#pragma unroll
        for (int j = 0; j < 4; j++) { float d = x[j] - mu; s2 += d * d; }
#pragma unroll
        for (int o = 16; o > 0; o >>= 1) s2 += __shfl_xor_sync(0xffffffffu, s2, o);
        float rs = rsqrtf(s2 * (1.0f / E) + LN_EPS);
#pragma unroll
        for (int j = 0; j < 4; j++)
            g_y[(size_t)(m0 + row) * E + lane + 32 * j] =
                __float2half_rn((x[j] - mu) * rs * g4[j] + b4[j]);
    }
}

// ---------------- two-stage mean over sequence ------------------------------
__global__ void mean1_kernel() {
    gdc_wait();
    int blk = blockIdx.x;             // b*8 + chunk
    int b = blk >> 3, ch = blk & 7;
    int e = threadIdx.x;
    const float* p = g_t + (size_t)b * NSEQ * E + (size_t)ch * 128 * E + e;
    float s = 0.f;
#pragma unroll 8
    for (int n = 0; n < 128; n++) s += p[(size_t)n * E];
    g_part[blk * E + e] = s;
}

__global__ void mean2_kernel(float* __restrict__ out) {
    gdc_wait();
    int b = blockIdx.x, e = threadIdx.x;
    float s = 0.f;
#pragma unroll
    for (int ch = 0; ch < 8; ch++) s += g_part[(b * 8 + ch) * E + e];
    out[b * E + e] = s * (1.0f / NSEQ);
}

// ---------------- PDL launch helper ------------------------------------------
template <typename F, typename... A>
static inline void launchPDL(F f, dim3 grid, dim3 block, size_t smem, A... args) {
    cudaLaunchConfig_t cfg = {};
    cfg.gridDim = grid;
    cfg.blockDim = block;
    cfg.dynamicSmemBytes = smem;
    cfg.stream = 0;
    cudaLaunchAttribute at[1];
    at[0].id = cudaLaunchAttributeProgrammaticStreamSerialization;
    at[0].val.programmaticStreamSerializationAllowed = 1;
    cfg.attrs = at;
    cfg.numAttrs = 1;
    cudaLaunchKernelEx(&cfg, f, args...);
}

// ---------------- launch -----------------------------------------------------
extern "C" void kernel_launch(void* const* d_in, const int* in_sizes, int n_in,
                              void* d_out, int out_size) {
    const float* x     = (const float*)d_in[0];
    const float* q_w   = (const float*)d_in[1];
    const float* k_w   = (const float*)d_in[2];
    const float* v_w   = (const float*)d_in[3];
    const float* o_w   = (const float*)d_in[4];
    const float* o_b   = (const float*)d_in[5];
    const float* ln1_g = (const float*)d_in[6];
    const float* ln1_b = (const float*)d_in[7];
    const float* ff_w1 = (const float*)d_in[8];
    const float* ff_b1 = (const float*)d_in[9];
    const float* ff_w2 = (const float*)d_in[10];
    const float* ff_b2 = (const float*)d_in[11];
    const float* ln2_g = (const float*)d_in[12];
    const float* ln2_b = (const float*)d_in[13];
    float* out = (float*)d_out;

    float* pt;
    __half *py, *pqkv, *pff, *pwt;
    cudaGetSymbolAddress((void**)&pt,   g_t);
    cudaGetSymbolAddress((void**)&py,   g_y);
    cudaGetSymbolAddress((void**)&pqkv, g_qkv);
    cudaGetSymbolAddress((void**)&pff,  g_ff);
    cudaGetSymbolAddress((void**)&pwt,  g_wt);

    cudaFuncSetAttribute(mma_gemm, cudaFuncAttributeMaxDynamicSharedMemorySize, SMEM_BYTES);
    cudaFuncSetAttribute(oproj_kernel, cudaFuncAttributeMaxDynamicSharedMemorySize, OP_SMEM);

    wt_cvt_all<<<dim3(192, NLAYERS), dim3(32, 8)>>>(q_w, k_w, v_w, o_w, ff_w1, ff_w2);
    transpose_ln_kernel<<<dim3(NSEQ / 32, BATCH), 256>>>(x, ln1_g, ln1_b);

    for (int l = 0; l < NLAYERS; l++) {
        const __half* wl = pwt + (size_t)l * WT_LAYER;
        // fused QKV GEMM (N=384), fp16 out
        launchPDL(mma_gemm, dim3(QKV_N / GBN, MROWS / GBM), dim3(256), SMEM_BYTES,
                  (const __half*)py, wl, (const float*)nullptr, (void*)pqkv,
                  (const float*)nullptr, (const float*)nullptr, (__half*)nullptr,
                  (int)E, (int)QKV_N, (int)16);
        // ctx partials (split-K over sequence)
        launchPDL(ctx_part_kernel, dim3(BATCH * NHEADS * NCHUNK), dim3(256), 0);
        // fused partial-reduce + attn prologue + o-proj + residual + LN2 -> y
        launchPDL(oproj_kernel, dim3(MROWS / GBM), dim3(256), OP_SMEM,
                  wl + 49152, (const float*)(o_b + l * E),
                  (const float*)(ln2_g + l * E), (const float*)(ln2_b + l * E));
        // FF1 + gelu -> half g_ff
        launchPDL(mma_gemm, dim3(DFF / GBN, MROWS / GBM), dim3(256), SMEM_BYTES,
                  (const __half*)py, wl + 65536, (const float*)(ff_b1 + l * DFF), (void*)pff,
                  (const float*)nullptr, (const float*)nullptr, (__half*)nullptr,
                  (int)E, (int)DFF, (int)(1 | 16));
        // FF2 + residual (+ next-layer LN1 -> y)
        if (l < NLAYERS - 1) {
            launchPDL(mma_gemm, dim3(1, MROWS / GBM), dim3(256), SMEM_BYTES,
                      (const __half*)pff, wl + 131072, (const float*)(ff_b2 + l * E), (void*)pt,
                      (const float*)(ln1_g + (l + 1) * E), (const float*)(ln1_b + (l + 1) * E),
                      py, (int)DFF, (int)E, (int)(2 | 8));
        } else {
            launchPDL(mma_gemm, dim3(1, MROWS / GBM), dim3(256), SMEM_BYTES,
                      (const __half*)pff, wl + 131072, (const float*)(ff_b2 + l * E), (void*)pt,
                      (const float*)nullptr, (const float*)nullptr, (__half*)nullptr,
                      (int)DFF, (int)E, (int)2);
        }
    }

    launchPDL(mean1_kernel, dim3(512), dim3(E), 0);
    launchPDL(mean2_kernel, dim3(BATCH), dim3(E), 0, out);
}

// round 13
// speedup vs baseline: 2.2114x; 1.0241x over previous
#include <cuda_runtime.h>
#include <cuda_fp16.h>
#include <math.h>
#include <stdint.h>

#define BATCH 64
#define E 128
#define NSEQ 1024
#define NHEADS 8
#define DH 16
#define DFF 512
#define MROWS (BATCH * NSEQ)   // 65536
#define NLAYERS 4
#define LN_EPS 1e-5f
#define QKV_N 384
#define NCHUNK 8
#define CHUNK_N (NSEQ / NCHUNK)   // 128

// ---------------- scratch (static device globals; allocation-free) ----------
__device__ float  g_t[MROWS * E];          // residual stream fp32
__device__ __half g_y[MROWS * E];          // layernorm output (fp16)
__device__ __half g_qkv[MROWS * QKV_N];    // fused q|k|v fp16, row stride 384
__device__ float  g_ctxp[BATCH * NHEADS * NCHUNK * 256];  // ctx partials
__device__ float  g_ssum[BATCH * NHEADS * NCHUNK * 16];   // exp-sum partials
__device__ __half g_ff[MROWS * DFF];       // gelu out (fp16)
__device__ float  g_part[512 * E];         // mean partials
#define WT_LAYER 196608
__device__ __half g_wt[NLAYERS * WT_LAYER];

__device__ __forceinline__ float gelu_f(float x) {
    float x3 = x * x * x;
    return 0.5f * x * (1.0f + tanhf(0.7978845608028654f * (x + 0.044715f * x3)));
}

__device__ __forceinline__ void gdc_wait() {
    asm volatile("griddepcontrol.wait;" ::: "memory");
}

#define LDSM4(d0, d1, d2, d3, addr) \
    asm volatile("ldmatrix.sync.aligned.m8n8.x4.shared.b16 {%0,%1,%2,%3}, [%4];" \
                 : "=r"(d0), "=r"(d1), "=r"(d2), "=r"(d3) : "r"(addr))

#define MMA_F16(c, a, b) \
    asm volatile("mma.sync.aligned.m16n8k16.row.col.f32.f16.f16.f32 " \
                 "{%0,%1,%2,%3},{%4,%5,%6,%7},{%8,%9},{%0,%1,%2,%3};" \
                 : "+f"((c)[0]), "+f"((c)[1]), "+f"((c)[2]), "+f"((c)[3]) \
                 : "r"((a)[0]), "r"((a)[1]), "r"((a)[2]), "r"((a)[3]), \
                   "r"((b)[0]), "r"((b)[1]))

__device__ __forceinline__ void cp_async16(uint32_t dst, const void* src) {
    asm volatile("cp.async.cg.shared.global [%0], [%1], 16;" :: "r"(dst), "l"(src));
}
#define CP_COMMIT() asm volatile("cp.async.commit_group;")
#define CP_WAIT0()  asm volatile("cp.async.wait_group 0;")
#define CP_WAIT1()  asm volatile("cp.async.wait_group 1;")

// ---------------- fused transpose + layer-0 LN ------------------------------
__global__ void transpose_ln_kernel(const float* __restrict__ x,
                                    const float* __restrict__ gamma,
                                    const float* __restrict__ beta) {
    __shared__ float tile[32][129];
    int b  = blockIdx.y;
    int n0 = blockIdx.x * 32;
    int tx = threadIdx.x & 31;
    int ty = threadIdx.x >> 5;     // 0..7
#pragma unroll
    for (int e0 = 0; e0 < E; e0 += 32) {
#pragma unroll
        for (int i = 0; i < 32; i += 8)
            tile[tx][e0 + ty + i] =
                x[(size_t)b * E * NSEQ + (size_t)(e0 + ty + i) * NSEQ + n0 + tx];
    }
    __syncthreads();
    int lane = tx, wid = ty;
    float g4[4], b4[4];
#pragma unroll
    for (int j = 0; j < 4; j++) { g4[j] = gamma[lane + 32 * j]; b4[j] = beta[lane + 32 * j]; }
    for (int rr = 0; rr < 4; rr++) {
        int row = wid * 4 + rr;
        size_t grow = (size_t)b * NSEQ + n0 + row;
        float xv[4];
#pragma unroll
        for (int j = 0; j < 4; j++) {
            xv[j] = tile[row][lane + 32 * j];
            g_t[grow * E + lane + 32 * j] = xv[j];
        }
        float s = xv[0] + xv[1] + xv[2] + xv[3];
#pragma unroll
        for (int o = 16; o > 0; o >>= 1) s += __shfl_xor_sync(0xffffffffu, s, o);
        float mu = s * (1.0f / E);
        float s2 = 0.f;
#pragma unroll
        for (int j = 0; j < 4; j++) { float d = xv[j] - mu; s2 += d * d; }
#pragma unroll
        for (int o = 16; o > 0; o >>= 1) s2 += __shfl_xor_sync(0xffffffffu, s2, o);
        float rs = rsqrtf(s2 * (1.0f / E) + LN_EPS);
#pragma unroll
        for (int j = 0; j < 4; j++)
            g_y[grow * E + lane + 32 * j] =
                __float2half_rn((xv[j] - mu) * rs * g4[j] + b4[j]);
    }
}

// ---------------- fused weight convert (ALL layers, one launch), fp16 -------
__global__ void wt_cvt_all(const float* __restrict__ q_w, const float* __restrict__ k_w,
                           const float* __restrict__ v_w, const float* __restrict__ o_w,
                           const float* __restrict__ ff_w1, const float* __restrict__ ff_w2) {
    __shared__ float tile[32][33];
    int l  = blockIdx.y;
    int id = blockIdx.x;
    __half* wl = g_wt + (size_t)l * WT_LAYER;

    const float* src;
    __half* dst;
    int K, N, tn, tk;
    if (id < 64) {
        int m = id >> 4;
        const float* srcs[4] = { q_w, k_w, v_w, o_w };
        src = srcs[m] + (size_t)l * E * E;
        dst = wl + m * 16384;
        K = E; N = E;
        int t = id & 15; tn = t & 3; tk = t >> 2;
    } else if (id < 128) {
        src = ff_w1 + (size_t)l * E * DFF;
        dst = wl + 65536;
        K = E; N = DFF;
        int t = id - 64; tn = t & 15; tk = t >> 4;
    } else {
        src = ff_w2 + (size_t)l * DFF * E;
        dst = wl + 131072;
        K = DFF; N = E;
        int t = id - 128; tn = t & 3; tk = t >> 2;
    }
    int n0 = tn * 32, k0 = tk * 32;
    int tx = threadIdx.x, ty = threadIdx.y;   // (32,8)
#pragma unroll
    for (int i = 0; i < 32; i += 8)
        tile[ty + i][tx] = src[(size_t)(k0 + ty + i) * N + n0 + tx];
    __syncthreads();
#pragma unroll
    for (int i = 0; i < 32; i += 8)
        dst[(size_t)(n0 + ty + i) * K + k0 + tx] = __float2half_rn(tile[tx][ty + i]);
}

// ---------------- generic FP16 GEMM (fp32 accum), pipelined, PDL-aware ------
#define GBM 128
#define GBN 128
#define NSTAGE 3
#define STAGE_BYTES 16384
#define BSMEM_OFF (NSTAGE * STAGE_BYTES)
#define SMEM_BYTES (2 * NSTAGE * STAGE_BYTES)   // 98304

__global__ __launch_bounds__(256, 2) void mma_gemm(
    const __half* __restrict__ A, const __half* __restrict__ Wt,
    const float* __restrict__ bias, void* __restrict__ Cv,
    const float* __restrict__ gamma, const float* __restrict__ beta,
    __half* __restrict__ Y,
    int K, int N, int flags)
{
    extern __shared__ float sm[];
    uint32_t smem_u = (uint32_t)__cvta_generic_to_shared(sm);

    int tid  = threadIdx.x;
    int lane = tid & 31;
    int wid  = tid >> 5;
    int warp_m = wid & 1;
    int warp_n = wid >> 1;
    int bm0 = blockIdx.y * GBM;
    int bn0 = blockIdx.x * GBN;

    int r0 = tid >> 3;
    int c8 = tid & 7;
    uint32_t cxor = (uint32_t)((c8 ^ (r0 & 7)) << 4);

    auto load_A = [&](int s, int k0) {
#pragma unroll
        for (int i = 0; i < 4; i++) {
            int r = r0 + i * 32;
            uint32_t doff = (uint32_t)(r << 7) + cxor;
            cp_async16(smem_u + s * STAGE_BYTES + doff, A + (size_t)(bm0 + r) * K + k0 + c8 * 8);
        }
    };
    auto load_B = [&](int s, int k0) {
#pragma unroll
        for (int i = 0; i < 4; i++) {
            int r = r0 + i * 32;
            uint32_t doff = (uint32_t)(r << 7) + cxor;
            cp_async16(smem_u + BSMEM_OFF + s * STAGE_BYTES + doff, Wt + (size_t)(bn0 + r) * K + k0 + c8 * 8);
        }
    };

    load_B(0, 0); CP_COMMIT();
    gdc_wait();

    int nIter = K >> 6;
    load_A(0, 0); CP_COMMIT();
    if (nIter > 1) { load_A(1, 64); load_B(1, 64); CP_COMMIT(); }

    int sub = lane >> 3;
    int l7  = lane & 7;
    int selA = sub >> 1;
    int rowAoff = ((sub & 1) << 3) + l7;
    int selB = sub & 1;
    int rowBoff = ((sub >> 1) << 3) + l7;

    float acc[4][4][4];
#pragma unroll
    for (int i = 0; i < 4; i++)
#pragma unroll
        for (int j = 0; j < 4; j++)
#pragma unroll
            for (int k = 0; k < 4; k++) acc[i][j][k] = 0.f;

    for (int it = 0; it < nIter; it++) {
        if (it < nIter - 1) CP_WAIT1(); else CP_WAIT0();
        __syncthreads();

        int s = it % NSTAGE;
        uint32_t baseA = smem_u + s * STAGE_BYTES;
        uint32_t baseB = smem_u + BSMEM_OFF + s * STAGE_BYTES;

#pragma unroll
        for (int ks = 0; ks < 4; ks++) {
            int cb = ks * 2;
            uint32_t a[4][4], b[4][2];
#pragma unroll
            for (int mt = 0; mt < 4; mt++) {
                int row = warp_m * 64 + mt * 16 + rowAoff;
                uint32_t addr = baseA + (row << 7) + (uint32_t)(((cb + selA) ^ (row & 7)) << 4);
                LDSM4(a[mt][0], a[mt][1], a[mt][2], a[mt][3], addr);
            }
#pragma unroll
            for (int bt = 0; bt < 2; bt++) {
                int row = warp_n * 32 + bt * 16 + rowBoff;
                uint32_t addr = baseB + (row << 7) + (uint32_t)(((cb + selB) ^ (row & 7)) << 4);
                LDSM4(b[2 * bt][0], b[2 * bt][1], b[2 * bt + 1][0], b[2 * bt + 1][1], addr);
            }
#pragma unroll
            for (int mt = 0; mt < 4; mt++)
#pragma unroll
                for (int nt = 0; nt < 4; nt++)
                    MMA_F16(acc[mt][nt], a[mt], b[nt]);
        }

        if (it + 2 < nIter) {
            load_A((it + 2) % NSTAGE, (it + 2) * 64);
            load_B((it + 2) % NSTAGE, (it + 2) * 64);
            CP_COMMIT();
        }
    }

    int g  = lane >> 2;
    int t4 = lane & 3;
    bool do_ln = (flags & 8) != 0;
    if (do_ln) __syncthreads();

    float* Cf = (float*)Cv;
    __half* Ch = (__half*)Cv;

#pragma unroll
    for (int mt = 0; mt < 4; mt++) {
        int rowl0 = warp_m * 64 + mt * 16 + g;
#pragma unroll
        for (int nt = 0; nt < 4; nt++) {
            int coll = warp_n * 32 + nt * 8 + t4 * 2;
            int col  = bn0 + coll;
            float v[4] = { acc[mt][nt][0], acc[mt][nt][1], acc[mt][nt][2], acc[mt][nt][3] };
            if (bias) {
                float b0 = bias[col], b1 = bias[col + 1];
                v[0] += b0; v[1] += b1; v[2] += b0; v[3] += b1;
            }
            if (flags & 1) {
#pragma unroll
                for (int z = 0; z < 4; z++) v[z] = gelu_f(v[z]);
            }
#pragma unroll
            for (int half2i = 0; half2i < 2; half2i++) {
                int rowl = rowl0 + half2i * 8;
                float f0 = v[half2i * 2], f1 = v[half2i * 2 + 1];
                if (flags & 16) {
                    *(__half2*)(Ch + (size_t)(bm0 + rowl) * N + col) =
                        __halves2half2(__float2half_rn(f0), __float2half_rn(f1));
                } else {
                    float2* p = (float2*)(Cf + (size_t)(bm0 + rowl) * N + col);
                    if (flags & 2) {
                        float2 o = *p;
                        f0 += o.x; f1 += o.y;
                    }
                    *p = make_float2(f0, f1);
                }
                if (do_ln) {
                    sm[rowl * 132 + coll]     = f0;
                    sm[rowl * 132 + coll + 1] = f1;
                }
            }
        }
    }

    if (do_ln) {
        __syncthreads();
        float g4[4], b4[4];
#pragma unroll
        for (int j = 0; j < 4; j++) {
            g4[j] = gamma[lane + 32 * j];
            b4[j] = beta[lane + 32 * j];
        }
        for (int r = 0; r < 16; r++) {
            int row = wid * 16 + r;
            float x[4];
#pragma unroll
            for (int j = 0; j < 4; j++) x[j] = sm[row * 132 + lane + 32 * j];
            float s = x[0] + x[1] + x[2] + x[3];
#pragma unroll
            for (int o = 16; o > 0; o >>= 1) s += __shfl_xor_sync(0xffffffffu, s, o);
            float mu = s * (1.0f / E);
            float s2 = 0.f;
#pragma unroll
            for (int j = 0; j < 4; j++) { float d = x[j] - mu; s2 += d * d; }
#pragma unroll
            for (int o = 16; o > 0; o >>= 1) s2 += __shfl_xor_sync(0xffffffffu, s2, o);
            float rs = rsqrtf(s2 * (1.0f / E) + LN_EPS);
#pragma unroll
            for (int j = 0; j < 4; j++)
                Y[(size_t)(bm0 + row) * E + lane + 32 * j] =
                    __float2half_rn((x[j] - mu) * rs * g4[j] + b4[j]);
        }
    }
}

// ---------------- ctx partial: one 128-row chunk per block ------------------
// grid = BATCH*NHEADS*NCHUNK. Thread (half, d, ep) accumulates over 64 rows,
// e-pair vectorized (float2 v), halves combined in smem.
__global__ void ctx_part_kernel() {
    gdc_wait();
    int blk = blockIdx.x;              // bh*NCHUNK + c
    int bh = blk >> 3, c = blk & 7;
    int b = bh >> 3, h = bh & 7;
    const __half* kbase = g_qkv + (size_t)b * NSEQ * QKV_N + (size_t)c * CHUNK_N * QKV_N + E + h * DH;
    const __half* vbase = kbase + E;
    int tid = threadIdx.x;

    __shared__ float  ks[128][17];
    __shared__ float2 vs2[128][9];
    __shared__ float2 red[2][128];
    __shared__ float  reds[2][16];

    // stage: exp(k) and v (float2 pairs)
    for (int l = tid; l < 128 * 8; l += 256) {
        int nl = l >> 3, c2 = l & 7;
        __half2 k2 = *(const __half2*)(kbase + (size_t)nl * QKV_N + c2 * 2);
        __half2 v2 = *(const __half2*)(vbase + (size_t)nl * QKV_N + c2 * 2);
        float2 kf = __half22float2(k2);
        float2 vf = __half22float2(v2);
        ks[nl][c2 * 2]     = expf(kf.x);
        ks[nl][c2 * 2 + 1] = expf(kf.y);
        vs2[nl][c2] = vf;
    }
    __syncthreads();

    int half = tid >> 7;               // 0..1 (n-split)
    int idx  = tid & 127;
    int d  = idx >> 3;                 // 0..15
    int ep = idx & 7;                  // 0..7 (e pair)
    int n0 = half * 64;

    float ax = 0.f, ay = 0.f, ssum = 0.f;
#pragma unroll 16
    for (int nl = 0; nl < 64; nl++) {
        float kk = ks[n0 + nl][d];
        float2 vv = vs2[n0 + nl][ep];
        ax += kk * vv.x;
        ay += kk * vv.y;
        ssum += kk;
    }
    red[half][idx] = make_float2(ax, ay);
    if (ep == 0) reds[half][d] = ssum;
    __syncthreads();

    if (half == 0) {
        float2 o = red[1][idx];
        g_ctxp[blk * 256 + d * 16 + ep * 2]     = ax + o.x;
        g_ctxp[blk * 256 + d * 16 + ep * 2 + 1] = ay + o.y;
        if (ep == 0) g_ssum[blk * 16 + d] = ssum + reds[1][d];
    }
}

// ---------------- o-proj: partial-reduce + attn prologue + GEMM + LN --------
#define OP_B_OFF 32768
#define OP_CTX_OFF 65536
#define OP_SMEM 73728

__global__ __launch_bounds__(256, 2) void oproj_kernel(
    const __half* __restrict__ Wt, const float* __restrict__ bias,
    const float* __restrict__ gamma, const float* __restrict__ beta)
{
    extern __shared__ float sm[];
    uint32_t smem_u = (uint32_t)__cvta_generic_to_shared(sm);

    int tid  = threadIdx.x;
    int lane = tid & 31;
    int wid  = tid >> 5;
    int warp_m = wid & 1;
    int warp_n = wid >> 1;
    int m0 = blockIdx.x * GBM;
    int b  = m0 >> 10;

    int r0 = tid >> 3;
    int c8 = tid & 7;
    uint32_t cxor = (uint32_t)((c8 ^ (r0 & 7)) << 4);

#pragma unroll
    for (int i = 0; i < 4; i++) {
        int r = r0 + i * 32;
        cp_async16(smem_u + OP_B_OFF + (r << 7) + cxor, Wt + (size_t)r * E + c8 * 8);
    }
    CP_COMMIT();
#pragma unroll
    for (int i = 0; i < 4; i++) {
        int r = r0 + i * 32;
        cp_async16(smem_u + OP_B_OFF + 16384 + (r << 7) + cxor, Wt + (size_t)r * E + 64 + c8 * 8);
    }
    CP_COMMIT();
    gdc_wait();

    // reduce ctx partials into smem: ctx = (Σ_c acc) / (Σ_c ssum)
    float* ctxs = (float*)((char*)sm + OP_CTX_OFF);
    for (int i = tid; i < 2048; i += 256) {
        int h = i >> 8, de = i & 255, d = de >> 4;
        int bh8 = ((b * NHEADS + h) << 3);
        float a = 0.f, ss = 0.f;
#pragma unroll
        for (int c = 0; c < NCHUNK; c++) {
            a  += g_ctxp[(bh8 + c) * 256 + de];
            ss += g_ssum[(bh8 + c) * 16 + d];
        }
        ctxs[i] = a / ss;
    }
    __syncthreads();

    // attention prologue: A[128][128] = f16(softmax_q(q) @ ctx * 0.25)
    {
        int row = tid >> 1, half = tid & 1;
        const __half* qrow = g_qkv + (size_t)(m0 + row) * QKV_N;
#pragma unroll
        for (int hh = 0; hh < 4; hh++) {
            int h = half * 4 + hh;
            float qv[16];
            const __half2* q2 = (const __half2*)(qrow + h * 16);
#pragma unroll
            for (int j = 0; j < 8; j++) {
                float2 t = __half22float2(q2[j]);
                qv[2 * j] = t.x; qv[2 * j + 1] = t.y;
            }
            float mxv = -1e30f;
#pragma unroll
            for (int d = 0; d < 16; d++) mxv = fmaxf(mxv, qv[d]);
            float s = 0.f;
#pragma unroll
            for (int d = 0; d < 16; d++) { qv[d] = expf(qv[d] - mxv); s += qv[d]; }
            float r = 0.25f / s;
            const float* cb = ctxs + h * 256;
#pragma unroll
            for (int e2 = 0; e2 < 16; e2 += 2) {
                float a0 = 0.f, a1 = 0.f;
#pragma unroll
                for (int d = 0; d < 16; d++) {
                    float qq = qv[d];
                    a0 += qq * cb[d * 16 + e2];
                    a1 += qq * cb[d * 16 + e2 + 1];
                }
                int col = h * 16 + e2;
                int t = col >> 6, chunk = (col >> 3) & 7, hi = col & 7;
                uint32_t off = (uint32_t)(t * 16384 + (row << 7) + (((chunk) ^ (row & 7)) << 4) + hi * 2);
                *(__half2*)((char*)sm + off) =
                    __halves2half2(__float2half_rn(a0 * r), __float2half_rn(a1 * r));
            }
        }
    }

    int sub = lane >> 3;
    int l7  = lane & 7;
    int selA = sub >> 1;
    int rowAoff = ((sub & 1) << 3) + l7;
    int selB = sub & 1;
    int rowBoff = ((sub >> 1) << 3) + l7;

    float acc[4][4][4];
#pragma unroll
    for (int i = 0; i < 4; i++)
#pragma unroll
        for (int j = 0; j < 4; j++)
#pragma unroll
            for (int k = 0; k < 4; k++) acc[i][j][k] = 0.f;

    for (int it = 0; it < 2; it++) {
        if (it == 0) CP_WAIT1(); else CP_WAIT0();
        __syncthreads();
        uint32_t baseA = smem_u + it * 16384;
        uint32_t baseB = smem_u + OP_B_OFF + it * 16384;
#pragma unroll
        for (int ks = 0; ks < 4; ks++) {
            int cb = ks * 2;
            uint32_t a[4][4], bb[4][2];
#pragma unroll
            for (int mt = 0; mt < 4; mt++) {
                int row = warp_m * 64 + mt * 16 + rowAoff;
                uint32_t addr = baseA + (row << 7) + (uint32_t)(((cb + selA) ^ (row & 7)) << 4);
                LDSM4(a[mt][0], a[mt][1], a[mt][2], a[mt][3], addr);
            }
#pragma unroll
            for (int bt = 0; bt < 2; bt++) {
                int row = warp_n * 32 + bt * 16 + rowBoff;
                uint32_t addr = baseB + (row << 7) + (uint32_t)(((cb + selB) ^ (row & 7)) << 4);
                LDSM4(bb[2 * bt][0], bb[2 * bt][1], bb[2 * bt + 1][0], bb[2 * bt + 1][1], addr);
            }
#pragma unroll
            for (int mt = 0; mt < 4; mt++)
#pragma unroll
                for (int nt = 0; nt < 4; nt++)
                    MMA_F16(acc[mt][nt], a[mt], bb[nt]);
        }
    }

    int g  = lane >> 2;
    int t4 = lane & 3;
    __syncthreads();
#pragma unroll
    for (int mt = 0; mt < 4; mt++) {
        int rowl0 = warp_m * 64 + mt * 16 + g;
#pragma unroll
        for (int nt = 0; nt < 4; nt++) {
            int col = warp_n * 32 + nt * 8 + t4 * 2;
            float b0 = bias[col], b1 = bias[col + 1];
#pragma unroll
            for (int hf = 0; hf < 2; hf++) {
                int rowl = rowl0 + hf * 8;
                float2* p = (float2*)(g_t + (size_t)(m0 + rowl) * E + col);
                float2 o = *p;
                float f0 = acc[mt][nt][hf * 2]     + b0 + o.x;
                float f1 = acc[mt][nt][hf * 2 + 1] + b1 + o.y;
                *p = make_float2(f0, f1);
                sm[rowl * 132 + col]     = f0;
                sm[rowl * 132 + col + 1] = f1;
            }
        }
    }
    __syncthreads();
    float g4[4], b4[4];
#pragma unroll
    for (int j = 0; j < 4; j++) { g4[j] = gamma[lane + 32 * j]; b4[j] = beta[lane + 32 * j]; }
    for (int rr = 0; rr < 16; rr++) {
        int row = wid * 16 + rr;
        float x[4];
#pragma unroll
        for (int j = 0; j < 4; j++) x[j] = sm[row * 132 + lane + 32 * j];
        float s = x[0] + x[1] + x[2] + x[3];
#pragma unroll
        for (int o = 16; o > 0; o >>= 1) s += __shfl_xor_sync(0xffffffffu, s, o);
        float mu = s * (1.0f / E);
        float s2 = 0.f;
#pragma unroll
        for (int j = 0; j < 4; j++) { float d = x[j] - mu; s2 += d * d; }
#pragma unroll
        for (int o = 16; o > 0; o >>= 1) s2 += __shfl_xor_sync(0xffffffffu, s2, o);
        float rs = rsqrtf(s2 * (1.0f / E) + LN_EPS);
#pragma unroll
        for (int j = 0; j < 4; j++)
            g_y[(size_t)(m0 + row) * E + lane + 32 * j] =
                __float2half_rn((x[j] - mu) * rs * g4[j] + b4[j]);
    }
}

// ---------------- two-stage mean over sequence ------------------------------
__global__ void mean1_kernel() {
    gdc_wait();
    int blk = blockIdx.x;             // b*8 + chunk
    int b = blk >> 3, ch = blk & 7;
    int e = threadIdx.x;
    const float* p = g_t + (size_t)b * NSEQ * E + (size_t)ch * 128 * E + e;
    float s = 0.f;
#pragma unroll 8
    for (int n = 0; n < 128; n++) s += p[(size_t)n * E];
    g_part[blk * E + e] = s;
}

__global__ void mean2_kernel(float* __restrict__ out) {
    gdc_wait();
    int b = blockIdx.x, e = threadIdx.x;
    float s = 0.f;
#pragma unroll
    for (int ch = 0; ch < 8; ch++) s += g_part[(b * 8 + ch) * E + e];
    out[b * E + e] = s * (1.0f / NSEQ);
}

// ---------------- PDL launch helper ------------------------------------------
template <typename F, typename... A>
static inline void launchPDL(F f, dim3 grid, dim3 block, size_t smem, A... args) {
    cudaLaunchConfig_t cfg = {};
    cfg.gridDim = grid;
    cfg.blockDim = block;
    cfg.dynamicSmemBytes = smem;
    cfg.stream = 0;
    cudaLaunchAttribute at[1];
    at[0].id = cudaLaunchAttributeProgrammaticStreamSerialization;
    at[0].val.programmaticStreamSerializationAllowed = 1;
    cfg.attrs = at;
    cfg.numAttrs = 1;
    cudaLaunchKernelEx(&cfg, f, args...);
}

// ---------------- launch -----------------------------------------------------
extern "C" void kernel_launch(void* const* d_in, const int* in_sizes, int n_in,
                              void* d_out, int out_size) {
    const float* x     = (const float*)d_in[0];
    const float* q_w   = (const float*)d_in[1];
    const float* k_w   = (const float*)d_in[2];
    const float* v_w   = (const float*)d_in[3];
    const float* o_w   = (const float*)d_in[4];
    const float* o_b   = (const float*)d_in[5];
    const float* ln1_g = (const float*)d_in[6];
    const float* ln1_b = (const float*)d_in[7];
    const float* ff_w1 = (const float*)d_in[8];
    const float* ff_b1 = (const float*)d_in[9];
    const float* ff_w2 = (const float*)d_in[10];
    const float* ff_b2 = (const float*)d_in[11];
    const float* ln2_g = (const float*)d_in[12];
    const float* ln2_b = (const float*)d_in[13];
    float* out = (float*)d_out;

    float* pt;
    __half *py, *pqkv, *pff, *pwt;
    cudaGetSymbolAddress((void**)&pt,   g_t);
    cudaGetSymbolAddress((void**)&py,   g_y);
    cudaGetSymbolAddress((void**)&pqkv, g_qkv);
    cudaGetSymbolAddress((void**)&pff,  g_ff);
    cudaGetSymbolAddress((void**)&pwt,  g_wt);

    cudaFuncSetAttribute(mma_gemm, cudaFuncAttributeMaxDynamicSharedMemorySize, SMEM_BYTES);
    cudaFuncSetAttribute(oproj_kernel, cudaFuncAttributeMaxDynamicSharedMemorySize, OP_SMEM);

    wt_cvt_all<<<dim3(192, NLAYERS), dim3(32, 8)>>>(q_w, k_w, v_w, o_w, ff_w1, ff_w2);
    transpose_ln_kernel<<<dim3(NSEQ / 32, BATCH), 256>>>(x, ln1_g, ln1_b);

    for (int l = 0; l < NLAYERS; l++) {
        const __half* wl = pwt + (size_t)l * WT_LAYER;
        // fused QKV GEMM (N=384), fp16 out
        launchPDL(mma_gemm, dim3(QKV_N / GBN, MROWS / GBM), dim3(256), SMEM_BYTES,
                  (const __half*)py, wl, (const float*)nullptr, (void*)pqkv,
                  (const float*)nullptr, (const float*)nullptr, (__half*)nullptr,
                  (int)E, (int)QKV_N, (int)16);
        // ctx partials (split-K over sequence, 8 chunks)
        launchPDL(ctx_part_kernel, dim3(BATCH * NHEADS * NCHUNK), dim3(256), 0);
        // fused partial-reduce + attn prologue + o-proj + residual + LN2 -> y
        launchPDL(oproj_kernel, dim3(MROWS / GBM), dim3(256), OP_SMEM,
                  wl + 49152, (const float*)(o_b + l * E),
                  (const float*)(ln2_g + l * E), (const float*)(ln2_b + l * E));
        // FF1 + gelu -> half g_ff
        launchPDL(mma_gemm, dim3(DFF / GBN, MROWS / GBM), dim3(256), SMEM_BYTES,
                  (const __half*)py, wl + 65536, (const float*)(ff_b1 + l * DFF), (void*)pff,
                  (const float*)nullptr, (const float*)nullptr, (__half*)nullptr,
                  (int)E, (int)DFF, (int)(1 | 16));
        // FF2 + residual (+ next-layer LN1 -> y)
        if (l < NLAYERS - 1) {
            launchPDL(mma_gemm, dim3(1, MROWS / GBM), dim3(256), SMEM_BYTES,
                      (const __half*)pff, wl + 131072, (const float*)(ff_b2 + l * E), (void*)pt,
                      (const float*)(ln1_g + (l + 1) * E), (const float*)(ln1_b + (l + 1) * E),
                      py, (int)DFF, (int)E, (int)(2 | 8));
        } else {
            launchPDL(mma_gemm, dim3(1, MROWS / GBM), dim3(256), SMEM_BYTES,
                      (const __half*)pff, wl + 131072, (const float*)(ff_b2 + l * E), (void*)pt,
                      (const float*)nullptr, (const float*)nullptr, (__half*)nullptr,
                      (int)DFF, (int)E, (int)2);
        }
    }

    launchPDL(mean1_kernel, dim3(512), dim3(E), 0);
    launchPDL(mean2_kernel, dim3(BATCH), dim3(E), 0, out);
}

// round 14
// speedup vs baseline: 2.2383x; 1.0121x over previous
#include <cuda_runtime.h>
#include <cuda_fp16.h>
#include <math.h>
#include <stdint.h>

#define BATCH 64
#define E 128
#define NSEQ 1024
#define NHEADS 8
#define DH 16
#define DFF 512
#define MROWS (BATCH * NSEQ)   // 65536
#define NLAYERS 4
#define LN_EPS 1e-5f
#define QKV_N 384
#define NCHUNK 8
#define CHUNK_N (NSEQ / NCHUNK)   // 128

// ---------------- scratch (static device globals; allocation-free) ----------
__device__ float  g_t[MROWS * E];          // residual stream fp32
__device__ __half g_y[MROWS * E];          // layernorm output (fp16)
__device__ __half g_qkv[MROWS * QKV_N];    // fused q|k|v fp16, row stride 384
__device__ float  g_ctxp[BATCH * NHEADS * NCHUNK * 256];  // ctx partials
__device__ float  g_ssum[BATCH * NHEADS * NCHUNK * 16];   // exp-sum partials
__device__ __half g_ff[MROWS * DFF];       // gelu out (fp16)
__device__ float  g_part[512 * E];         // mean partials
#define WT_LAYER 196608
__device__ __half g_wt[NLAYERS * WT_LAYER];

__device__ __forceinline__ float gelu_f(float x) {
    float x3 = x * x * x;
    return 0.5f * x * (1.0f + tanhf(0.7978845608028654f * (x + 0.044715f * x3)));
}

__device__ __forceinline__ void gdc_wait() {
    asm volatile("griddepcontrol.wait;" ::: "memory");
}

#define LDSM4(d0, d1, d2, d3, addr) \
    asm volatile("ldmatrix.sync.aligned.m8n8.x4.shared.b16 {%0,%1,%2,%3}, [%4];" \
                 : "=r"(d0), "=r"(d1), "=r"(d2), "=r"(d3) : "r"(addr))

#define MMA_F16(c, a, b) \
    asm volatile("mma.sync.aligned.m16n8k16.row.col.f32.f16.f16.f32 " \
                 "{%0,%1,%2,%3},{%4,%5,%6,%7},{%8,%9},{%0,%1,%2,%3};" \
                 : "+f"((c)[0]), "+f"((c)[1]), "+f"((c)[2]), "+f"((c)[3]) \
                 : "r"((a)[0]), "r"((a)[1]), "r"((a)[2]), "r"((a)[3]), \
                   "r"((b)[0]), "r"((b)[1]))

__device__ __forceinline__ void cp_async16(uint32_t dst, const void* src) {
    asm volatile("cp.async.cg.shared.global [%0], [%1], 16;" :: "r"(dst), "l"(src));
}
#define CP_COMMIT() asm volatile("cp.async.commit_group;")
#define CP_WAIT0()  asm volatile("cp.async.wait_group 0;")
#define CP_WAIT1()  asm volatile("cp.async.wait_group 1;")

// ---------------- fused transpose + layer-0 LN ------------------------------
__global__ void transpose_ln_kernel(const float* __restrict__ x,
                                    const float* __restrict__ gamma,
                                    const float* __restrict__ beta) {
    __shared__ float tile[32][129];
    int b  = blockIdx.y;
    int n0 = blockIdx.x * 32;
    int tx = threadIdx.x & 31;
    int ty = threadIdx.x >> 5;     // 0..7
#pragma unroll
    for (int e0 = 0; e0 < E; e0 += 32) {
#pragma unroll
        for (int i = 0; i < 32; i += 8)
            tile[tx][e0 + ty + i] =
                x[(size_t)b * E * NSEQ + (size_t)(e0 + ty + i) * NSEQ + n0 + tx];
    }
    __syncthreads();
    int lane = tx, wid = ty;
    float g4[4], b4[4];
#pragma unroll
    for (int j = 0; j < 4; j++) { g4[j] = gamma[lane + 32 * j]; b4[j] = beta[lane + 32 * j]; }
    for (int rr = 0; rr < 4; rr++) {
        int row = wid * 4 + rr;
        size_t grow = (size_t)b * NSEQ + n0 + row;
        float xv[4];
#pragma unroll
        for (int j = 0; j < 4; j++) {
            xv[j] = tile[row][lane + 32 * j];
            g_t[grow * E + lane + 32 * j] = xv[j];
        }
        float s = xv[0] + xv[1] + xv[2] + xv[3];
#pragma unroll
        for (int o = 16; o > 0; o >>= 1) s += __shfl_xor_sync(0xffffffffu, s, o);
        float mu = s * (1.0f / E);
        float s2 = 0.f;
#pragma unroll
        for (int j = 0; j < 4; j++) { float d = xv[j] - mu; s2 += d * d; }
#pragma unroll
        for (int o = 16; o > 0; o >>= 1) s2 += __shfl_xor_sync(0xffffffffu, s2, o);
        float rs = rsqrtf(s2 * (1.0f / E) + LN_EPS);
#pragma unroll
        for (int j = 0; j < 4; j++)
            g_y[grow * E + lane + 32 * j] =
                __float2half_rn((xv[j] - mu) * rs * g4[j] + b4[j]);
    }
}

// ---------------- fused weight convert (ALL layers, one launch), fp16 -------
__global__ void wt_cvt_all(const float* __restrict__ q_w, const float* __restrict__ k_w,
                           const float* __restrict__ v_w, const float* __restrict__ o_w,
                           const float* __restrict__ ff_w1, const float* __restrict__ ff_w2) {
    __shared__ float tile[32][33];
    int l  = blockIdx.y;
    int id = blockIdx.x;
    __half* wl = g_wt + (size_t)l * WT_LAYER;

    const float* src;
    __half* dst;
    int K, N, tn, tk;
    if (id < 64) {
        int m = id >> 4;
        const float* srcs[4] = { q_w, k_w, v_w, o_w };
        src = srcs[m] + (size_t)l * E * E;
        dst = wl + m * 16384;
        K = E; N = E;
        int t = id & 15; tn = t & 3; tk = t >> 2;
    } else if (id < 128) {
        src = ff_w1 + (size_t)l * E * DFF;
        dst = wl + 65536;
        K = E; N = DFF;
        int t = id - 64; tn = t & 15; tk = t >> 4;
    } else {
        src = ff_w2 + (size_t)l * DFF * E;
        dst = wl + 131072;
        K = DFF; N = E;
        int t = id - 128; tn = t & 3; tk = t >> 2;
    }
    int n0 = tn * 32, k0 = tk * 32;
    int tx = threadIdx.x, ty = threadIdx.y;   // (32,8)
#pragma unroll
    for (int i = 0; i < 32; i += 8)
        tile[ty + i][tx] = src[(size_t)(k0 + ty + i) * N + n0 + tx];
    __syncthreads();
#pragma unroll
    for (int i = 0; i < 32; i += 8)
        dst[(size_t)(n0 + ty + i) * K + k0 + tx] = __float2half_rn(tile[tx][ty + i]);
}

// ---------------- generic FP16 GEMM (fp32 accum), pipelined, PDL-aware ------
#define GBM 128
#define GBN 128
#define NSTAGE 3
#define STAGE_BYTES 16384
#define BSMEM_OFF (NSTAGE * STAGE_BYTES)
#define SMEM_BYTES (2 * NSTAGE * STAGE_BYTES)   // 98304

__global__ __launch_bounds__(256, 2) void mma_gemm(
    const __half* __restrict__ A, const __half* __restrict__ Wt,
    const float* __restrict__ bias, void* __restrict__ Cv,
    const float* __restrict__ gamma, const float* __restrict__ beta,
    __half* __restrict__ Y,
    int K, int N, int flags)
{
    extern __shared__ float sm[];
    uint32_t smem_u = (uint32_t)__cvta_generic_to_shared(sm);

    int tid  = threadIdx.x;
    int lane = tid & 31;
    int wid  = tid >> 5;
    int warp_m = wid & 1;
    int warp_n = wid >> 1;
    int bm0 = blockIdx.y * GBM;
    int bn0 = blockIdx.x * GBN;

    int r0 = tid >> 3;
    int c8 = tid & 7;
    uint32_t cxor = (uint32_t)((c8 ^ (r0 & 7)) << 4);

    auto load_A = [&](int s, int k0) {
#pragma unroll
        for (int i = 0; i < 4; i++) {
            int r = r0 + i * 32;
            uint32_t doff = (uint32_t)(r << 7) + cxor;
            cp_async16(smem_u + s * STAGE_BYTES + doff, A + (size_t)(bm0 + r) * K + k0 + c8 * 8);
        }
    };
    auto load_B = [&](int s, int k0) {
#pragma unroll
        for (int i = 0; i < 4; i++) {
            int r = r0 + i * 32;
            uint32_t doff = (uint32_t)(r << 7) + cxor;
            cp_async16(smem_u + BSMEM_OFF + s * STAGE_BYTES + doff, Wt + (size_t)(bn0 + r) * K + k0 + c8 * 8);
        }
    };

    load_B(0, 0); CP_COMMIT();
    gdc_wait();

    int nIter = K >> 6;
    load_A(0, 0); CP_COMMIT();
    if (nIter > 1) { load_A(1, 64); load_B(1, 64); CP_COMMIT(); }

    int sub = lane >> 3;
    int l7  = lane & 7;
    int selA = sub >> 1;
    int rowAoff = ((sub & 1) << 3) + l7;
    int selB = sub & 1;
    int rowBoff = ((sub >> 1) << 3) + l7;

    float acc[4][4][4];
#pragma unroll
    for (int i = 0; i < 4; i++)
#pragma unroll
        for (int j = 0; j < 4; j++)
#pragma unroll
            for (int k = 0; k < 4; k++) acc[i][j][k] = 0.f;

    for (int it = 0; it < nIter; it++) {
        if (it < nIter - 1) CP_WAIT1(); else CP_WAIT0();
        __syncthreads();

        int s = it % NSTAGE;
        uint32_t baseA = smem_u + s * STAGE_BYTES;
        uint32_t baseB = smem_u + BSMEM_OFF + s * STAGE_BYTES;

#pragma unroll
        for (int ks = 0; ks < 4; ks++) {
            int cb = ks * 2;
            uint32_t a[4][4], b[4][2];
#pragma unroll
            for (int mt = 0; mt < 4; mt++) {
                int row = warp_m * 64 + mt * 16 + rowAoff;
                uint32_t addr = baseA + (row << 7) + (uint32_t)(((cb + selA) ^ (row & 7)) << 4);
                LDSM4(a[mt][0], a[mt][1], a[mt][2], a[mt][3], addr);
            }
#pragma unroll
            for (int bt = 0; bt < 2; bt++) {
                int row = warp_n * 32 + bt * 16 + rowBoff;
                uint32_t addr = baseB + (row << 7) + (uint32_t)(((cb + selB) ^ (row & 7)) << 4);
                LDSM4(b[2 * bt][0], b[2 * bt][1], b[2 * bt + 1][0], b[2 * bt + 1][1], addr);
            }
#pragma unroll
            for (int mt = 0; mt < 4; mt++)
#pragma unroll
                for (int nt = 0; nt < 4; nt++)
                    MMA_F16(acc[mt][nt], a[mt], b[nt]);
        }

        if (it + 2 < nIter) {
            load_A((it + 2) % NSTAGE, (it + 2) * 64);
            load_B((it + 2) % NSTAGE, (it + 2) * 64);
            CP_COMMIT();
        }
    }

    int g  = lane >> 2;
    int t4 = lane & 3;
    bool do_ln = (flags & 8) != 0;
    if (do_ln) __syncthreads();

    float* Cf = (float*)Cv;
    __half* Ch = (__half*)Cv;

#pragma unroll
    for (int mt = 0; mt < 4; mt++) {
        int rowl0 = warp_m * 64 + mt * 16 + g;
#pragma unroll
        for (int nt = 0; nt < 4; nt++) {
            int coll = warp_n * 32 + nt * 8 + t4 * 2;
            int col  = bn0 + coll;
            float v[4] = { acc[mt][nt][0], acc[mt][nt][1], acc[mt][nt][2], acc[mt][nt][3] };
            if (bias) {
                float b0 = bias[col], b1 = bias[col + 1];
                v[0] += b0; v[1] += b1; v[2] += b0; v[3] += b1;
            }
            if (flags & 1) {
#pragma unroll
                for (int z = 0; z < 4; z++) v[z] = gelu_f(v[z]);
            }
#pragma unroll
            for (int half2i = 0; half2i < 2; half2i++) {
                int rowl = rowl0 + half2i * 8;
                float f0 = v[half2i * 2], f1 = v[half2i * 2 + 1];
                if (flags & 16) {
                    *(__half2*)(Ch + (size_t)(bm0 + rowl) * N + col) =
                        __halves2half2(__float2half_rn(f0), __float2half_rn(f1));
                } else {
                    float2* p = (float2*)(Cf + (size_t)(bm0 + rowl) * N + col);
                    if (flags & 2) {
                        float2 o = *p;
                        f0 += o.x; f1 += o.y;
                    }
                    *p = make_float2(f0, f1);
                }
                if (do_ln) {
                    sm[rowl * 132 + coll]     = f0;
                    sm[rowl * 132 + coll + 1] = f1;
                }
            }
        }
    }

    if (do_ln) {
        __syncthreads();
        float g4[4], b4[4];
#pragma unroll
        for (int j = 0; j < 4; j++) {
            g4[j] = gamma[lane + 32 * j];
            b4[j] = beta[lane + 32 * j];
        }
        for (int r = 0; r < 16; r++) {
            int row = wid * 16 + r;
            float x[4];
#pragma unroll
            for (int j = 0; j < 4; j++) x[j] = sm[row * 132 + lane + 32 * j];
            float s = x[0] + x[1] + x[2] + x[3];
#pragma unroll
            for (int o = 16; o > 0; o >>= 1) s += __shfl_xor_sync(0xffffffffu, s, o);
            float mu = s * (1.0f / E);
            float s2 = 0.f;
#pragma unroll
            for (int j = 0; j < 4; j++) { float d = x[j] - mu; s2 += d * d; }
#pragma unroll
            for (int o = 16; o > 0; o >>= 1) s2 += __shfl_xor_sync(0xffffffffu, s2, o);
            float rs = rsqrtf(s2 * (1.0f / E) + LN_EPS);
#pragma unroll
            for (int j = 0; j < 4; j++)
                Y[(size_t)(bm0 + row) * E + lane + 32 * j] =
                    __float2half_rn((x[j] - mu) * rs * g4[j] + b4[j]);
        }
    }
}

// ---------------- ctx partial: one 128-row chunk per block ------------------
// Thread (ns, d, eq): 4-way n-split, e-quad (float4 v), 32 rows each.
__global__ void ctx_part_kernel() {
    gdc_wait();
    int blk = blockIdx.x;              // bh*NCHUNK + c
    int bh = blk >> 3, c = blk & 7;
    int b = bh >> 3, h = bh & 7;
    const __half* kbase = g_qkv + (size_t)b * NSEQ * QKV_N + (size_t)c * CHUNK_N * QKV_N + E + h * DH;
    const __half* vbase = kbase + E;
    int tid = threadIdx.x;

    __shared__ float  ks[128][17];
    __shared__ float4 vs4[128][5];     // 4 quads + pad
    __shared__ float4 red[4][64];
    __shared__ float  reds[4][16];

    // stage: exp(k) and v
    for (int l = tid; l < 128 * 8; l += 256) {
        int nl = l >> 3, c2 = l & 7;
        __half2 k2 = *(const __half2*)(kbase + (size_t)nl * QKV_N + c2 * 2);
        __half2 v2 = *(const __half2*)(vbase + (size_t)nl * QKV_N + c2 * 2);
        float2 kf = __half22float2(k2);
        float2 vf = __half22float2(v2);
        ks[nl][c2 * 2]     = expf(kf.x);
        ks[nl][c2 * 2 + 1] = expf(kf.y);
        float* vq = (float*)&vs4[nl][c2 >> 1];
        vq[(c2 & 1) * 2]     = vf.x;
        vq[(c2 & 1) * 2 + 1] = vf.y;
    }
    __syncthreads();

    int ns  = tid >> 6;                // 0..3 (n-split)
    int idx = tid & 63;
    int d  = idx >> 2;                 // 0..15
    int eq = idx & 3;                  // 0..3 (e quad)
    int n0 = ns * 32;

    float a0 = 0.f, a1 = 0.f, a2 = 0.f, a3 = 0.f, ssum = 0.f;
#pragma unroll 16
    for (int nl = 0; nl < 32; nl++) {
        float kk = ks[n0 + nl][d];
        float4 vv = vs4[n0 + nl][eq];
        a0 += kk * vv.x;
        a1 += kk * vv.y;
        a2 += kk * vv.z;
        a3 += kk * vv.w;
        ssum += kk;
    }
    red[ns][idx] = make_float4(a0, a1, a2, a3);
    if (eq == 0) reds[ns][d] = ssum;
    __syncthreads();

    if (ns == 0) {
#pragma unroll
        for (int s = 1; s < 4; s++) {
            float4 o = red[s][idx];
            a0 += o.x; a1 += o.y; a2 += o.z; a3 += o.w;
        }
        float* dst = g_ctxp + blk * 256 + d * 16 + eq * 4;
        dst[0] = a0; dst[1] = a1; dst[2] = a2; dst[3] = a3;
        if (eq == 0) {
            float ss = ssum;
#pragma unroll
            for (int s = 1; s < 4; s++) ss += reds[s][d];
            g_ssum[blk * 16 + d] = ss;
        }
    }
}

// ---------------- o-proj: partial-reduce + attn prologue + GEMM + LN --------
#define OP_B_OFF 32768
#define OP_CTX_OFF 65536
#define OP_SMEM 73728

__global__ __launch_bounds__(256, 2) void oproj_kernel(
    const __half* __restrict__ Wt, const float* __restrict__ bias,
    const float* __restrict__ gamma, const float* __restrict__ beta)
{
    extern __shared__ float sm[];
    uint32_t smem_u = (uint32_t)__cvta_generic_to_shared(sm);

    int tid  = threadIdx.x;
    int lane = tid & 31;
    int wid  = tid >> 5;
    int warp_m = wid & 1;
    int warp_n = wid >> 1;
    int m0 = blockIdx.x * GBM;
    int b  = m0 >> 10;

    int r0 = tid >> 3;
    int c8 = tid & 7;
    uint32_t cxor = (uint32_t)((c8 ^ (r0 & 7)) << 4);

#pragma unroll
    for (int i = 0; i < 4; i++) {
        int r = r0 + i * 32;
        cp_async16(smem_u + OP_B_OFF + (r << 7) + cxor, Wt + (size_t)r * E + c8 * 8);
    }
    CP_COMMIT();
#pragma unroll
    for (int i = 0; i < 4; i++) {
        int r = r0 + i * 32;
        cp_async16(smem_u + OP_B_OFF + 16384 + (r << 7) + cxor, Wt + (size_t)r * E + 64 + c8 * 8);
    }
    CP_COMMIT();
    gdc_wait();

    // reduce ctx partials into smem: ctx = (Σ_c acc) / (Σ_c ssum)
    float* ctxs = (float*)((char*)sm + OP_CTX_OFF);
    for (int i = tid; i < 2048; i += 256) {
        int h = i >> 8, de = i & 255, d = de >> 4;
        int bh8 = ((b * NHEADS + h) << 3);
        float a = 0.f, ss = 0.f;
#pragma unroll
        for (int c = 0; c < NCHUNK; c++) {
            a  += g_ctxp[(bh8 + c) * 256 + de];
            ss += g_ssum[(bh8 + c) * 16 + d];
        }
        ctxs[i] = a / ss;
    }
    __syncthreads();

    // attention prologue: A[128][128] = f16(softmax_q(q) @ ctx * 0.25)
    {
        int row = tid >> 1, half = tid & 1;
        const __half* qrow = g_qkv + (size_t)(m0 + row) * QKV_N;
#pragma unroll
        for (int hh = 0; hh < 4; hh++) {
            int h = half * 4 + hh;
            float qv[16];
            const __half2* q2 = (const __half2*)(qrow + h * 16);
#pragma unroll
            for (int j = 0; j < 8; j++) {
                float2 t = __half22float2(q2[j]);
                qv[2 * j] = t.x; qv[2 * j + 1] = t.y;
            }
            float mxv = -1e30f;
#pragma unroll
            for (int d = 0; d < 16; d++) mxv = fmaxf(mxv, qv[d]);
            float s = 0.f;
#pragma unroll
            for (int d = 0; d < 16; d++) { qv[d] = expf(qv[d] - mxv); s += qv[d]; }
            float r = 0.25f / s;
            const float* cb = ctxs + h * 256;
#pragma unroll
            for (int e2 = 0; e2 < 16; e2 += 2) {
                float a0 = 0.f, a1 = 0.f;
#pragma unroll
                for (int d = 0; d < 16; d++) {
                    float qq = qv[d];
                    a0 += qq * cb[d * 16 + e2];
                    a1 += qq * cb[d * 16 + e2 + 1];
                }
                int col = h * 16 + e2;
                int t = col >> 6, chunk = (col >> 3) & 7, hi = col & 7;
                uint32_t off = (uint32_t)(t * 16384 + (row << 7) + (((chunk) ^ (row & 7)) << 4) + hi * 2);
                *(__half2*)((char*)sm + off) =
                    __halves2half2(__float2half_rn(a0 * r), __float2half_rn(a1 * r));
            }
        }
    }

    int sub = lane >> 3;
    int l7  = lane & 7;
    int selA = sub >> 1;
    int rowAoff = ((sub & 1) << 3) + l7;
    int selB = sub & 1;
    int rowBoff = ((sub >> 1) << 3) + l7;

    float acc[4][4][4];
#pragma unroll
    for (int i = 0; i < 4; i++)
#pragma unroll
        for (int j = 0; j < 4; j++)
#pragma unroll
            for (int k = 0; k < 4; k++) acc[i][j][k] = 0.f;

    for (int it = 0; it < 2; it++) {
        if (it == 0) CP_WAIT1(); else CP_WAIT0();
        __syncthreads();
        uint32_t baseA = smem_u + it * 16384;
        uint32_t baseB = smem_u + OP_B_OFF + it * 16384;
#pragma unroll
        for (int ks = 0; ks < 4; ks++) {
            int cb = ks * 2;
            uint32_t a[4][4], bb[4][2];
#pragma unroll
            for (int mt = 0; mt < 4; mt++) {
                int row = warp_m * 64 + mt * 16 + rowAoff;
                uint32_t addr = baseA + (row << 7) + (uint32_t)(((cb + selA) ^ (row & 7)) << 4);
                LDSM4(a[mt][0], a[mt][1], a[mt][2], a[mt][3], addr);
            }
#pragma unroll
            for (int bt = 0; bt < 2; bt++) {
                int row = warp_n * 32 + bt * 16 + rowBoff;
                uint32_t addr = baseB + (row << 7) + (uint32_t)(((cb + selB) ^ (row & 7)) << 4);
                LDSM4(bb[2 * bt][0], bb[2 * bt][1], bb[2 * bt + 1][0], bb[2 * bt + 1][1], addr);
            }
#pragma unroll
            for (int mt = 0; mt < 4; mt++)
#pragma unroll
                for (int nt = 0; nt < 4; nt++)
                    MMA_F16(acc[mt][nt], a[mt], bb[nt]);
        }
    }

    int g  = lane >> 2;
    int t4 = lane & 3;
    __syncthreads();
#pragma unroll
    for (int mt = 0; mt < 4; mt++) {
        int rowl0 = warp_m * 64 + mt * 16 + g;
#pragma unroll
        for (int nt = 0; nt < 4; nt++) {
            int col = warp_n * 32 + nt * 8 + t4 * 2;
            float b0 = bias[col], b1 = bias[col + 1];
#pragma unroll
            for (int hf = 0; hf < 2; hf++) {
                int rowl = rowl0 + hf * 8;
                float2* p = (float2*)(g_t + (size_t)(m0 + rowl) * E + col);
                float2 o = *p;
                float f0 = acc[mt][nt][hf * 2]     + b0 + o.x;
                float f1 = acc[mt][nt][hf * 2 + 1] + b1 + o.y;
                *p = make_float2(f0, f1);
                sm[rowl * 132 + col]     = f0;
                sm[rowl * 132 + col + 1] = f1;
            }
        }
    }
    __syncthreads();
    float g4[4], b4[4];
#pragma unroll
    for (int j = 0; j < 4; j++) { g4[j] = gamma[lane + 32 * j]; b4[j] = beta[lane + 32 * j]; }
    for (int rr = 0; rr < 16; rr++) {
        int row = wid * 16 + rr;
        float x[4];
#pragma unroll
        for (int j = 0; j < 4; j++) x[j] = sm[row * 132 + lane + 32 * j];
        float s = x[0] + x[1] + x[2] + x[3];
#pragma unroll
        for (int o = 16; o > 0; o >>= 1) s += __shfl_xor_sync(0xffffffffu, s, o);
        float mu = s * (1.0f / E);
        float s2 = 0.f;
#pragma unroll
        for (int j = 0; j < 4; j++) { float d = x[j] - mu; s2 += d * d; }
#pragma unroll
        for (int o = 16; o > 0; o >>= 1) s2 += __shfl_xor_sync(0xffffffffu, s2, o);
        float rs = rsqrtf(s2 * (1.0f / E) + LN_EPS);
#pragma unroll
        for (int j = 0; j < 4; j++)
            g_y[(size_t)(m0 + row) * E + lane + 32 * j] =
                __float2half_rn((x[j] - mu) * rs * g4[j] + b4[j]);
    }
}

// ---------------- two-stage mean over sequence ------------------------------
__global__ void mean1_kernel() {
    gdc_wait();
    int blk = blockIdx.x;             // b*8 + chunk
    int b = blk >> 3, ch = blk & 7;
    int e = threadIdx.x;
    const float* p = g_t + (size_t)b * NSEQ * E + (size_t)ch * 128 * E + e;
    float s = 0.f;
#pragma unroll 8
    for (int n = 0; n < 128; n++) s += p[(size_t)n * E];
    g_part[blk * E + e] = s;
}

__global__ void mean2_kernel(float* __restrict__ out) {
    gdc_wait();
    int b = blockIdx.x, e = threadIdx.x;
    float s = 0.f;
#pragma unroll
    for (int ch = 0; ch < 8; ch++) s += g_part[(b * 8 + ch) * E + e];
    out[b * E + e] = s * (1.0f / NSEQ);
}

// ---------------- PDL launch helper ------------------------------------------
template <typename F, typename... A>
static inline void launchPDL(F f, dim3 grid, dim3 block, size_t smem, A... args) {
    cudaLaunchConfig_t cfg = {};
    cfg.gridDim = grid;
    cfg.blockDim = block;
    cfg.dynamicSmemBytes = smem;
    cfg.stream = 0;
    cudaLaunchAttribute at[1];
    at[0].id = cudaLaunchAttributeProgrammaticStreamSerialization;
    at[0].val.programmaticStreamSerializationAllowed = 1;
    cfg.attrs = at;
    cfg.numAttrs = 1;
    cudaLaunchKernelEx(&cfg, f, args...);
}

// ---------------- launch -----------------------------------------------------
extern "C" void kernel_launch(void* const* d_in, const int* in_sizes, int n_in,
                              void* d_out, int out_size) {
    const float* x     = (const float*)d_in[0];
    const float* q_w   = (const float*)d_in[1];
    const float* k_w   = (const float*)d_in[2];
    const float* v_w   = (const float*)d_in[3];
    const float* o_w   = (const float*)d_in[4];
    const float* o_b   = (const float*)d_in[5];
    const float* ln1_g = (const float*)d_in[6];
    const float* ln1_b = (const float*)d_in[7];
    const float* ff_w1 = (const float*)d_in[8];
    const float* ff_b1 = (const float*)d_in[9];
    const float* ff_w2 = (const float*)d_in[10];
    const float* ff_b2 = (const float*)d_in[11];
    const float* ln2_g = (const float*)d_in[12];
    const float* ln2_b = (const float*)d_in[13];
    float* out = (float*)d_out;

    float* pt;
    __half *py, *pqkv, *pff, *pwt;
    cudaGetSymbolAddress((void**)&pt,   g_t);
    cudaGetSymbolAddress((void**)&py,   g_y);
    cudaGetSymbolAddress((void**)&pqkv, g_qkv);
    cudaGetSymbolAddress((void**)&pff,  g_ff);
    cudaGetSymbolAddress((void**)&pwt,  g_wt);

    cudaFuncSetAttribute(mma_gemm, cudaFuncAttributeMaxDynamicSharedMemorySize, SMEM_BYTES);
    cudaFuncSetAttribute(oproj_kernel, cudaFuncAttributeMaxDynamicSharedMemorySize, OP_SMEM);

    wt_cvt_all<<<dim3(192, NLAYERS), dim3(32, 8)>>>(q_w, k_w, v_w, o_w, ff_w1, ff_w2);
    transpose_ln_kernel<<<dim3(NSEQ / 32, BATCH), 256>>>(x, ln1_g, ln1_b);

    for (int l = 0; l < NLAYERS; l++) {
        const __half* wl = pwt + (size_t)l * WT_LAYER;
        launchPDL(mma_gemm, dim3(QKV_N / GBN, MROWS / GBM), dim3(256), SMEM_BYTES,
                  (const __half*)py, wl, (const float*)nullptr, (void*)pqkv,
                  (const float*)nullptr, (const float*)nullptr, (__half*)nullptr,
                  (int)E, (int)QKV_N, (int)16);
        launchPDL(ctx_part_kernel, dim3(BATCH * NHEADS * NCHUNK), dim3(256), 0);
        launchPDL(oproj_kernel, dim3(MROWS / GBM), dim3(256), OP_SMEM,
                  wl + 49152, (const float*)(o_b + l * E),
                  (const float*)(ln2_g + l * E), (const float*)(ln2_b + l * E));
        launchPDL(mma_gemm, dim3(DFF / GBN, MROWS / GBM), dim3(256), SMEM_BYTES,
                  (const __half*)py, wl + 65536, (const float*)(ff_b1 + l * DFF), (void*)pff,
                  (const float*)nullptr, (const float*)nullptr, (__half*)nullptr,
                  (int)E, (int)DFF, (int)(1 | 16));
        if (l < NLAYERS - 1) {
            launchPDL(mma_gemm, dim3(1, MROWS / GBM), dim3(256), SMEM_BYTES,
                      (const __half*)pff, wl + 131072, (const float*)(ff_b2 + l * E), (void*)pt,
                      (const float*)(ln1_g + (l + 1) * E), (const float*)(ln1_b + (l + 1) * E),
                      py, (int)DFF, (int)E, (int)(2 | 8));
        } else {
            launchPDL(mma_gemm, dim3(1, MROWS / GBM), dim3(256), SMEM_BYTES,
                      (const __half*)pff, wl + 131072, (const float*)(ff_b2 + l * E), (void*)pt,
                      (const float*)nullptr, (const float*)nullptr, (__half*)nullptr,
                      (int)DFF, (int)E, (int)2);
        }
    }

    launchPDL(mean1_kernel, dim3(512), dim3(E), 0);
    launchPDL(mean2_kernel, dim3(BATCH), dim3(E), 0, out);
}

// round 15
// speedup vs baseline: 2.2428x; 1.0020x over previous
#include <cuda_runtime.h>
#include <cuda_fp16.h>
#include <math.h>
#include <stdint.h>

#define BATCH 64
#define E 128
#define NSEQ 1024
#define NHEADS 8
#define DH 16
#define DFF 512
#define MROWS (BATCH * NSEQ)   // 65536
#define NLAYERS 4
#define LN_EPS 1e-5f
#define QKV_N 384
#define NCHUNK 8
#define CHUNK_N (NSEQ / NCHUNK)   // 128

// ---------------- scratch (static device globals; allocation-free) ----------
__device__ float  g_t[MROWS * E];          // residual stream fp32
__device__ __half g_y[MROWS * E];          // layernorm output (fp16)
__device__ __half g_qkv[MROWS * QKV_N];    // fused q|k|v fp16, row stride 384
__device__ float  g_ctxp[BATCH * NHEADS * NCHUNK * 256];  // ctx partials
__device__ float  g_ssum[BATCH * NHEADS * NCHUNK * 16];   // exp-sum partials
__device__ __half g_ff[MROWS * DFF];       // gelu out (fp16)
__device__ float  g_part[512 * E];         // mean partials
#define WT_LAYER 196608
__device__ __half g_wt[NLAYERS * WT_LAYER];

__device__ __forceinline__ float gelu_f(float x) {
    float x3 = x * x * x;
    return 0.5f * x * (1.0f + tanhf(0.7978845608028654f * (x + 0.044715f * x3)));
}

__device__ __forceinline__ void gdc_wait() {
    asm volatile("griddepcontrol.wait;" ::: "memory");
}

#define LDSM4(d0, d1, d2, d3, addr) \
    asm volatile("ldmatrix.sync.aligned.m8n8.x4.shared.b16 {%0,%1,%2,%3}, [%4];" \
                 : "=r"(d0), "=r"(d1), "=r"(d2), "=r"(d3) : "r"(addr))

#define MMA_F16(c, a, b) \
    asm volatile("mma.sync.aligned.m16n8k16.row.col.f32.f16.f16.f32 " \
                 "{%0,%1,%2,%3},{%4,%5,%6,%7},{%8,%9},{%0,%1,%2,%3};" \
                 : "+f"((c)[0]), "+f"((c)[1]), "+f"((c)[2]), "+f"((c)[3]) \
                 : "r"((a)[0]), "r"((a)[1]), "r"((a)[2]), "r"((a)[3]), \
                   "r"((b)[0]), "r"((b)[1]))

__device__ __forceinline__ void cp_async16(uint32_t dst, const void* src) {
    asm volatile("cp.async.cg.shared.global [%0], [%1], 16;" :: "r"(dst), "l"(src));
}
#define CP_COMMIT() asm volatile("cp.async.commit_group;")
#define CP_WAIT0()  asm volatile("cp.async.wait_group 0;")
#define CP_WAIT1()  asm volatile("cp.async.wait_group 1;")

// ---------------- fused transpose + layer-0 LN ------------------------------
__global__ void transpose_ln_kernel(const float* __restrict__ x,
                                    const float* __restrict__ gamma,
                                    const float* __restrict__ beta) {
    __shared__ float tile[32][129];
    int b  = blockIdx.y;
    int n0 = blockIdx.x * 32;
    int tx = threadIdx.x & 31;
    int ty = threadIdx.x >> 5;     // 0..7
#pragma unroll
    for (int e0 = 0; e0 < E; e0 += 32) {
#pragma unroll
        for (int i = 0; i < 32; i += 8)
            tile[tx][e0 + ty + i] =
                x[(size_t)b * E * NSEQ + (size_t)(e0 + ty + i) * NSEQ + n0 + tx];
    }
    __syncthreads();
    int lane = tx, wid = ty;
    float g4[4], b4[4];
#pragma unroll
    for (int j = 0; j < 4; j++) { g4[j] = gamma[lane + 32 * j]; b4[j] = beta[lane + 32 * j]; }
    for (int rr = 0; rr < 4; rr++) {
        int row = wid * 4 + rr;
        size_t grow = (size_t)b * NSEQ + n0 + row;
        float xv[4];
#pragma unroll
        for (int j = 0; j < 4; j++) {
            xv[j] = tile[row][lane + 32 * j];
            g_t[grow * E + lane + 32 * j] = xv[j];
        }
        float s = xv[0] + xv[1] + xv[2] + xv[3];
#pragma unroll
        for (int o = 16; o > 0; o >>= 1) s += __shfl_xor_sync(0xffffffffu, s, o);
        float mu = s * (1.0f / E);
        float s2 = 0.f;
#pragma unroll
        for (int j = 0; j < 4; j++) { float d = xv[j] - mu; s2 += d * d; }
#pragma unroll
        for (int o = 16; o > 0; o >>= 1) s2 += __shfl_xor_sync(0xffffffffu, s2, o);
        float rs = rsqrtf(s2 * (1.0f / E) + LN_EPS);
#pragma unroll
        for (int j = 0; j < 4; j++)
            g_y[grow * E + lane + 32 * j] =
                __float2half_rn((xv[j] - mu) * rs * g4[j] + b4[j]);
    }
}

// ---------------- fused weight convert (ALL layers, one launch), fp16 -------
__global__ void wt_cvt_all(const float* __restrict__ q_w, const float* __restrict__ k_w,
                           const float* __restrict__ v_w, const float* __restrict__ o_w,
                           const float* __restrict__ ff_w1, const float* __restrict__ ff_w2) {
    __shared__ float tile[32][33];
    int l  = blockIdx.y;
    int id = blockIdx.x;
    __half* wl = g_wt + (size_t)l * WT_LAYER;

    const float* src;
    __half* dst;
    int K, N, tn, tk;
    if (id < 64) {
        int m = id >> 4;
        const float* srcs[4] = { q_w, k_w, v_w, o_w };
        src = srcs[m] + (size_t)l * E * E;
        dst = wl + m * 16384;
        K = E; N = E;
        int t = id & 15; tn = t & 3; tk = t >> 2;
    } else if (id < 128) {
        src = ff_w1 + (size_t)l * E * DFF;
        dst = wl + 65536;
        K = E; N = DFF;
        int t = id - 64; tn = t & 15; tk = t >> 4;
    } else {
        src = ff_w2 + (size_t)l * DFF * E;
        dst = wl + 131072;
        K = DFF; N = E;
        int t = id - 128; tn = t & 3; tk = t >> 2;
    }
    int n0 = tn * 32, k0 = tk * 32;
    int tx = threadIdx.x, ty = threadIdx.y;   // (32,8)
#pragma unroll
    for (int i = 0; i < 32; i += 8)
        tile[ty + i][tx] = src[(size_t)(k0 + ty + i) * N + n0 + tx];
    __syncthreads();
#pragma unroll
    for (int i = 0; i < 32; i += 8)
        dst[(size_t)(n0 + ty + i) * K + k0 + tx] = __float2half_rn(tile[tx][ty + i]);
}

// ---------------- generic FP16 GEMM (fp32 accum), pipelined, PDL-aware ------
#define GBM 128
#define GBN 128
#define NSTAGE 3
#define STAGE_BYTES 16384
#define BSMEM_OFF (NSTAGE * STAGE_BYTES)
#define SMEM_BYTES (2 * NSTAGE * STAGE_BYTES)   // 98304

__global__ __launch_bounds__(256, 2) void mma_gemm(
    const __half* __restrict__ A, const __half* __restrict__ Wt,
    const float* __restrict__ bias, void* __restrict__ Cv,
    const float* __restrict__ gamma, const float* __restrict__ beta,
    __half* __restrict__ Y,
    int K, int N, int flags)
{
    extern __shared__ float sm[];
    uint32_t smem_u = (uint32_t)__cvta_generic_to_shared(sm);

    int tid  = threadIdx.x;
    int lane = tid & 31;
    int wid  = tid >> 5;
    int warp_m = wid & 1;
    int warp_n = wid >> 1;
    int bm0 = blockIdx.y * GBM;
    int bn0 = blockIdx.x * GBN;

    int r0 = tid >> 3;
    int c8 = tid & 7;
    uint32_t cxor = (uint32_t)((c8 ^ (r0 & 7)) << 4);

    auto load_A = [&](int s, int k0) {
#pragma unroll
        for (int i = 0; i < 4; i++) {
            int r = r0 + i * 32;
            uint32_t doff = (uint32_t)(r << 7) + cxor;
            cp_async16(smem_u + s * STAGE_BYTES + doff, A + (size_t)(bm0 + r) * K + k0 + c8 * 8);
        }
    };
    auto load_B = [&](int s, int k0) {
#pragma unroll
        for (int i = 0; i < 4; i++) {
            int r = r0 + i * 32;
            uint32_t doff = (uint32_t)(r << 7) + cxor;
            cp_async16(smem_u + BSMEM_OFF + s * STAGE_BYTES + doff, Wt + (size_t)(bn0 + r) * K + k0 + c8 * 8);
        }
    };

    load_B(0, 0); CP_COMMIT();
    gdc_wait();

    int nIter = K >> 6;
    load_A(0, 0); CP_COMMIT();
    if (nIter > 1) { load_A(1, 64); load_B(1, 64); CP_COMMIT(); }

    int sub = lane >> 3;
    int l7  = lane & 7;
    int selA = sub >> 1;
    int rowAoff = ((sub & 1) << 3) + l7;
    int selB = sub & 1;
    int rowBoff = ((sub >> 1) << 3) + l7;

    float acc[4][4][4];
#pragma unroll
    for (int i = 0; i < 4; i++)
#pragma unroll
        for (int j = 0; j < 4; j++)
#pragma unroll
            for (int k = 0; k < 4; k++) acc[i][j][k] = 0.f;

    for (int it = 0; it < nIter; it++) {
        if (it < nIter - 1) CP_WAIT1(); else CP_WAIT0();
        __syncthreads();

        int s = it % NSTAGE;
        uint32_t baseA = smem_u + s * STAGE_BYTES;
        uint32_t baseB = smem_u + BSMEM_OFF + s * STAGE_BYTES;

#pragma unroll
        for (int ks = 0; ks < 4; ks++) {
            int cb = ks * 2;
            uint32_t a[4][4], b[4][2];
#pragma unroll
            for (int mt = 0; mt < 4; mt++) {
                int row = warp_m * 64 + mt * 16 + rowAoff;
                uint32_t addr = baseA + (row << 7) + (uint32_t)(((cb + selA) ^ (row & 7)) << 4);
                LDSM4(a[mt][0], a[mt][1], a[mt][2], a[mt][3], addr);
            }
#pragma unroll
            for (int bt = 0; bt < 2; bt++) {
                int row = warp_n * 32 + bt * 16 + rowBoff;
                uint32_t addr = baseB + (row << 7) + (uint32_t)(((cb + selB) ^ (row & 7)) << 4);
                LDSM4(b[2 * bt][0], b[2 * bt][1], b[2 * bt + 1][0], b[2 * bt + 1][1], addr);
            }
#pragma unroll
            for (int mt = 0; mt < 4; mt++)
#pragma unroll
                for (int nt = 0; nt < 4; nt++)
                    MMA_F16(acc[mt][nt], a[mt], b[nt]);
        }

        if (it + 2 < nIter) {
            load_A((it + 2) % NSTAGE, (it + 2) * 64);
            load_B((it + 2) % NSTAGE, (it + 2) * 64);
            CP_COMMIT();
        }
    }

    int g  = lane >> 2;
    int t4 = lane & 3;
    bool do_ln = (flags & 8) != 0;
    if (do_ln) __syncthreads();

    float* Cf = (float*)Cv;
    __half* Ch = (__half*)Cv;

#pragma unroll
    for (int mt = 0; mt < 4; mt++) {
        int rowl0 = warp_m * 64 + mt * 16 + g;
#pragma unroll
        for (int nt = 0; nt < 4; nt++) {
            int coll = warp_n * 32 + nt * 8 + t4 * 2;
            int col  = bn0 + coll;
            float v[4] = { acc[mt][nt][0], acc[mt][nt][1], acc[mt][nt][2], acc[mt][nt][3] };
            if (bias) {
                float b0 = bias[col], b1 = bias[col + 1];
                v[0] += b0; v[1] += b1; v[2] += b0; v[3] += b1;
            }
            if (flags & 1) {
#pragma unroll
                for (int z = 0; z < 4; z++) v[z] = gelu_f(v[z]);
            }
#pragma unroll
            for (int half2i = 0; half2i < 2; half2i++) {
                int rowl = rowl0 + half2i * 8;
                float f0 = v[half2i * 2], f1 = v[half2i * 2 + 1];
                if (flags & 16) {
                    *(__half2*)(Ch + (size_t)(bm0 + rowl) * N + col) =
                        __halves2half2(__float2half_rn(f0), __float2half_rn(f1));
                } else {
                    float2* p = (float2*)(Cf + (size_t)(bm0 + rowl) * N + col);
                    if (flags & 2) {
                        float2 o = *p;
                        f0 += o.x; f1 += o.y;
                    }
                    *p = make_float2(f0, f1);
                }
                if (do_ln) {
                    sm[rowl * 132 + coll]     = f0;
                    sm[rowl * 132 + coll + 1] = f1;
                }
            }
        }
    }

    if (do_ln) {
        __syncthreads();
        float g4[4], b4[4];
#pragma unroll
        for (int j = 0; j < 4; j++) {
            g4[j] = gamma[lane + 32 * j];
            b4[j] = beta[lane + 32 * j];
        }
        for (int r = 0; r < 16; r++) {
            int row = wid * 16 + r;
            float x[4];
#pragma unroll
            for (int j = 0; j < 4; j++) x[j] = sm[row * 132 + lane + 32 * j];
            float s = x[0] + x[1] + x[2] + x[3];
#pragma unroll
            for (int o = 16; o > 0; o >>= 1) s += __shfl_xor_sync(0xffffffffu, s, o);
            float mu = s * (1.0f / E);
            float s2 = 0.f;
#pragma unroll
            for (int j = 0; j < 4; j++) { float d = x[j] - mu; s2 += d * d; }
#pragma unroll
            for (int o = 16; o > 0; o >>= 1) s2 += __shfl_xor_sync(0xffffffffu, s2, o);
            float rs = rsqrtf(s2 * (1.0f / E) + LN_EPS);
#pragma unroll
            for (int j = 0; j < 4; j++)
                Y[(size_t)(bm0 + row) * E + lane + 32 * j] =
                    __float2half_rn((x[j] - mu) * rs * g4[j] + b4[j]);
        }
    }
}

// ---------------- ctx partial: one 128-row chunk per block ------------------
// Staging via int4 (8 halfs per load); __expf; 4-way n-split x e-quad accum.
__global__ void ctx_part_kernel() {
    gdc_wait();
    int blk = blockIdx.x;              // bh*NCHUNK + c
    int bh = blk >> 3, c = blk & 7;
    int b = bh >> 3, h = bh & 7;
    const __half* kbase = g_qkv + (size_t)b * NSEQ * QKV_N + (size_t)c * CHUNK_N * QKV_N + E + h * DH;
    const __half* vbase = kbase + E;
    int tid = threadIdx.x;

    __shared__ float  ks[128][17];
    __shared__ float4 vs4[128][5];     // 4 quads + pad
    __shared__ float4 red[4][64];
    __shared__ float  reds[4][16];

    // stage: 512 16B segments (128 rows x {k0,k1,v0,v1}), 2 per thread
#pragma unroll
    for (int s = tid; s < 512; s += 256) {
        int nl = s >> 2, sub = s & 3;
        bool isv = (sub & 2) != 0;
        int seg = sub & 1;
        const __half* p = (isv ? vbase : kbase) + (size_t)nl * QKV_N + seg * 8;
        int4 raw = *(const int4*)p;
        __half2* h2 = (__half2*)&raw;
        float2 f0 = __half22float2(h2[0]);
        float2 f1 = __half22float2(h2[1]);
        float2 f2 = __half22float2(h2[2]);
        float2 f3 = __half22float2(h2[3]);
        if (isv) {
            vs4[nl][seg * 2]     = make_float4(f0.x, f0.y, f1.x, f1.y);
            vs4[nl][seg * 2 + 1] = make_float4(f2.x, f2.y, f3.x, f3.y);
        } else {
            float* kd = &ks[nl][seg * 8];
            kd[0] = __expf(f0.x); kd[1] = __expf(f0.y);
            kd[2] = __expf(f1.x); kd[3] = __expf(f1.y);
            kd[4] = __expf(f2.x); kd[5] = __expf(f2.y);
            kd[6] = __expf(f3.x); kd[7] = __expf(f3.y);
        }
    }
    __syncthreads();

    int ns  = tid >> 6;                // 0..3 (n-split)
    int idx = tid & 63;
    int d  = idx >> 2;                 // 0..15
    int eq = idx & 3;                  // 0..3 (e quad)
    int n0 = ns * 32;

    float a0 = 0.f, a1 = 0.f, a2 = 0.f, a3 = 0.f, ssum = 0.f;
#pragma unroll 16
    for (int nl = 0; nl < 32; nl++) {
        float kk = ks[n0 + nl][d];
        float4 vv = vs4[n0 + nl][eq];
        a0 += kk * vv.x;
        a1 += kk * vv.y;
        a2 += kk * vv.z;
        a3 += kk * vv.w;
        ssum += kk;
    }
    red[ns][idx] = make_float4(a0, a1, a2, a3);
    if (eq == 0) reds[ns][d] = ssum;
    __syncthreads();

    if (ns == 0) {
#pragma unroll
        for (int s = 1; s < 4; s++) {
            float4 o = red[s][idx];
            a0 += o.x; a1 += o.y; a2 += o.z; a3 += o.w;
        }
        float* dst = g_ctxp + blk * 256 + d * 16 + eq * 4;
        dst[0] = a0; dst[1] = a1; dst[2] = a2; dst[3] = a3;
        if (eq == 0) {
            float ss = ssum;
#pragma unroll
            for (int s = 1; s < 4; s++) ss += reds[s][d];
            g_ssum[blk * 16 + d] = ss;
        }
    }
}

// ---------------- o-proj: partial-reduce + attn prologue + GEMM + LN --------
#define OP_B_OFF 32768
#define OP_CTX_OFF 65536
#define OP_SMEM 73728

__global__ __launch_bounds__(256, 2) void oproj_kernel(
    const __half* __restrict__ Wt, const float* __restrict__ bias,
    const float* __restrict__ gamma, const float* __restrict__ beta)
{
    extern __shared__ float sm[];
    uint32_t smem_u = (uint32_t)__cvta_generic_to_shared(sm);

    int tid  = threadIdx.x;
    int lane = tid & 31;
    int wid  = tid >> 5;
    int warp_m = wid & 1;
    int warp_n = wid >> 1;
    int m0 = blockIdx.x * GBM;
    int b  = m0 >> 10;

    int r0 = tid >> 3;
    int c8 = tid & 7;
    uint32_t cxor = (uint32_t)((c8 ^ (r0 & 7)) << 4);

#pragma unroll
    for (int i = 0; i < 4; i++) {
        int r = r0 + i * 32;
        cp_async16(smem_u + OP_B_OFF + (r << 7) + cxor, Wt + (size_t)r * E + c8 * 8);
    }
    CP_COMMIT();
#pragma unroll
    for (int i = 0; i < 4; i++) {
        int r = r0 + i * 32;
        cp_async16(smem_u + OP_B_OFF + 16384 + (r << 7) + cxor, Wt + (size_t)r * E + 64 + c8 * 8);
    }
    CP_COMMIT();
    gdc_wait();

    // reduce ctx partials into smem: ctx = (Σ_c acc) / (Σ_c ssum)
    float* ctxs = (float*)((char*)sm + OP_CTX_OFF);
    for (int i = tid; i < 2048; i += 256) {
        int h = i >> 8, de = i & 255, d = de >> 4;
        int bh8 = ((b * NHEADS + h) << 3);
        float a = 0.f, ss = 0.f;
#pragma unroll
        for (int c = 0; c < NCHUNK; c++) {
            a  += g_ctxp[(bh8 + c) * 256 + de];
            ss += g_ssum[(bh8 + c) * 16 + d];
        }
        ctxs[i] = a / ss;
    }
    __syncthreads();

    // attention prologue: A[128][128] = f16(softmax_q(q) @ ctx * 0.25)
    {
        int row = tid >> 1, half = tid & 1;
        const __half* qrow = g_qkv + (size_t)(m0 + row) * QKV_N;
#pragma unroll
        for (int hh = 0; hh < 4; hh++) {
            int h = half * 4 + hh;
            float qv[16];
            const __half2* q2 = (const __half2*)(qrow + h * 16);
#pragma unroll
            for (int j = 0; j < 8; j++) {
                float2 t = __half22float2(q2[j]);
                qv[2 * j] = t.x; qv[2 * j + 1] = t.y;
            }
            float mxv = -1e30f;
#pragma unroll
            for (int d = 0; d < 16; d++) mxv = fmaxf(mxv, qv[d]);
            float s = 0.f;
#pragma unroll
            for (int d = 0; d < 16; d++) { qv[d] = __expf(qv[d] - mxv); s += qv[d]; }
            float r = 0.25f / s;
            const float* cb = ctxs + h * 256;
#pragma unroll
            for (int e2 = 0; e2 < 16; e2 += 2) {
                float a0 = 0.f, a1 = 0.f;
#pragma unroll
                for (int d = 0; d < 16; d++) {
                    float qq = qv[d];
                    a0 += qq * cb[d * 16 + e2];
                    a1 += qq * cb[d * 16 + e2 + 1];
                }
                int col = h * 16 + e2;
                int t = col >> 6, chunk = (col >> 3) & 7, hi = col & 7;
                uint32_t off = (uint32_t)(t * 16384 + (row << 7) + (((chunk) ^ (row & 7)) << 4) + hi * 2);
                *(__half2*)((char*)sm + off) =
                    __halves2half2(__float2half_rn(a0 * r), __float2half_rn(a1 * r));
            }
        }
    }

    int sub = lane >> 3;
    int l7  = lane & 7;
    int selA = sub >> 1;
    int rowAoff = ((sub & 1) << 3) + l7;
    int selB = sub & 1;
    int rowBoff = ((sub >> 1) << 3) + l7;

    float acc[4][4][4];
#pragma unroll
    for (int i = 0; i < 4; i++)
#pragma unroll
        for (int j = 0; j < 4; j++)
#pragma unroll
            for (int k = 0; k < 4; k++) acc[i][j][k] = 0.f;

    for (int it = 0; it < 2; it++) {
        if (it == 0) CP_WAIT1(); else CP_WAIT0();
        __syncthreads();
        uint32_t baseA = smem_u + it * 16384;
        uint32_t baseB = smem_u + OP_B_OFF + it * 16384;
#pragma unroll
        for (int ks = 0; ks < 4; ks++) {
            int cb = ks * 2;
            uint32_t a[4][4], bb[4][2];
#pragma unroll
            for (int mt = 0; mt < 4; mt++) {
                int row = warp_m * 64 + mt * 16 + rowAoff;
                uint32_t addr = baseA + (row << 7) + (uint32_t)(((cb + selA) ^ (row & 7)) << 4);
                LDSM4(a[mt][0], a[mt][1], a[mt][2], a[mt][3], addr);
            }
#pragma unroll
            for (int bt = 0; bt < 2; bt++) {
                int row = warp_n * 32 + bt * 16 + rowBoff;
                uint32_t addr = baseB + (row << 7) + (uint32_t)(((cb + selB) ^ (row & 7)) << 4);
                LDSM4(bb[2 * bt][0], bb[2 * bt][1], bb[2 * bt + 1][0], bb[2 * bt + 1][1], addr);
            }
#pragma unroll
            for (int mt = 0; mt < 4; mt++)
#pragma unroll
                for (int nt = 0; nt < 4; nt++)
                    MMA_F16(acc[mt][nt], a[mt], bb[nt]);
        }
    }

    int g  = lane >> 2;
    int t4 = lane & 3;
    __syncthreads();
#pragma unroll
    for (int mt = 0; mt < 4; mt++) {
        int rowl0 = warp_m * 64 + mt * 16 + g;
#pragma unroll
        for (int nt = 0; nt < 4; nt++) {
            int col = warp_n * 32 + nt * 8 + t4 * 2;
            float b0 = bias[col], b1 = bias[col + 1];
#pragma unroll
            for (int hf = 0; hf < 2; hf++) {
                int rowl = rowl0 + hf * 8;
                float2* p = (float2*)(g_t + (size_t)(m0 + rowl) * E + col);
                float2 o = *p;
                float f0 = acc[mt][nt][hf * 2]     + b0 + o.x;
                float f1 = acc[mt][nt][hf * 2 + 1] + b1 + o.y;
                *p = make_float2(f0, f1);
                sm[rowl * 132 + col]     = f0;
                sm[rowl * 132 + col + 1] = f1;
            }
        }
    }
    __syncthreads();
    float g4[4], b4[4];
#pragma unroll
    for (int j = 0; j < 4; j++) { g4[j] = gamma[lane + 32 * j]; b4[j] = beta[lane + 32 * j]; }
    for (int rr = 0; rr < 16; rr++) {
        int row = wid * 16 + rr;
        float x[4];
#pragma unroll
        for (int j = 0; j < 4; j++) x[j] = sm[row * 132 + lane + 32 * j];
        float s = x[0] + x[1] + x[2] + x[3];
#pragma unroll
        for (int o = 16; o > 0; o >>= 1) s += __shfl_xor_sync(0xffffffffu, s, o);
        float mu = s * (1.0f / E);
        float s2 = 0.f;
#pragma unroll
        for (int j = 0; j < 4; j++) { float d = x[j] - mu; s2 += d * d; }
#pragma unroll
        for (int o = 16; o > 0; o >>= 1) s2 += __shfl_xor_sync(0xffffffffu, s2, o);
        float rs = rsqrtf(s2 * (1.0f / E) + LN_EPS);
#pragma unroll
        for (int j = 0; j < 4; j++)
            g_y[(size_t)(m0 + row) * E + lane + 32 * j] =
                __float2half_rn((x[j] - mu) * rs * g4[j] + b4[j]);
    }
}

// ---------------- two-stage mean over sequence ------------------------------
__global__ void mean1_kernel() {
    gdc_wait();
    int blk = blockIdx.x;             // b*8 + chunk
    int b = blk >> 3, ch = blk & 7;
    int e = threadIdx.x;
    const float* p = g_t + (size_t)b * NSEQ * E + (size_t)ch * 128 * E + e;
    float s = 0.f;
#pragma unroll 8
    for (int n = 0; n < 128; n++) s += p[(size_t)n * E];
    g_part[blk * E + e] = s;
}

__global__ void mean2_kernel(float* __restrict__ out) {
    gdc_wait();
    int b = blockIdx.x, e = threadIdx.x;
    float s = 0.f;
#pragma unroll
    for (int ch = 0; ch < 8; ch++) s += g_part[(b * 8 + ch) * E + e];
    out[b * E + e] = s * (1.0f / NSEQ);
}

// ---------------- PDL launch helper ------------------------------------------
template <typename F, typename... A>
static inline void launchPDL(F f, dim3 grid, dim3 block, size_t smem, A... args) {
    cudaLaunchConfig_t cfg = {};
    cfg.gridDim = grid;
    cfg.blockDim = block;
    cfg.dynamicSmemBytes = smem;
    cfg.stream = 0;
    cudaLaunchAttribute at[1];
    at[0].id = cudaLaunchAttributeProgrammaticStreamSerialization;
    at[0].val.programmaticStreamSerializationAllowed = 1;
    cfg.attrs = at;
    cfg.numAttrs = 1;
    cudaLaunchKernelEx(&cfg, f, args...);
}

// ---------------- launch -----------------------------------------------------
extern "C" void kernel_launch(void* const* d_in, const int* in_sizes, int n_in,
                              void* d_out, int out_size) {
    const float* x     = (const float*)d_in[0];
    const float* q_w   = (const float*)d_in[1];
    const float* k_w   = (const float*)d_in[2];
    const float* v_w   = (const float*)d_in[3];
    const float* o_w   = (const float*)d_in[4];
    const float* o_b   = (const float*)d_in[5];
    const float* ln1_g = (const float*)d_in[6];
    const float* ln1_b = (const float*)d_in[7];
    const float* ff_w1 = (const float*)d_in[8];
    const float* ff_b1 = (const float*)d_in[9];
    const float* ff_w2 = (const float*)d_in[10];
    const float* ff_b2 = (const float*)d_in[11];
    const float* ln2_g = (const float*)d_in[12];
    const float* ln2_b = (const float*)d_in[13];
    float* out = (float*)d_out;

    float* pt;
    __half *py, *pqkv, *pff, *pwt;
    cudaGetSymbolAddress((void**)&pt,   g_t);
    cudaGetSymbolAddress((void**)&py,   g_y);
    cudaGetSymbolAddress((void**)&pqkv, g_qkv);
    cudaGetSymbolAddress((void**)&pff,  g_ff);
    cudaGetSymbolAddress((void**)&pwt,  g_wt);

    cudaFuncSetAttribute(mma_gemm, cudaFuncAttributeMaxDynamicSharedMemorySize, SMEM_BYTES);
    cudaFuncSetAttribute(oproj_kernel, cudaFuncAttributeMaxDynamicSharedMemorySize, OP_SMEM);

    wt_cvt_all<<<dim3(192, NLAYERS), dim3(32, 8)>>>(q_w, k_w, v_w, o_w, ff_w1, ff_w2);
    transpose_ln_kernel<<<dim3(NSEQ / 32, BATCH), 256>>>(x, ln1_g, ln1_b);

    for (int l = 0; l < NLAYERS; l++) {
        const __half* wl = pwt + (size_t)l * WT_LAYER;
        launchPDL(mma_gemm, dim3(QKV_N / GBN, MROWS / GBM), dim3(256), SMEM_BYTES,
                  (const __half*)py, wl, (const float*)nullptr, (void*)pqkv,
                  (const float*)nullptr, (const float*)nullptr, (__half*)nullptr,
                  (int)E, (int)QKV_N, (int)16);
        launchPDL(ctx_part_kernel, dim3(BATCH * NHEADS * NCHUNK), dim3(256), 0);
        launchPDL(oproj_kernel, dim3(MROWS / GBM), dim3(256), OP_SMEM,
                  wl + 49152, (const float*)(o_b + l * E),
                  (const float*)(ln2_g + l * E), (const float*)(ln2_b + l * E));
        launchPDL(mma_gemm, dim3(DFF / GBN, MROWS / GBM), dim3(256), SMEM_BYTES,
                  (const __half*)py, wl + 65536, (const float*)(ff_b1 + l * DFF), (void*)pff,
                  (const float*)nullptr, (const float*)nullptr, (__half*)nullptr,
                  (int)E, (int)DFF, (int)(1 | 16));
        if (l < NLAYERS - 1) {
            launchPDL(mma_gemm, dim3(1, MROWS / GBM), dim3(256), SMEM_BYTES,
                      (const __half*)pff, wl + 131072, (const float*)(ff_b2 + l * E), (void*)pt,
                      (const float*)(ln1_g + (l + 1) * E), (const float*)(ln1_b + (l + 1) * E),
                      py, (int)DFF, (int)E, (int)(2 | 8));
        } else {
            launchPDL(mma_gemm, dim3(1, MROWS / GBM), dim3(256), SMEM_BYTES,
                      (const __half*)pff, wl + 131072, (const float*)(ff_b2 + l * E), (void*)pt,
                      (const float*)nullptr, (const float*)nullptr, (__half*)nullptr,
                      (int)DFF, (int)E, (int)2);
        }
    }

    launchPDL(mean1_kernel, dim3(512), dim3(E), 0);
    launchPDL(mean2_kernel, dim3(BATCH), dim3(E), 0, out);
}

// round 16
// speedup vs baseline: 2.3594x; 1.0520x over previous
#include <cuda_runtime.h>
#include <cuda_fp16.h>
#include <math.h>
#include <stdint.h>

#define BATCH 64
#define E 128
#define NSEQ 1024
#define NHEADS 8
#define DH 16
#define DFF 512
#define MROWS (BATCH * NSEQ)   // 65536
#define NLAYERS 4
#define LN_EPS 1e-5f
#define QKV_N 384
#define NCHUNK 8
#define CHUNK_N (NSEQ / NCHUNK)   // 128

// ---------------- scratch (static device globals; allocation-free) ----------
__device__ float  g_t[MROWS * E];          // residual stream fp32
__device__ __half g_y[MROWS * E];          // layernorm output (fp16)
__device__ __half g_qkv[MROWS * QKV_N];    // fused q|k|v fp16, row stride 384
__device__ float  g_ctxp[BATCH * NHEADS * NCHUNK * 256];  // ctx partials
__device__ float  g_ssum[BATCH * NHEADS * NCHUNK * 16];   // exp-sum partials
__device__ __half g_ff[MROWS * DFF];       // gelu out (fp16)
__device__ float  g_part[512 * E];         // mean partials
#define WT_LAYER 196608
__device__ __half g_wt[NLAYERS * WT_LAYER];

__device__ __forceinline__ float gelu_f(float x) {
    float x3 = x * x * x;
    return 0.5f * x * (1.0f + tanhf(0.7978845608028654f * (x + 0.044715f * x3)));
}

__device__ __forceinline__ void gdc_wait() {
    asm volatile("griddepcontrol.wait;" ::: "memory");
}

#define LDSM4(d0, d1, d2, d3, addr) \
    asm volatile("ldmatrix.sync.aligned.m8n8.x4.shared.b16 {%0,%1,%2,%3}, [%4];" \
                 : "=r"(d0), "=r"(d1), "=r"(d2), "=r"(d3) : "r"(addr))

#define MMA_F16(c, a, b) \
    asm volatile("mma.sync.aligned.m16n8k16.row.col.f32.f16.f16.f32 " \
                 "{%0,%1,%2,%3},{%4,%5,%6,%7},{%8,%9},{%0,%1,%2,%3};" \
                 : "+f"((c)[0]), "+f"((c)[1]), "+f"((c)[2]), "+f"((c)[3]) \
                 : "r"((a)[0]), "r"((a)[1]), "r"((a)[2]), "r"((a)[3]), \
                   "r"((b)[0]), "r"((b)[1]))

__device__ __forceinline__ void cp_async16(uint32_t dst, const void* src) {
    asm volatile("cp.async.cg.shared.global [%0], [%1], 16;" :: "r"(dst), "l"(src));
}
#define CP_COMMIT() asm volatile("cp.async.commit_group;")
#define CP_WAIT0()  asm volatile("cp.async.wait_group 0;")
#define CP_WAIT1()  asm volatile("cp.async.wait_group 1;")

// ---------------- fused transpose + layer-0 LN ------------------------------
__global__ void transpose_ln_kernel(const float* __restrict__ x,
                                    const float* __restrict__ gamma,
                                    const float* __restrict__ beta) {
    __shared__ float tile[32][129];
    int b  = blockIdx.y;
    int n0 = blockIdx.x * 32;
    int tx = threadIdx.x & 31;
    int ty = threadIdx.x >> 5;     // 0..7
#pragma unroll
    for (int e0 = 0; e0 < E; e0 += 32) {
#pragma unroll
        for (int i = 0; i < 32; i += 8)
            tile[tx][e0 + ty + i] =
                x[(size_t)b * E * NSEQ + (size_t)(e0 + ty + i) * NSEQ + n0 + tx];
    }
    __syncthreads();
    int lane = tx, wid = ty;
    float g4[4], b4[4];
#pragma unroll
    for (int j = 0; j < 4; j++) { g4[j] = gamma[lane + 32 * j]; b4[j] = beta[lane + 32 * j]; }
    for (int rr = 0; rr < 4; rr++) {
        int row = wid * 4 + rr;
        size_t grow = (size_t)b * NSEQ + n0 + row;
        float xv[4];
#pragma unroll
        for (int j = 0; j < 4; j++) {
            xv[j] = tile[row][lane + 32 * j];
            g_t[grow * E + lane + 32 * j] = xv[j];
        }
        float s = xv[0] + xv[1] + xv[2] + xv[3];
#pragma unroll
        for (int o = 16; o > 0; o >>= 1) s += __shfl_xor_sync(0xffffffffu, s, o);
        float mu = s * (1.0f / E);
        float s2 = 0.f;
#pragma unroll
        for (int j = 0; j < 4; j++) { float d = xv[j] - mu; s2 += d * d; }
#pragma unroll
        for (int o = 16; o > 0; o >>= 1) s2 += __shfl_xor_sync(0xffffffffu, s2, o);
        float rs = rsqrtf(s2 * (1.0f / E) + LN_EPS);
#pragma unroll
        for (int j = 0; j < 4; j++)
            g_y[grow * E + lane + 32 * j] =
                __float2half_rn((xv[j] - mu) * rs * g4[j] + b4[j]);
    }
}

// ---------------- fused weight convert (ALL layers, one launch), fp16 -------
__global__ void wt_cvt_all(const float* __restrict__ q_w, const float* __restrict__ k_w,
                           const float* __restrict__ v_w, const float* __restrict__ o_w,
                           const float* __restrict__ ff_w1, const float* __restrict__ ff_w2) {
    __shared__ float tile[32][33];
    int l  = blockIdx.y;
    int id = blockIdx.x;
    __half* wl = g_wt + (size_t)l * WT_LAYER;

    const float* src;
    __half* dst;
    int K, N, tn, tk;
    if (id < 64) {
        int m = id >> 4;
        const float* srcs[4] = { q_w, k_w, v_w, o_w };
        src = srcs[m] + (size_t)l * E * E;
        dst = wl + m * 16384;
        K = E; N = E;
        int t = id & 15; tn = t & 3; tk = t >> 2;
    } else if (id < 128) {
        src = ff_w1 + (size_t)l * E * DFF;
        dst = wl + 65536;
        K = E; N = DFF;
        int t = id - 64; tn = t & 15; tk = t >> 4;
    } else {
        src = ff_w2 + (size_t)l * DFF * E;
        dst = wl + 131072;
        K = DFF; N = E;
        int t = id - 128; tn = t & 3; tk = t >> 2;
    }
    int n0 = tn * 32, k0 = tk * 32;
    int tx = threadIdx.x, ty = threadIdx.y;   // (32,8)
#pragma unroll
    for (int i = 0; i < 32; i += 8)
        tile[ty + i][tx] = src[(size_t)(k0 + ty + i) * N + n0 + tx];
    __syncthreads();
#pragma unroll
    for (int i = 0; i < 32; i += 8)
        dst[(size_t)(n0 + ty + i) * K + k0 + tx] = __float2half_rn(tile[tx][ty + i]);
}

// ---------------- generic FP16 GEMM (fp32 accum), pipelined, PDL-aware ------
#define GBM 128
#define GBN 128
#define NSTAGE 3
#define STAGE_BYTES 16384
#define BSMEM_OFF (NSTAGE * STAGE_BYTES)
#define SMEM_BYTES (2 * NSTAGE * STAGE_BYTES)   // 98304

__global__ __launch_bounds__(256, 2) void mma_gemm(
    const __half* __restrict__ A, const __half* __restrict__ Wt,
    const float* __restrict__ bias, void* __restrict__ Cv,
    const float* __restrict__ gamma, const float* __restrict__ beta,
    __half* __restrict__ Y,
    int K, int N, int flags)
{
    extern __shared__ float sm[];
    uint32_t smem_u = (uint32_t)__cvta_generic_to_shared(sm);

    int tid  = threadIdx.x;
    int lane = tid & 31;
    int wid  = tid >> 5;
    int warp_m = wid & 1;
    int warp_n = wid >> 1;
    int bm0 = blockIdx.y * GBM;
    int bn0 = blockIdx.x * GBN;

    int r0 = tid >> 3;
    int c8 = tid & 7;
    uint32_t cxor = (uint32_t)((c8 ^ (r0 & 7)) << 4);

    auto load_A = [&](int s, int k0) {
#pragma unroll
        for (int i = 0; i < 4; i++) {
            int r = r0 + i * 32;
            uint32_t doff = (uint32_t)(r << 7) + cxor;
            cp_async16(smem_u + s * STAGE_BYTES + doff, A + (size_t)(bm0 + r) * K + k0 + c8 * 8);
        }
    };
    auto load_B = [&](int s, int k0) {
#pragma unroll
        for (int i = 0; i < 4; i++) {
            int r = r0 + i * 32;
            uint32_t doff = (uint32_t)(r << 7) + cxor;
            cp_async16(smem_u + BSMEM_OFF + s * STAGE_BYTES + doff, Wt + (size_t)(bn0 + r) * K + k0 + c8 * 8);
        }
    };

    load_B(0, 0); CP_COMMIT();
    gdc_wait();

    int nIter = K >> 6;
    load_A(0, 0); CP_COMMIT();
    if (nIter > 1) { load_A(1, 64); load_B(1, 64); CP_COMMIT(); }

    int sub = lane >> 3;
    int l7  = lane & 7;
    int selA = sub >> 1;
    int rowAoff = ((sub & 1) << 3) + l7;
    int selB = sub & 1;
    int rowBoff = ((sub >> 1) << 3) + l7;

    float acc[4][4][4];
#pragma unroll
    for (int i = 0; i < 4; i++)
#pragma unroll
        for (int j = 0; j < 4; j++)
#pragma unroll
            for (int k = 0; k < 4; k++) acc[i][j][k] = 0.f;

    for (int it = 0; it < nIter; it++) {
        if (it < nIter - 1) CP_WAIT1(); else CP_WAIT0();
        __syncthreads();

        int s = it % NSTAGE;
        uint32_t baseA = smem_u + s * STAGE_BYTES;
        uint32_t baseB = smem_u + BSMEM_OFF + s * STAGE_BYTES;

#pragma unroll
        for (int ks = 0; ks < 4; ks++) {
            int cb = ks * 2;
            uint32_t a[4][4], b[4][2];
#pragma unroll
            for (int mt = 0; mt < 4; mt++) {
                int row = warp_m * 64 + mt * 16 + rowAoff;
                uint32_t addr = baseA + (row << 7) + (uint32_t)(((cb + selA) ^ (row & 7)) << 4);
                LDSM4(a[mt][0], a[mt][1], a[mt][2], a[mt][3], addr);
            }
#pragma unroll
            for (int bt = 0; bt < 2; bt++) {
                int row = warp_n * 32 + bt * 16 + rowBoff;
                uint32_t addr = baseB + (row << 7) + (uint32_t)(((cb + selB) ^ (row & 7)) << 4);
                LDSM4(b[2 * bt][0], b[2 * bt][1], b[2 * bt + 1][0], b[2 * bt + 1][1], addr);
            }
#pragma unroll
            for (int mt = 0; mt < 4; mt++)
#pragma unroll
                for (int nt = 0; nt < 4; nt++)
                    MMA_F16(acc[mt][nt], a[mt], b[nt]);
        }

        if (it + 2 < nIter) {
            load_A((it + 2) % NSTAGE, (it + 2) * 64);
            load_B((it + 2) % NSTAGE, (it + 2) * 64);
            CP_COMMIT();
        }
    }

    int g  = lane >> 2;
    int t4 = lane & 3;
    bool do_ln = (flags & 8) != 0;
    if (do_ln) __syncthreads();

    float* Cf = (float*)Cv;
    __half* Ch = (__half*)Cv;

#pragma unroll
    for (int mt = 0; mt < 4; mt++) {
        int rowl0 = warp_m * 64 + mt * 16 + g;
#pragma unroll
        for (int nt = 0; nt < 4; nt++) {
            int coll = warp_n * 32 + nt * 8 + t4 * 2;
            int col  = bn0 + coll;
            float v[4] = { acc[mt][nt][0], acc[mt][nt][1], acc[mt][nt][2], acc[mt][nt][3] };
            if (bias) {
                float b0 = bias[col], b1 = bias[col + 1];
                v[0] += b0; v[1] += b1; v[2] += b0; v[3] += b1;
            }
            if (flags & 1) {
#pragma unroll
                for (int z = 0; z < 4; z++) v[z] = gelu_f(v[z]);
            }
#pragma unroll
            for (int half2i = 0; half2i < 2; half2i++) {
                int rowl = rowl0 + half2i * 8;
                float f0 = v[half2i * 2], f1 = v[half2i * 2 + 1];
                if (flags & 16) {
                    *(__half2*)(Ch + (size_t)(bm0 + rowl) * N + col) =
                        __halves2half2(__float2half_rn(f0), __float2half_rn(f1));
                } else {
                    float2* p = (float2*)(Cf + (size_t)(bm0 + rowl) * N + col);
                    if (flags & 2) {
                        float2 o = *p;
                        f0 += o.x; f1 += o.y;
                    }
                    *p = make_float2(f0, f1);
                }
                if (do_ln) {
                    sm[rowl * 132 + coll]     = f0;
                    sm[rowl * 132 + coll + 1] = f1;
                }
            }
        }
    }

    if (do_ln) {
        __syncthreads();
        float g4[4], b4[4];
#pragma unroll
        for (int j = 0; j < 4; j++) {
            g4[j] = gamma[lane + 32 * j];
            b4[j] = beta[lane + 32 * j];
        }
        for (int r = 0; r < 16; r++) {
            int row = wid * 16 + r;
            float x[4];
#pragma unroll
            for (int j = 0; j < 4; j++) x[j] = sm[row * 132 + lane + 32 * j];
            float s = x[0] + x[1] + x[2] + x[3];
#pragma unroll
            for (int o = 16; o > 0; o >>= 1) s += __shfl_xor_sync(0xffffffffu, s, o);
            float mu = s * (1.0f / E);
            float s2 = 0.f;
#pragma unroll
            for (int j = 0; j < 4; j++) { float d = x[j] - mu; s2 += d * d; }
#pragma unroll
            for (int o = 16; o > 0; o >>= 1) s2 += __shfl_xor_sync(0xffffffffu, s2, o);
            float rs = rsqrtf(s2 * (1.0f / E) + LN_EPS);
#pragma unroll
            for (int j = 0; j < 4; j++)
                Y[(size_t)(bm0 + row) * E + lane + 32 * j] =
                    __float2half_rn((x[j] - mu) * rs * g4[j] + b4[j]);
        }
    }
}

// ---------------- ctx partial via tensor cores ------------------------------
// Per block: P[16d][16e] = expk^T(16x128) @ v(128x16) on warp 0 (16 MMAs),
// ssum[16] on warp 1 from the same staged fp16 expk.
__global__ void ctx_part_kernel() {
    gdc_wait();
    int blk = blockIdx.x;              // bh*NCHUNK + c
    int bh = blk >> 3, c = blk & 7;
    int b = bh >> 3, h = bh & 7;
    const __half* kbase = g_qkv + (size_t)b * NSEQ * QKV_N + (size_t)c * CHUNK_N * QKV_N + E + h * DH;
    const __half* vbase = kbase + E;
    int tid = threadIdx.x;

    __shared__ __half aT[16][136];     // expk^T [d][n], 272B row stride
    __shared__ __half vT[16][136];     // v^T    [e][n]

    // stage: 512 16B segments (128 rows x {k0,k1,v0,v1}), transposed stores
#pragma unroll
    for (int s = tid; s < 512; s += 256) {
        int nl = s >> 2, sub = s & 3;
        bool isv = (sub & 2) != 0;
        int seg = sub & 1;
        const __half* p = (isv ? vbase : kbase) + (size_t)nl * QKV_N + seg * 8;
        int4 raw = *(const int4*)p;
        __half* hh = (__half*)&raw;
        if (isv) {
#pragma unroll
            for (int j = 0; j < 8; j++) vT[seg * 8 + j][nl] = hh[j];
        } else {
#pragma unroll
            for (int j = 0; j < 8; j++)
                aT[seg * 8 + j][nl] = __float2half_rn(__expf(__half2float(hh[j])));
        }
    }
    __syncthreads();

    int wid = tid >> 5, lane = tid & 31;
    if (wid == 0) {
        int sub = lane >> 3, l7 = lane & 7;
        int selA = sub >> 1;
        int rowAoff = ((sub & 1) << 3) + l7;
        int selB = sub & 1;
        int rowBoff = ((sub >> 1) << 3) + l7;

        float c0[4] = {0.f, 0.f, 0.f, 0.f};
        float c1[4] = {0.f, 0.f, 0.f, 0.f};
#pragma unroll
        for (int kc = 0; kc < 8; kc++) {
            uint32_t a[4], b0[2], b1[2];
            uint32_t aaddr = (uint32_t)__cvta_generic_to_shared(&aT[rowAoff][kc * 16 + selA * 8]);
            LDSM4(a[0], a[1], a[2], a[3], aaddr);
            uint32_t baddr = (uint32_t)__cvta_generic_to_shared(&vT[rowBoff][kc * 16 + selB * 8]);
            LDSM4(b0[0], b0[1], b1[0], b1[1], baddr);
            MMA_F16(c0, a, b0);
            MMA_F16(c1, a, b1);
        }
        int g = lane >> 2, t4 = lane & 3;
        float* dst = g_ctxp + blk * 256;
        dst[g * 16 + t4 * 2]           = c0[0];
        dst[g * 16 + t4 * 2 + 1]       = c0[1];
        dst[(g + 8) * 16 + t4 * 2]     = c0[2];
        dst[(g + 8) * 16 + t4 * 2 + 1] = c0[3];
        dst[g * 16 + 8 + t4 * 2]           = c1[0];
        dst[g * 16 + 8 + t4 * 2 + 1]       = c1[1];
        dst[(g + 8) * 16 + 8 + t4 * 2]     = c1[2];
        dst[(g + 8) * 16 + 8 + t4 * 2 + 1] = c1[3];
    } else if (wid == 1) {
        int d = lane >> 1, hf = lane & 1;
        const __half* row = &aT[d][hf * 64];
        float s = 0.f;
#pragma unroll 16
        for (int j = 0; j < 64; j++) s += __half2float(row[j]);
        float o = __shfl_xor_sync(0xffffffffu, s, 1);
        if (hf == 0) g_ssum[blk * 16 + d] = s + o;
    }
}

// ---------------- o-proj: partial-reduce + attn prologue + GEMM + LN --------
#define OP_B_OFF 32768
#define OP_CTX_OFF 65536
#define OP_SMEM 73728

__global__ __launch_bounds__(256, 2) void oproj_kernel(
    const __half* __restrict__ Wt, const float* __restrict__ bias,
    const float* __restrict__ gamma, const float* __restrict__ beta)
{
    extern __shared__ float sm[];
    uint32_t smem_u = (uint32_t)__cvta_generic_to_shared(sm);

    int tid  = threadIdx.x;
    int lane = tid & 31;
    int wid  = tid >> 5;
    int warp_m = wid & 1;
    int warp_n = wid >> 1;
    int m0 = blockIdx.x * GBM;
    int b  = m0 >> 10;

    int r0 = tid >> 3;
    int c8 = tid & 7;
    uint32_t cxor = (uint32_t)((c8 ^ (r0 & 7)) << 4);

#pragma unroll
    for (int i = 0; i < 4; i++) {
        int r = r0 + i * 32;
        cp_async16(smem_u + OP_B_OFF + (r << 7) + cxor, Wt + (size_t)r * E + c8 * 8);
    }
    CP_COMMIT();
#pragma unroll
    for (int i = 0; i < 4; i++) {
        int r = r0 + i * 32;
        cp_async16(smem_u + OP_B_OFF + 16384 + (r << 7) + cxor, Wt + (size_t)r * E + 64 + c8 * 8);
    }
    CP_COMMIT();
    gdc_wait();

    // reduce ctx partials into smem: ctx = (Σ_c acc) / (Σ_c ssum)
    float* ctxs = (float*)((char*)sm + OP_CTX_OFF);
    for (int i = tid; i < 2048; i += 256) {
        int h = i >> 8, de = i & 255, d = de >> 4;
        int bh8 = ((b * NHEADS + h) << 3);
        float a = 0.f, ss = 0.f;
#pragma unroll
        for (int c = 0; c < NCHUNK; c++) {
            a  += g_ctxp[(bh8 + c) * 256 + de];
            ss += g_ssum[(bh8 + c) * 16 + d];
        }
        ctxs[i] = a / ss;
    }
    __syncthreads();

    // attention prologue: A[128][128] = f16(softmax_q(q) @ ctx * 0.25)
    {
        int row = tid >> 1, half = tid & 1;
        const __half* qrow = g_qkv + (size_t)(m0 + row) * QKV_N;
#pragma unroll
        for (int hh = 0; hh < 4; hh++) {
            int h = half * 4 + hh;
            float qv[16];
            const __half2* q2 = (const __half2*)(qrow + h * 16);
#pragma unroll
            for (int j = 0; j < 8; j++) {
                float2 t = __half22float2(q2[j]);
                qv[2 * j] = t.x; qv[2 * j + 1] = t.y;
            }
            float mxv = -1e30f;
#pragma unroll
            for (int d = 0; d < 16; d++) mxv = fmaxf(mxv, qv[d]);
            float s = 0.f;
#pragma unroll
            for (int d = 0; d < 16; d++) { qv[d] = __expf(qv[d] - mxv); s += qv[d]; }
            float r = 0.25f / s;
            const float* cb = ctxs + h * 256;
#pragma unroll
            for (int e2 = 0; e2 < 16; e2 += 2) {
                float a0 = 0.f, a1 = 0.f;
#pragma unroll
                for (int d = 0; d < 16; d++) {
                    float qq = qv[d];
                    a0 += qq * cb[d * 16 + e2];
                    a1 += qq * cb[d * 16 + e2 + 1];
                }
                int col = h * 16 + e2;
                int t = col >> 6, chunk = (col >> 3) & 7, hi = col & 7;
                uint32_t off = (uint32_t)(t * 16384 + (row << 7) + (((chunk) ^ (row & 7)) << 4) + hi * 2);
                *(__half2*)((char*)sm + off) =
                    __halves2half2(__float2half_rn(a0 * r), __float2half_rn(a1 * r));
            }
        }
    }

    int sub = lane >> 3;
    int l7  = lane & 7;
    int selA = sub >> 1;
    int rowAoff = ((sub & 1) << 3) + l7;
    int selB = sub & 1;
    int rowBoff = ((sub >> 1) << 3) + l7;

    float acc[4][4][4];
#pragma unroll
    for (int i = 0; i < 4; i++)
#pragma unroll
        for (int j = 0; j < 4; j++)
#pragma unroll
            for (int k = 0; k < 4; k++) acc[i][j][k] = 0.f;

    for (int it = 0; it < 2; it++) {
        if (it == 0) CP_WAIT1(); else CP_WAIT0();
        __syncthreads();
        uint32_t baseA = smem_u + it * 16384;
        uint32_t baseB = smem_u + OP_B_OFF + it * 16384;
#pragma unroll
        for (int ks = 0; ks < 4; ks++) {
            int cb = ks * 2;
            uint32_t a[4][4], bb[4][2];
#pragma unroll
            for (int mt = 0; mt < 4; mt++) {
                int row = warp_m * 64 + mt * 16 + rowAoff;
                uint32_t addr = baseA + (row << 7) + (uint32_t)(((cb + selA) ^ (row & 7)) << 4);
                LDSM4(a[mt][0], a[mt][1], a[mt][2], a[mt][3], addr);
            }
#pragma unroll
            for (int bt = 0; bt < 2; bt++) {
                int row = warp_n * 32 + bt * 16 + rowBoff;
                uint32_t addr = baseB + (row << 7) + (uint32_t)(((cb + selB) ^ (row & 7)) << 4);
                LDSM4(bb[2 * bt][0], bb[2 * bt][1], bb[2 * bt + 1][0], bb[2 * bt + 1][1], addr);
            }
#pragma unroll
            for (int mt = 0; mt < 4; mt++)
#pragma unroll
                for (int nt = 0; nt < 4; nt++)
                    MMA_F16(acc[mt][nt], a[mt], bb[nt]);
        }
    }

    int g  = lane >> 2;
    int t4 = lane & 3;
    __syncthreads();
#pragma unroll
    for (int mt = 0; mt < 4; mt++) {
        int rowl0 = warp_m * 64 + mt * 16 + g;
#pragma unroll
        for (int nt = 0; nt < 4; nt++) {
            int col = warp_n * 32 + nt * 8 + t4 * 2;
            float b0 = bias[col], b1 = bias[col + 1];
#pragma unroll
            for (int hf = 0; hf < 2; hf++) {
                int rowl = rowl0 + hf * 8;
                float2* p = (float2*)(g_t + (size_t)(m0 + rowl) * E + col);
                float2 o = *p;
                float f0 = acc[mt][nt][hf * 2]     + b0 + o.x;
                float f1 = acc[mt][nt][hf * 2 + 1] + b1 + o.y;
                *p = make_float2(f0, f1);
                sm[rowl * 132 + col]     = f0;
                sm[rowl * 132 + col + 1] = f1;
            }
        }
    }
    __syncthreads();
    float g4[4], b4[4];
#pragma unroll
    for (int j = 0; j < 4; j++) { g4[j] = gamma[lane + 32 * j]; b4[j] = beta[lane + 32 * j]; }
    for (int rr = 0; rr < 16; rr++) {
        int row = wid * 16 + rr;
        float x[4];
#pragma unroll
        for (int j = 0; j < 4; j++) x[j] = sm[row * 132 + lane + 32 * j];
        float s = x[0] + x[1] + x[2] + x[3];
#pragma unroll
        for (int o = 16; o > 0; o >>= 1) s += __shfl_xor_sync(0xffffffffu, s, o);
        float mu = s * (1.0f / E);
        float s2 = 0.f;
#pragma unroll
        for (int j = 0; j < 4; j++) { float d = x[j] - mu; s2 += d * d; }
#pragma unroll
        for (int o = 16; o > 0; o >>= 1) s2 += __shfl_xor_sync(0xffffffffu, s2, o);
        float rs = rsqrtf(s2 * (1.0f / E) + LN_EPS);
#pragma unroll
        for (int j = 0; j < 4; j++)
            g_y[(size_t)(m0 + row) * E + lane + 32 * j] =
                __float2half_rn((x[j] - mu) * rs * g4[j] + b4[j]);
    }
}

// ---------------- two-stage mean over sequence ------------------------------
__global__ void mean1_kernel() {
    gdc_wait();
    int blk = blockIdx.x;             // b*8 + chunk
    int b = blk >> 3, ch = blk & 7;
    int e = threadIdx.x;
    const float* p = g_t + (size_t)b * NSEQ * E + (size_t)ch * 128 * E + e;
    float s = 0.f;
#pragma unroll 8
    for (int n = 0; n < 128; n++) s += p[(size_t)n * E];
    g_part[blk * E + e] = s;
}

__global__ void mean2_kernel(float* __restrict__ out) {
    gdc_wait();
    int b = blockIdx.x, e = threadIdx.x;
    float s = 0.f;
#pragma unroll
    for (int ch = 0; ch < 8; ch++) s += g_part[(b * 8 + ch) * E + e];
    out[b * E + e] = s * (1.0f / NSEQ);
}

// ---------------- PDL launch helper ------------------------------------------
template <typename F, typename... A>
static inline void launchPDL(F f, dim3 grid, dim3 block, size_t smem, A... args) {
    cudaLaunchConfig_t cfg = {};
    cfg.gridDim = grid;
    cfg.blockDim = block;
    cfg.dynamicSmemBytes = smem;
    cfg.stream = 0;
    cudaLaunchAttribute at[1];
    at[0].id = cudaLaunchAttributeProgrammaticStreamSerialization;
    at[0].val.programmaticStreamSerializationAllowed = 1;
    cfg.attrs = at;
    cfg.numAttrs = 1;
    cudaLaunchKernelEx(&cfg, f, args...);
}

// ---------------- launch -----------------------------------------------------
extern "C" void kernel_launch(void* const* d_in, const int* in_sizes, int n_in,
                              void* d_out, int out_size) {
    const float* x     = (const float*)d_in[0];
    const float* q_w   = (const float*)d_in[1];
    const float* k_w   = (const float*)d_in[2];
    const float* v_w   = (const float*)d_in[3];
    const float* o_w   = (const float*)d_in[4];
    const float* o_b   = (const float*)d_in[5];
    const float* ln1_g = (const float*)d_in[6];
    const float* ln1_b = (const float*)d_in[7];
    const float* ff_w1 = (const float*)d_in[8];
    const float* ff_b1 = (const float*)d_in[9];
    const float* ff_w2 = (const float*)d_in[10];
    const float* ff_b2 = (const float*)d_in[11];
    const float* ln2_g = (const float*)d_in[12];
    const float* ln2_b = (const float*)d_in[13];
    float* out = (float*)d_out;

    float* pt;
    __half *py, *pqkv, *pff, *pwt;
    cudaGetSymbolAddress((void**)&pt,   g_t);
    cudaGetSymbolAddress((void**)&py,   g_y);
    cudaGetSymbolAddress((void**)&pqkv, g_qkv);
    cudaGetSymbolAddress((void**)&pff,  g_ff);
    cudaGetSymbolAddress((void**)&pwt,  g_wt);

    cudaFuncSetAttribute(mma_gemm, cudaFuncAttributeMaxDynamicSharedMemorySize, SMEM_BYTES);
    cudaFuncSetAttribute(oproj_kernel, cudaFuncAttributeMaxDynamicSharedMemorySize, OP_SMEM);

    wt_cvt_all<<<dim3(192, NLAYERS), dim3(32, 8)>>>(q_w, k_w, v_w, o_w, ff_w1, ff_w2);
    transpose_ln_kernel<<<dim3(NSEQ / 32, BATCH), 256>>>(x, ln1_g, ln1_b);

    for (int l = 0; l < NLAYERS; l++) {
        const __half* wl = pwt + (size_t)l * WT_LAYER;
        launchPDL(mma_gemm, dim3(QKV_N / GBN, MROWS / GBM), dim3(256), SMEM_BYTES,
                  (const __half*)py, wl, (const float*)nullptr, (void*)pqkv,
                  (const float*)nullptr, (const float*)nullptr, (__half*)nullptr,
                  (int)E, (int)QKV_N, (int)16);
        launchPDL(ctx_part_kernel, dim3(BATCH * NHEADS * NCHUNK), dim3(256), 0);
        launchPDL(oproj_kernel, dim3(MROWS / GBM), dim3(256), OP_SMEM,
                  wl + 49152, (const float*)(o_b + l * E),
                  (const float*)(ln2_g + l * E), (const float*)(ln2_b + l * E));
        launchPDL(mma_gemm, dim3(DFF / GBN, MROWS / GBM), dim3(256), SMEM_BYTES,
                  (const __half*)py, wl + 65536, (const float*)(ff_b1 + l * DFF), (void*)pff,
                  (const float*)nullptr, (const float*)nullptr, (__half*)nullptr,
                  (int)E, (int)DFF, (int)(1 | 16));
        if (l < NLAYERS - 1) {
            launchPDL(mma_gemm, dim3(1, MROWS / GBM), dim3(256), SMEM_BYTES,
                      (const __half*)pff, wl + 131072, (const float*)(ff_b2 + l * E), (void*)pt,
                      (const float*)(ln1_g + (l + 1) * E), (const float*)(ln1_b + (l + 1) * E),
                      py, (int)DFF, (int)E, (int)(2 | 8));
        } else {
            launchPDL(mma_gemm, dim3(1, MROWS / GBM), dim3(256), SMEM_BYTES,
                      (const __half*)pff, wl + 131072, (const float*)(ff_b2 + l * E), (void*)pt,
                      (const float*)nullptr, (const float*)nullptr, (__half*)nullptr,
                      (int)DFF, (int)E, (int)2);
        }
    }

    launchPDL(mean1_kernel, dim3(512), dim3(E), 0);
    launchPDL(mean2_kernel, dim3(BATCH), dim3(E), 0, out);
}

// round 17
// speedup vs baseline: 2.4097x; 1.0213x over previous
#include <cuda_runtime.h>
#include <cuda_fp16.h>
#include <math.h>
#include <stdint.h>

#define BATCH 64
#define E 128
#define NSEQ 1024
#define NHEADS 8
#define DH 16
#define DFF 512
#define MROWS (BATCH * NSEQ)   // 65536
#define NLAYERS 4
#define LN_EPS 1e-5f
#define QKV_N 384
#define NCHUNK 8
#define CHUNK_N (NSEQ / NCHUNK)   // 128

// ---------------- scratch (static device globals; allocation-free) ----------
__device__ float  g_t[MROWS * E];          // residual stream fp32
__device__ __half g_y[MROWS * E];          // layernorm output (fp16)
__device__ __half g_qkv[MROWS * QKV_N];    // fused q|k|v fp16, row stride 384
__device__ float  g_ctxp[BATCH * NHEADS * NCHUNK * 256];  // ctx partials
__device__ float  g_ssum[BATCH * NHEADS * NCHUNK * 16];   // exp-sum partials
__device__ __half g_ff[MROWS * DFF];       // gelu out (fp16)
__device__ float  g_part[512 * E];         // mean partials
#define WT_LAYER 196608
__device__ __half g_wt[NLAYERS * WT_LAYER];

__device__ __forceinline__ float gelu_f(float x) {
    float x3 = x * x * x;
    return 0.5f * x * (1.0f + tanhf(0.7978845608028654f * (x + 0.044715f * x3)));
}

__device__ __forceinline__ void gdc_wait() {
    asm volatile("griddepcontrol.wait;" ::: "memory");
}

#define LDSM4(d0, d1, d2, d3, addr) \
    asm volatile("ldmatrix.sync.aligned.m8n8.x4.shared.b16 {%0,%1,%2,%3}, [%4];" \
                 : "=r"(d0), "=r"(d1), "=r"(d2), "=r"(d3) : "r"(addr))

#define LDSM4T(d0, d1, d2, d3, addr) \
    asm volatile("ldmatrix.sync.aligned.m8n8.x4.trans.shared.b16 {%0,%1,%2,%3}, [%4];" \
                 : "=r"(d0), "=r"(d1), "=r"(d2), "=r"(d3) : "r"(addr))

#define MMA_F16(c, a, b) \
    asm volatile("mma.sync.aligned.m16n8k16.row.col.f32.f16.f16.f32 " \
                 "{%0,%1,%2,%3},{%4,%5,%6,%7},{%8,%9},{%0,%1,%2,%3};" \
                 : "+f"((c)[0]), "+f"((c)[1]), "+f"((c)[2]), "+f"((c)[3]) \
                 : "r"((a)[0]), "r"((a)[1]), "r"((a)[2]), "r"((a)[3]), \
                   "r"((b)[0]), "r"((b)[1]))

__device__ __forceinline__ void cp_async16(uint32_t dst, const void* src) {
    asm volatile("cp.async.cg.shared.global [%0], [%1], 16;" :: "r"(dst), "l"(src));
}
#define CP_COMMIT() asm volatile("cp.async.commit_group;")
#define CP_WAIT0()  asm volatile("cp.async.wait_group 0;")
#define CP_WAIT1()  asm volatile("cp.async.wait_group 1;")

// ---------------- fused transpose + layer-0 LN ------------------------------
__global__ void transpose_ln_kernel(const float* __restrict__ x,
                                    const float* __restrict__ gamma,
                                    const float* __restrict__ beta) {
    __shared__ float tile[32][129];
    int b  = blockIdx.y;
    int n0 = blockIdx.x * 32;
    int tx = threadIdx.x & 31;
    int ty = threadIdx.x >> 5;     // 0..7
#pragma unroll
    for (int e0 = 0; e0 < E; e0 += 32) {
#pragma unroll
        for (int i = 0; i < 32; i += 8)
            tile[tx][e0 + ty + i] =
                x[(size_t)b * E * NSEQ + (size_t)(e0 + ty + i) * NSEQ + n0 + tx];
    }
    __syncthreads();
    int lane = tx, wid = ty;
    float g4[4], b4[4];
#pragma unroll
    for (int j = 0; j < 4; j++) { g4[j] = gamma[lane + 32 * j]; b4[j] = beta[lane + 32 * j]; }
    for (int rr = 0; rr < 4; rr++) {
        int row = wid * 4 + rr;
        size_t grow = (size_t)b * NSEQ + n0 + row;
        float xv[4];
#pragma unroll
        for (int j = 0; j < 4; j++) {
            xv[j] = tile[row][lane + 32 * j];
            g_t[grow * E + lane + 32 * j] = xv[j];
        }
        float s = xv[0] + xv[1] + xv[2] + xv[3];
#pragma unroll
        for (int o = 16; o > 0; o >>= 1) s += __shfl_xor_sync(0xffffffffu, s, o);
        float mu = s * (1.0f / E);
        float s2 = 0.f;
#pragma unroll
        for (int j = 0; j < 4; j++) { float d = xv[j] - mu; s2 += d * d; }
#pragma unroll
        for (int o = 16; o > 0; o >>= 1) s2 += __shfl_xor_sync(0xffffffffu, s2, o);
        float rs = rsqrtf(s2 * (1.0f / E) + LN_EPS);
#pragma unroll
        for (int j = 0; j < 4; j++)
            g_y[grow * E + lane + 32 * j] =
                __float2half_rn((xv[j] - mu) * rs * g4[j] + b4[j]);
    }
}

// ---------------- fused weight convert (ALL layers, one launch), fp16 -------
__global__ void wt_cvt_all(const float* __restrict__ q_w, const float* __restrict__ k_w,
                           const float* __restrict__ v_w, const float* __restrict__ o_w,
                           const float* __restrict__ ff_w1, const float* __restrict__ ff_w2) {
    __shared__ float tile[32][33];
    int l  = blockIdx.y;
    int id = blockIdx.x;
    __half* wl = g_wt + (size_t)l * WT_LAYER;

    const float* src;
    __half* dst;
    int K, N, tn, tk;
    if (id < 64) {
        int m = id >> 4;
        const float* srcs[4] = { q_w, k_w, v_w, o_w };
        src = srcs[m] + (size_t)l * E * E;
        dst = wl + m * 16384;
        K = E; N = E;
        int t = id & 15; tn = t & 3; tk = t >> 2;
    } else if (id < 128) {
        src = ff_w1 + (size_t)l * E * DFF;
        dst = wl + 65536;
        K = E; N = DFF;
        int t = id - 64; tn = t & 15; tk = t >> 4;
    } else {
        src = ff_w2 + (size_t)l * DFF * E;
        dst = wl + 131072;
        K = DFF; N = E;
        int t = id - 128; tn = t & 3; tk = t >> 2;
    }
    int n0 = tn * 32, k0 = tk * 32;
    int tx = threadIdx.x, ty = threadIdx.y;   // (32,8)
#pragma unroll
    for (int i = 0; i < 32; i += 8)
        tile[ty + i][tx] = src[(size_t)(k0 + ty + i) * N + n0 + tx];
    __syncthreads();
#pragma unroll
    for (int i = 0; i < 32; i += 8)
        dst[(size_t)(n0 + ty + i) * K + k0 + tx] = __float2half_rn(tile[tx][ty + i]);
}

// ---------------- generic FP16 GEMM (fp32 accum), pipelined, PDL-aware ------
#define GBM 128
#define GBN 128
#define NSTAGE 3
#define STAGE_BYTES 16384
#define BSMEM_OFF (NSTAGE * STAGE_BYTES)
#define SMEM_BYTES (2 * NSTAGE * STAGE_BYTES)   // 98304

__global__ __launch_bounds__(256, 2) void mma_gemm(
    const __half* __restrict__ A, const __half* __restrict__ Wt,
    const float* __restrict__ bias, void* __restrict__ Cv,
    const float* __restrict__ gamma, const float* __restrict__ beta,
    __half* __restrict__ Y,
    int K, int N, int flags)
{
    extern __shared__ float sm[];
    uint32_t smem_u = (uint32_t)__cvta_generic_to_shared(sm);

    int tid  = threadIdx.x;
    int lane = tid & 31;
    int wid  = tid >> 5;
    int warp_m = wid & 1;
    int warp_n = wid >> 1;
    int bm0 = blockIdx.y * GBM;
    int bn0 = blockIdx.x * GBN;

    int r0 = tid >> 3;
    int c8 = tid & 7;
    uint32_t cxor = (uint32_t)((c8 ^ (r0 & 7)) << 4);

    auto load_A = [&](int s, int k0) {
#pragma unroll
        for (int i = 0; i < 4; i++) {
            int r = r0 + i * 32;
            uint32_t doff = (uint32_t)(r << 7) + cxor;
            cp_async16(smem_u + s * STAGE_BYTES + doff, A + (size_t)(bm0 + r) * K + k0 + c8 * 8);
        }
    };
    auto load_B = [&](int s, int k0) {
#pragma unroll
        for (int i = 0; i < 4; i++) {
            int r = r0 + i * 32;
            uint32_t doff = (uint32_t)(r << 7) + cxor;
            cp_async16(smem_u + BSMEM_OFF + s * STAGE_BYTES + doff, Wt + (size_t)(bn0 + r) * K + k0 + c8 * 8);
        }
    };

    load_B(0, 0); CP_COMMIT();
    gdc_wait();

    int nIter = K >> 6;
    load_A(0, 0); CP_COMMIT();
    if (nIter > 1) { load_A(1, 64); load_B(1, 64); CP_COMMIT(); }

    int sub = lane >> 3;
    int l7  = lane & 7;
    int selA = sub >> 1;
    int rowAoff = ((sub & 1) << 3) + l7;
    int selB = sub & 1;
    int rowBoff = ((sub >> 1) << 3) + l7;

    float acc[4][4][4];
#pragma unroll
    for (int i = 0; i < 4; i++)
#pragma unroll
        for (int j = 0; j < 4; j++)
#pragma unroll
            for (int k = 0; k < 4; k++) acc[i][j][k] = 0.f;

    for (int it = 0; it < nIter; it++) {
        if (it < nIter - 1) CP_WAIT1(); else CP_WAIT0();
        __syncthreads();

        int s = it % NSTAGE;
        uint32_t baseA = smem_u + s * STAGE_BYTES;
        uint32_t baseB = smem_u + BSMEM_OFF + s * STAGE_BYTES;

#pragma unroll
        for (int ks = 0; ks < 4; ks++) {
            int cb = ks * 2;
            uint32_t a[4][4], b[4][2];
#pragma unroll
            for (int mt = 0; mt < 4; mt++) {
                int row = warp_m * 64 + mt * 16 + rowAoff;
                uint32_t addr = baseA + (row << 7) + (uint32_t)(((cb + selA) ^ (row & 7)) << 4);
                LDSM4(a[mt][0], a[mt][1], a[mt][2], a[mt][3], addr);
            }
#pragma unroll
            for (int bt = 0; bt < 2; bt++) {
                int row = warp_n * 32 + bt * 16 + rowBoff;
                uint32_t addr = baseB + (row << 7) + (uint32_t)(((cb + selB) ^ (row & 7)) << 4);
                LDSM4(b[2 * bt][0], b[2 * bt][1], b[2 * bt + 1][0], b[2 * bt + 1][1], addr);
            }
#pragma unroll
            for (int mt = 0; mt < 4; mt++)
#pragma unroll
                for (int nt = 0; nt < 4; nt++)
                    MMA_F16(acc[mt][nt], a[mt], b[nt]);
        }

        if (it + 2 < nIter) {
            load_A((it + 2) % NSTAGE, (it + 2) * 64);
            load_B((it + 2) % NSTAGE, (it + 2) * 64);
            CP_COMMIT();
        }
    }

    int g  = lane >> 2;
    int t4 = lane & 3;
    bool do_ln = (flags & 8) != 0;
    if (do_ln) __syncthreads();

    float* Cf = (float*)Cv;
    __half* Ch = (__half*)Cv;

#pragma unroll
    for (int mt = 0; mt < 4; mt++) {
        int rowl0 = warp_m * 64 + mt * 16 + g;
#pragma unroll
        for (int nt = 0; nt < 4; nt++) {
            int coll = warp_n * 32 + nt * 8 + t4 * 2;
            int col  = bn0 + coll;
            float v[4] = { acc[mt][nt][0], acc[mt][nt][1], acc[mt][nt][2], acc[mt][nt][3] };
            if (bias) {
                float b0 = bias[col], b1 = bias[col + 1];
                v[0] += b0; v[1] += b1; v[2] += b0; v[3] += b1;
            }
            if (flags & 1) {
#pragma unroll
                for (int z = 0; z < 4; z++) v[z] = gelu_f(v[z]);
            }
#pragma unroll
            for (int half2i = 0; half2i < 2; half2i++) {
                int rowl = rowl0 + half2i * 8;
                float f0 = v[half2i * 2], f1 = v[half2i * 2 + 1];
                if (flags & 16) {
                    *(__half2*)(Ch + (size_t)(bm0 + rowl) * N + col) =
                        __halves2half2(__float2half_rn(f0), __float2half_rn(f1));
                } else {
                    float2* p = (float2*)(Cf + (size_t)(bm0 + rowl) * N + col);
                    if (flags & 2) {
                        float2 o = *p;
                        f0 += o.x; f1 += o.y;
                    }
                    *p = make_float2(f0, f1);
                }
                if (do_ln) {
                    sm[rowl * 132 + coll]     = f0;
                    sm[rowl * 132 + coll + 1] = f1;
                }
            }
        }
    }

    if (do_ln) {
        __syncthreads();
        float g4[4], b4[4];
#pragma unroll
        for (int j = 0; j < 4; j++) {
            g4[j] = gamma[lane + 32 * j];
            b4[j] = beta[lane + 32 * j];
        }
        for (int r = 0; r < 16; r++) {
            int row = wid * 16 + r;
            float x[4];
#pragma unroll
            for (int j = 0; j < 4; j++) x[j] = sm[row * 132 + lane + 32 * j];
            float s = x[0] + x[1] + x[2] + x[3];
#pragma unroll
            for (int o = 16; o > 0; o >>= 1) s += __shfl_xor_sync(0xffffffffu, s, o);
            float mu = s * (1.0f / E);
            float s2 = 0.f;
#pragma unroll
            for (int j = 0; j < 4; j++) { float d = x[j] - mu; s2 += d * d; }
#pragma unroll
            for (int o = 16; o > 0; o >>= 1) s2 += __shfl_xor_sync(0xffffffffu, s2, o);
            float rs = rsqrtf(s2 * (1.0f / E) + LN_EPS);
#pragma unroll
            for (int j = 0; j < 4; j++)
                Y[(size_t)(bm0 + row) * E + lane + 32 * j] =
                    __float2half_rn((x[j] - mu) * rs * g4[j] + b4[j]);
        }
    }
}

// ---------------- ctx partial via tensor cores + ldmatrix.trans -------------
// Row-major fp16 staging (one int4 store per segment), trans fragments.
__global__ void ctx_part_kernel() {
    gdc_wait();
    int blk = blockIdx.x;              // bh*NCHUNK + c
    int bh = blk >> 3, c = blk & 7;
    int b = bh >> 3, h = bh & 7;
    const __half* kbase = g_qkv + (size_t)b * NSEQ * QKV_N + (size_t)c * CHUNK_N * QKV_N + E + h * DH;
    const __half* vbase = kbase + E;
    int tid = threadIdx.x;

    __shared__ __half kE[128][24];     // exp(k), row-major, 48B row stride
    __shared__ __half vE[128][24];     // v, row-major

    // stage: 512 segments of 8 halfs ({k seg0, k seg1, v seg0, v seg1} x 128 rows)
#pragma unroll
    for (int s = tid; s < 512; s += 256) {
        int nl = s >> 2, sub = s & 3;
        bool isv = (sub & 2) != 0;
        int seg = sub & 1;
        const __half* p = (isv ? vbase : kbase) + (size_t)nl * QKV_N + seg * 8;
        int4 raw = *(const int4*)p;
        if (isv) {
            *(int4*)&vE[nl][seg * 8] = raw;
        } else {
            __half2* h2 = (__half2*)&raw;
            __half2 out[4];
#pragma unroll
            for (int j = 0; j < 4; j++) {
                float2 f = __half22float2(h2[j]);
                out[j] = __halves2half2(__float2half_rn(__expf(f.x)),
                                        __float2half_rn(__expf(f.y)));
            }
            *(int4*)&kE[nl][seg * 8] = *(int4*)out;
        }
    }
    __syncthreads();

    int wid = tid >> 5, lane = tid & 31;
    if (wid == 0) {
        int grp = lane >> 3, l7 = lane & 7;
        // A (expk^T) trans groups: {m0k0, m8k0, m0k8, m8k8}
        int rowAoff = ((grp >> 1) << 3) + l7;   // k-block in rows
        int colA    = (grp & 1) << 3;           // m-block in cols
        // B (v) trans groups: {n0k0, n0k8, n8k0, n8k8}
        int rowBoff = ((grp & 1) << 3) + l7;    // k-block in rows
        int colB    = (grp & 2) << 2;           // n-block in cols

        float c0[4] = {0.f, 0.f, 0.f, 0.f};
        float c1[4] = {0.f, 0.f, 0.f, 0.f};
#pragma unroll
        for (int kc = 0; kc < 8; kc++) {
            uint32_t a[4], b0[2], b1[2];
            uint32_t aaddr = (uint32_t)__cvta_generic_to_shared(&kE[kc * 16 + rowAoff][colA]);
            LDSM4T(a[0], a[1], a[2], a[3], aaddr);
            uint32_t baddr = (uint32_t)__cvta_generic_to_shared(&vE[kc * 16 + rowBoff][colB]);
            LDSM4T(b0[0], b0[1], b1[0], b1[1], baddr);
            MMA_F16(c0, a, b0);
            MMA_F16(c1, a, b1);
        }
        int g = lane >> 2, t4 = lane & 3;
        float* dst = g_ctxp + blk * 256;
        dst[g * 16 + t4 * 2]           = c0[0];
        dst[g * 16 + t4 * 2 + 1]       = c0[1];
        dst[(g + 8) * 16 + t4 * 2]     = c0[2];
        dst[(g + 8) * 16 + t4 * 2 + 1] = c0[3];
        dst[g * 16 + 8 + t4 * 2]           = c1[0];
        dst[g * 16 + 8 + t4 * 2 + 1]       = c1[1];
        dst[(g + 8) * 16 + 8 + t4 * 2]     = c1[2];
        dst[(g + 8) * 16 + 8 + t4 * 2 + 1] = c1[3];
    } else if (wid == 1) {
        int d = lane >> 1, hf = lane & 1;
        float s = 0.f;
#pragma unroll 16
        for (int j = 0; j < 64; j++) s += __half2float(kE[hf * 64 + j][d]);
        float o = __shfl_xor_sync(0xffffffffu, s, 1);
        if (hf == 0) g_ssum[blk * 16 + d] = s + o;
    }
}

// ---------------- o-proj: partial-reduce + attn prologue + GEMM + LN --------
#define OP_B_OFF 32768
#define OP_CTX_OFF 65536
#define OP_SMEM 73728

__global__ __launch_bounds__(256, 2) void oproj_kernel(
    const __half* __restrict__ Wt, const float* __restrict__ bias,
    const float* __restrict__ gamma, const float* __restrict__ beta)
{
    extern __shared__ float sm[];
    uint32_t smem_u = (uint32_t)__cvta_generic_to_shared(sm);

    int tid  = threadIdx.x;
    int lane = tid & 31;
    int wid  = tid >> 5;
    int warp_m = wid & 1;
    int warp_n = wid >> 1;
    int m0 = blockIdx.x * GBM;
    int b  = m0 >> 10;

    int r0 = tid >> 3;
    int c8 = tid & 7;
    uint32_t cxor = (uint32_t)((c8 ^ (r0 & 7)) << 4);

#pragma unroll
    for (int i = 0; i < 4; i++) {
        int r = r0 + i * 32;
        cp_async16(smem_u + OP_B_OFF + (r << 7) + cxor, Wt + (size_t)r * E + c8 * 8);
    }
    CP_COMMIT();
#pragma unroll
    for (int i = 0; i < 4; i++) {
        int r = r0 + i * 32;
        cp_async16(smem_u + OP_B_OFF + 16384 + (r << 7) + cxor, Wt + (size_t)r * E + 64 + c8 * 8);
    }
    CP_COMMIT();
    gdc_wait();

    // reduce ctx partials into smem: ctx = (Σ_c acc) / (Σ_c ssum)
    float* ctxs = (float*)((char*)sm + OP_CTX_OFF);
    for (int i = tid; i < 2048; i += 256) {
        int h = i >> 8, de = i & 255, d = de >> 4;
        int bh8 = ((b * NHEADS + h) << 3);
        float a = 0.f, ss = 0.f;
#pragma unroll
        for (int c = 0; c < NCHUNK; c++) {
            a  += g_ctxp[(bh8 + c) * 256 + de];
            ss += g_ssum[(bh8 + c) * 16 + d];
        }
        ctxs[i] = a / ss;
    }
    __syncthreads();

    // attention prologue: A[128][128] = f16(softmax_q(q) @ ctx * 0.25)
    {
        int row = tid >> 1, half = tid & 1;
        const __half* qrow = g_qkv + (size_t)(m0 + row) * QKV_N;
#pragma unroll
        for (int hh = 0; hh < 4; hh++) {
            int h = half * 4 + hh;
            float qv[16];
            const __half2* q2 = (const __half2*)(qrow + h * 16);
#pragma unroll
            for (int j = 0; j < 8; j++) {
                float2 t = __half22float2(q2[j]);
                qv[2 * j] = t.x; qv[2 * j + 1] = t.y;
            }
            float mxv = -1e30f;
#pragma unroll
            for (int d = 0; d < 16; d++) mxv = fmaxf(mxv, qv[d]);
            float s = 0.f;
#pragma unroll
            for (int d = 0; d < 16; d++) { qv[d] = __expf(qv[d] - mxv); s += qv[d]; }
            float r = 0.25f / s;
            const float* cb = ctxs + h * 256;
#pragma unroll
            for (int e2 = 0; e2 < 16; e2 += 2) {
                float a0 = 0.f, a1 = 0.f;
#pragma unroll
                for (int d = 0; d < 16; d++) {
                    float qq = qv[d];
                    a0 += qq * cb[d * 16 + e2];
                    a1 += qq * cb[d * 16 + e2 + 1];
                }
                int col = h * 16 + e2;
                int t = col >> 6, chunk = (col >> 3) & 7, hi = col & 7;
                uint32_t off = (uint32_t)(t * 16384 + (row << 7) + (((chunk) ^ (row & 7)) << 4) + hi * 2);
                *(__half2*)((char*)sm + off) =
                    __halves2half2(__float2half_rn(a0 * r), __float2half_rn(a1 * r));
            }
        }
    }

    int sub = lane >> 3;
    int l7  = lane & 7;
    int selA = sub >> 1;
    int rowAoff = ((sub & 1) << 3) + l7;
    int selB = sub & 1;
    int rowBoff = ((sub >> 1) << 3) + l7;

    float acc[4][4][4];
#pragma unroll
    for (int i = 0; i < 4; i++)
#pragma unroll
        for (int j = 0; j < 4; j++)
#pragma unroll
            for (int k = 0; k < 4; k++) acc[i][j][k] = 0.f;

    for (int it = 0; it < 2; it++) {
        if (it == 0) CP_WAIT1(); else CP_WAIT0();
        __syncthreads();
        uint32_t baseA = smem_u + it * 16384;
        uint32_t baseB = smem_u + OP_B_OFF + it * 16384;
#pragma unroll
        for (int ks = 0; ks < 4; ks++) {
            int cb = ks * 2;
            uint32_t a[4][4], bb[4][2];
#pragma unroll
            for (int mt = 0; mt < 4; mt++) {
                int row = warp_m * 64 + mt * 16 + rowAoff;
                uint32_t addr = baseA + (row << 7) + (uint32_t)(((cb + selA) ^ (row & 7)) << 4);
                LDSM4(a[mt][0], a[mt][1], a[mt][2], a[mt][3], addr);
            }
#pragma unroll
            for (int bt = 0; bt < 2; bt++) {
                int row = warp_n * 32 + bt * 16 + rowBoff;
                uint32_t addr = baseB + (row << 7) + (uint32_t)(((cb + selB) ^ (row & 7)) << 4);
                LDSM4(bb[2 * bt][0], bb[2 * bt][1], bb[2 * bt + 1][0], bb[2 * bt + 1][1], addr);
            }
#pragma unroll
            for (int mt = 0; mt < 4; mt++)
#pragma unroll
                for (int nt = 0; nt < 4; nt++)
                    MMA_F16(acc[mt][nt], a[mt], bb[nt]);
        }
    }

    int g  = lane >> 2;
    int t4 = lane & 3;
    __syncthreads();
#pragma unroll
    for (int mt = 0; mt < 4; mt++) {
        int rowl0 = warp_m * 64 + mt * 16 + g;
#pragma unroll
        for (int nt = 0; nt < 4; nt++) {
            int col = warp_n * 32 + nt * 8 + t4 * 2;
            float b0 = bias[col], b1 = bias[col + 1];
#pragma unroll
            for (int hf = 0; hf < 2; hf++) {
                int rowl = rowl0 + hf * 8;
                float2* p = (float2*)(g_t + (size_t)(m0 + rowl) * E + col);
                float2 o = *p;
                float f0 = acc[mt][nt][hf * 2]     + b0 + o.x;
                float f1 = acc[mt][nt][hf * 2 + 1] + b1 + o.y;
                *p = make_float2(f0, f1);
                sm[rowl * 132 + col]     = f0;
                sm[rowl * 132 + col + 1] = f1;
            }
        }
    }
    __syncthreads();
    float g4[4], b4[4];
#pragma unroll
    for (int j = 0; j < 4; j++) { g4[j] = gamma[lane + 32 * j]; b4[j] = beta[lane + 32 * j]; }
    for (int rr = 0; rr < 16; rr++) {
        int row = wid * 16 + rr;
        float x[4];
#pragma unroll
        for (int j = 0; j < 4; j++) x[j] = sm[row * 132 + lane + 32 * j];
        float s = x[0] + x[1] + x[2] + x[3];
#pragma unroll
        for (int o = 16; o > 0; o >>= 1) s += __shfl_xor_sync(0xffffffffu, s, o);
        float mu = s * (1.0f / E);
        float s2 = 0.f;
#pragma unroll
        for (int j = 0; j < 4; j++) { float d = x[j] - mu; s2 += d * d; }
#pragma unroll
        for (int o = 16; o > 0; o >>= 1) s2 += __shfl_xor_sync(0xffffffffu, s2, o);
        float rs = rsqrtf(s2 * (1.0f / E) + LN_EPS);
#pragma unroll
        for (int j = 0; j < 4; j++)
            g_y[(size_t)(m0 + row) * E + lane + 32 * j] =
                __float2half_rn((x[j] - mu) * rs * g4[j] + b4[j]);
    }
}

// ---------------- two-stage mean over sequence ------------------------------
__global__ void mean1_kernel() {
    gdc_wait();
    int blk = blockIdx.x;             // b*8 + chunk
    int b = blk >> 3, ch = blk & 7;
    int e = threadIdx.x;
    const float* p = g_t + (size_t)b * NSEQ * E + (size_t)ch * 128 * E + e;
    float s = 0.f;
#pragma unroll 8
    for (int n = 0; n < 128; n++) s += p[(size_t)n * E];
    g_part[blk * E + e] = s;
}

__global__ void mean2_kernel(float* __restrict__ out) {
    gdc_wait();
    int b = blockIdx.x, e = threadIdx.x;
    float s = 0.f;
#pragma unroll
    for (int ch = 0; ch < 8; ch++) s += g_part[(b * 8 + ch) * E + e];
    out[b * E + e] = s * (1.0f / NSEQ);
}

// ---------------- PDL launch helper ------------------------------------------
template <typename F, typename... A>
static inline void launchPDL(F f, dim3 grid, dim3 block, size_t smem, A... args) {
    cudaLaunchConfig_t cfg = {};
    cfg.gridDim = grid;
    cfg.blockDim = block;
    cfg.dynamicSmemBytes = smem;
    cfg.stream = 0;
    cudaLaunchAttribute at[1];
    at[0].id = cudaLaunchAttributeProgrammaticStreamSerialization;
    at[0].val.programmaticStreamSerializationAllowed = 1;
    cfg.attrs = at;
    cfg.numAttrs = 1;
    cudaLaunchKernelEx(&cfg, f, args...);
}

// ---------------- launch -----------------------------------------------------
extern "C" void kernel_launch(void* const* d_in, const int* in_sizes, int n_in,
                              void* d_out, int out_size) {
    const float* x     = (const float*)d_in[0];
    const float* q_w   = (const float*)d_in[1];
    const float* k_w   = (const float*)d_in[2];
    const float* v_w   = (const float*)d_in[3];
    const float* o_w   = (const float*)d_in[4];
    const float* o_b   = (const float*)d_in[5];
    const float* ln1_g = (const float*)d_in[6];
    const float* ln1_b = (const float*)d_in[7];
    const float* ff_w1 = (const float*)d_in[8];
    const float* ff_b1 = (const float*)d_in[9];
    const float* ff_w2 = (const float*)d_in[10];
    const float* ff_b2 = (const float*)d_in[11];
    const float* ln2_g = (const float*)d_in[12];
    const float* ln2_b = (const float*)d_in[13];
    float* out = (float*)d_out;

    float* pt;
    __half *py, *pqkv, *pff, *pwt;
    cudaGetSymbolAddress((void**)&pt,   g_t);
    cudaGetSymbolAddress((void**)&py,   g_y);
    cudaGetSymbolAddress((void**)&pqkv, g_qkv);
    cudaGetSymbolAddress((void**)&pff,  g_ff);
    cudaGetSymbolAddress((void**)&pwt,  g_wt);

    cudaFuncSetAttribute(mma_gemm, cudaFuncAttributeMaxDynamicSharedMemorySize, SMEM_BYTES);
    cudaFuncSetAttribute(oproj_kernel, cudaFuncAttributeMaxDynamicSharedMemorySize, OP_SMEM);

    wt_cvt_all<<<dim3(192, NLAYERS), dim3(32, 8)>>>(q_w, k_w, v_w, o_w, ff_w1, ff_w2);
    transpose_ln_kernel<<<dim3(NSEQ / 32, BATCH), 256>>>(x, ln1_g, ln1_b);

    for (int l = 0; l < NLAYERS; l++) {
        const __half* wl = pwt + (size_t)l * WT_LAYER;
        launchPDL(mma_gemm, dim3(QKV_N / GBN, MROWS / GBM), dim3(256), SMEM_BYTES,
                  (const __half*)py, wl, (const float*)nullptr, (void*)pqkv,
                  (const float*)nullptr, (const float*)nullptr, (__half*)nullptr,
                  (int)E, (int)QKV_N, (int)16);
        launchPDL(ctx_part_kernel, dim3(BATCH * NHEADS * NCHUNK), dim3(256), 0);
        launchPDL(oproj_kernel, dim3(MROWS / GBM), dim3(256), OP_SMEM,
                  wl + 49152, (const float*)(o_b + l * E),
                  (const float*)(ln2_g + l * E), (const float*)(ln2_b + l * E));
        launchPDL(mma_gemm, dim3(DFF / GBN, MROWS / GBM), dim3(256), SMEM_BYTES,
                  (const __half*)py, wl + 65536, (const float*)(ff_b1 + l * DFF), (void*)pff,
                  (const float*)nullptr, (const float*)nullptr, (__half*)nullptr,
                  (int)E, (int)DFF, (int)(1 | 16));
        if (l < NLAYERS - 1) {
            launchPDL(mma_gemm, dim3(1, MROWS / GBM), dim3(256), SMEM_BYTES,
                      (const __half*)pff, wl + 131072, (const float*)(ff_b2 + l * E), (void*)pt,
                      (const float*)(ln1_g + (l + 1) * E), (const float*)(ln1_b + (l + 1) * E),
                      py, (int)DFF, (int)E, (int)(2 | 8));
        } else {
            launchPDL(mma_gemm, dim3(1, MROWS / GBM), dim3(256), SMEM_BYTES,
                      (const __half*)pff, wl + 131072, (const float*)(ff_b2 + l * E), (void*)pt,
                      (const float*)nullptr, (const float*)nullptr, (__half*)nullptr,
                      (int)DFF, (int)E, (int)2);
        }
    }

    launchPDL(mean1_kernel, dim3(512), dim3(E), 0);
    launchPDL(mean2_kernel, dim3(BATCH), dim3(E), 0, out);
}